// round 1
// baseline (speedup 1.0000x reference)
#include <cuda_runtime.h>
#include <math.h>

#define B 256
#define T 200
#define P1 1024
#define P2 512
#define PT 1536   // P1 + P2
#define O 512
#define I 2

// -------- device scratch (no cudaMalloc allowed) --------
__device__ float g_Wcat[PT * PT];   // packed [W_rec1|W_21 ; W_12|W_rec2], row n, col k (K-major rows)
__device__ float g_bias[PT];        // b_rec + b_cross + b_in fused
__device__ float g_win[PT * 2];     // input-projection weights per output unit
__device__ float g_h0[B * PT];      // initial hidden state [h1 | h2]

// ---------------------------------------------------------
// Pack weights once per launch (deterministic, cheap)
// ---------------------------------------------------------
__global__ void pack_kernel(const float* __restrict__ W_rec1, const float* __restrict__ b_rec1,
                            const float* __restrict__ W_rec2, const float* __restrict__ b_rec2,
                            const float* __restrict__ W_12,   const float* __restrict__ b_12,
                            const float* __restrict__ W_21,   const float* __restrict__ b_21,
                            const float* __restrict__ W_in1,  const float* __restrict__ b_in1,
                            const float* __restrict__ W_in2,  const float* __restrict__ b_in2) {
    int idx = blockIdx.x * blockDim.x + threadIdx.x;
    int stride = gridDim.x * blockDim.x;
    for (int i = idx; i < PT * PT; i += stride) {
        int n = i / PT, k = i % PT;
        float v;
        if (n < P1) {
            v = (k < P1) ? W_rec1[n * P1 + k] : W_21[n * P2 + (k - P1)];
        } else {
            int n2 = n - P1;
            v = (k < P1) ? W_12[n2 * P1 + k] : W_rec2[n2 * P2 + (k - P1)];
        }
        g_Wcat[i] = v;
    }
    for (int n = idx; n < PT; n += stride) {
        if (n < P1) {
            g_bias[n] = b_rec1[n] + b_21[n] + b_in1[n];
            g_win[2 * n]     = W_in1[2 * n];
            g_win[2 * n + 1] = W_in1[2 * n + 1];
        } else {
            int n2 = n - P1;
            g_bias[n] = b_rec2[n2] + b_12[n2] + b_in2[n2];
            g_win[2 * n]     = W_in2[2 * n2];
            g_win[2 * n + 1] = W_in2[2 * n2 + 1];
        }
    }
}

// ---------------------------------------------------------
// Init: h0 = place_cells_0 @ [W_h1 ; W_h2].T   (256 x 1536, K=512)
// ---------------------------------------------------------
__global__ void init_kernel(const float* __restrict__ place,
                            const float* __restrict__ Wh1,
                            const float* __restrict__ Wh2) {
    __shared__ float As[16][65];
    __shared__ float Ws[16][65];
    int tid = threadIdx.x;
    int bn = blockIdx.x * 64;   // over PT
    int bm = blockIdx.y * 64;   // over B
    float acc[4][4] = {};

    for (int k0 = 0; k0 < O; k0 += 16) {
        #pragma unroll
        for (int i = 0; i < 4; i++) {
            int lin = tid + 256 * i;
            int r = lin >> 4, c = lin & 15;
            As[c][r] = place[(bm + r) * O + k0 + c];
            int n = bn + r;
            Ws[c][r] = (n < P1) ? Wh1[n * O + k0 + c] : Wh2[(n - P1) * O + k0 + c];
        }
        __syncthreads();
        #pragma unroll
        for (int c = 0; c < 16; c++) {
            float af[4], wf[4];
            int ty = tid >> 4, tx = tid & 15;
            #pragma unroll
            for (int j = 0; j < 4; j++) { af[j] = As[c][ty * 4 + j]; wf[j] = Ws[c][tx * 4 + j]; }
            #pragma unroll
            for (int a = 0; a < 4; a++)
                #pragma unroll
                for (int b2 = 0; b2 < 4; b2++)
                    acc[a][b2] = fmaf(af[a], wf[b2], acc[a][b2]);
        }
        __syncthreads();
    }
    int ty = tid >> 4, tx = tid & 15;
    #pragma unroll
    for (int a = 0; a < 4; a++)
        #pragma unroll
        for (int b2 = 0; b2 < 4; b2++)
            g_h0[(bm + ty * 4 + a) * PT + bn + tx * 4 + b2] = acc[a][b2];
}

// ---------------------------------------------------------
// One RNN step: t = h(step-1) @ Wcat.T, fused epilogue writes h(step) into d_out
// h(step-1) read from g_h0 (step==0) or from d_out h-sections (contiguous (B,T,P) layout)
// ---------------------------------------------------------
__device__ __forceinline__ float load_h(int b, int k, int step,
                                        const float* __restrict__ oh1,
                                        const float* __restrict__ oh2) {
    if (step == 0) return g_h0[b * PT + k];
    if (k < P1) return oh1[(b * T + (step - 1)) * P1 + k];
    return oh2[(b * T + (step - 1)) * P2 + (k - P1)];
}

__global__ void step_kernel(int step, const float* __restrict__ inputs,
                            float* __restrict__ oh1, float* __restrict__ oh2) {
    __shared__ float As[16][65];
    __shared__ float Ws[16][65];
    int tid = threadIdx.x;
    int bn = blockIdx.x * 64;   // over PT (output units)
    int bm = blockIdx.y * 64;   // over batch
    float acc[4][4] = {};

    for (int k0 = 0; k0 < PT; k0 += 16) {
        #pragma unroll
        for (int i = 0; i < 4; i++) {
            int lin = tid + 256 * i;
            int r = lin >> 4, c = lin & 15;
            As[c][r] = load_h(bm + r, k0 + c, step, oh1, oh2);
            Ws[c][r] = g_Wcat[(bn + r) * PT + k0 + c];
        }
        __syncthreads();
        #pragma unroll
        for (int c = 0; c < 16; c++) {
            float af[4], wf[4];
            int ty = tid >> 4, tx = tid & 15;
            #pragma unroll
            for (int j = 0; j < 4; j++) { af[j] = As[c][ty * 4 + j]; wf[j] = Ws[c][tx * 4 + j]; }
            #pragma unroll
            for (int a = 0; a < 4; a++)
                #pragma unroll
                for (int b2 = 0; b2 < 4; b2++)
                    acc[a][b2] = fmaf(af[a], wf[b2], acc[a][b2]);
        }
        __syncthreads();
    }

    int ty = tid >> 4, tx = tid & 15;
    #pragma unroll
    for (int a = 0; a < 4; a++) {
        int b = bm + ty * 4 + a;
        float x0 = inputs[(b * T + step) * I + 0];
        float x1 = inputs[(b * T + step) * I + 1];
        #pragma unroll
        for (int j = 0; j < 4; j++) {
            int n = bn + tx * 4 + j;
            float arg = acc[a][j] + g_bias[n] + x0 * g_win[2 * n] + x1 * g_win[2 * n + 1];
            float hold = load_h(b, n, step, oh1, oh2);
            float alpha = (n < P1) ? 0.1f : 0.05f;
            float nh = (1.0f - alpha) * hold + alpha * tanhf(arg);
            if (n < P1) oh1[(b * T + step) * P1 + n] = nh;
            else        oh2[(b * T + step) * P2 + (n - P1)] = nh;
        }
    }
}

// ---------------------------------------------------------
// Output projection: outputs = [h1s|h2s] @ W_out.T   (51200 x 512, K=1536)
// A row m = b*T + t maps directly to contiguous oh1/oh2 rows.
// ---------------------------------------------------------
__global__ void out_kernel(const float* __restrict__ Wout,
                           const float* __restrict__ oh1,
                           const float* __restrict__ oh2,
                           float* __restrict__ out2) {
    __shared__ float As[16][65];
    __shared__ float Ws[16][65];
    int tid = threadIdx.x;
    int bn = blockIdx.x * 64;   // over O
    int bm = blockIdx.y * 64;   // over B*T
    float acc[4][4] = {};

    for (int k0 = 0; k0 < PT; k0 += 16) {
        #pragma unroll
        for (int i = 0; i < 4; i++) {
            int lin = tid + 256 * i;
            int r = lin >> 4, c = lin & 15;
            int m = bm + r, k = k0 + c;
            As[c][r] = (k < P1) ? oh1[m * P1 + k] : oh2[m * P2 + (k - P1)];
            Ws[c][r] = Wout[(bn + r) * PT + k];
        }
        __syncthreads();
        #pragma unroll
        for (int c = 0; c < 16; c++) {
            float af[4], wf[4];
            int ty = tid >> 4, tx = tid & 15;
            #pragma unroll
            for (int j = 0; j < 4; j++) { af[j] = As[c][ty * 4 + j]; wf[j] = Ws[c][tx * 4 + j]; }
            #pragma unroll
            for (int a = 0; a < 4; a++)
                #pragma unroll
                for (int b2 = 0; b2 < 4; b2++)
                    acc[a][b2] = fmaf(af[a], wf[b2], acc[a][b2]);
        }
        __syncthreads();
    }
    int ty = tid >> 4, tx = tid & 15;
    #pragma unroll
    for (int a = 0; a < 4; a++)
        #pragma unroll
        for (int b2 = 0; b2 < 4; b2++)
            out2[(bm + ty * 4 + a) * O + bn + tx * 4 + b2] = acc[a][b2];
}

// ---------------------------------------------------------
extern "C" void kernel_launch(void* const* d_in, const int* in_sizes, int n_in,
                              void* d_out, int out_size) {
    const float* inputs  = (const float*)d_in[0];   // (B,T,I)
    const float* place0  = (const float*)d_in[1];   // (B,O)
    const float* W_in1   = (const float*)d_in[2];
    const float* b_in1   = (const float*)d_in[3];
    const float* W_in2   = (const float*)d_in[4];
    const float* b_in2   = (const float*)d_in[5];
    const float* W_rec1  = (const float*)d_in[6];
    const float* b_rec1  = (const float*)d_in[7];
    const float* W_rec2  = (const float*)d_in[8];
    const float* b_rec2  = (const float*)d_in[9];
    const float* W_12    = (const float*)d_in[10];
    const float* b_12    = (const float*)d_in[11];
    const float* W_21    = (const float*)d_in[12];
    const float* b_21    = (const float*)d_in[13];
    const float* W_out   = (const float*)d_in[14];  // (O, PT)
    const float* W_h1    = (const float*)d_in[15];  // (P1, O)
    const float* W_h2    = (const float*)d_in[16];  // (P2, O)

    float* oh1  = (float*)d_out;                          // (B,T,P1)
    float* oh2  = oh1 + (size_t)B * T * P1;               // (B,T,P2)
    float* out2 = oh2 + (size_t)B * T * P2;               // (B,T,O)

    pack_kernel<<<256, 256>>>(W_rec1, b_rec1, W_rec2, b_rec2,
                              W_12, b_12, W_21, b_21,
                              W_in1, b_in1, W_in2, b_in2);

    {
        dim3 grid(PT / 64, B / 64);
        init_kernel<<<grid, 256>>>(place0, W_h1, W_h2);
    }

    {
        dim3 grid(PT / 64, B / 64);   // 24 x 4 = 96 CTAs
        for (int t = 0; t < T; t++)
            step_kernel<<<grid, 256>>>(t, inputs, oh1, oh2);
    }

    {
        dim3 grid(O / 64, (B * T) / 64);  // 8 x 800
        out_kernel<<<grid, 256>>>(W_out, oh1, oh2, out2);
    }
}

// round 3
// speedup vs baseline: 2.7680x; 2.7680x over previous
#include <cuda_runtime.h>
#include <cuda_bf16.h>
#include <cstdint>

#define B 256
#define T 200
#define P1 1024
#define P2 512
#define PT 1536
#define O 512
#define NCHUNK 24        // K chunks of 64

// ---------------- device scratch ----------------
__device__ float g_bias[PT];
__device__ float g_win[2 * PT];
__device__ float g_h0[B * PT];
__device__ __nv_bfloat16 g_Whi[PT * PT];
__device__ __nv_bfloat16 g_Wlo[PT * PT];
__device__ __nv_bfloat16 g_Wouthi[O * PT];
__device__ __nv_bfloat16 g_Woutlo[O * PT];

// ---------------- smem layout (offsets from 1024-aligned base) ----------------
#define SM_BIAS 0              // 64 floats
#define SM_WIN  256            // 128 floats
#define SM_AB   1024
#define A_HI(b) (SM_AB + (b) * 16384)          // hi 8KB, lo at +8192
#define SM_WB   (SM_AB + 2 * 16384)            // 33792
#define W_HI(b) (SM_WB + (b) * 16384)          // hi 8KB, lo at +8192
#define SM_USED (SM_WB + 3 * 16384)            // 82944
#define SM_REQ  (SM_USED + 1024)

// ---------------- helpers ----------------
__device__ __forceinline__ uint32_t smem_u32(const void* p) {
    uint32_t a;
    asm("{ .reg .u64 t; cvta.to.shared.u64 t, %1; cvt.u32.u64 %0, t; }" : "=r"(a) : "l"(p));
    return a;
}
__device__ __forceinline__ uint32_t swz(uint32_t o) { return o ^ ((o >> 3) & 0x70); }

__device__ __forceinline__ void ldmx4(uint32_t r[4], uint32_t addr) {
    asm volatile("ldmatrix.sync.aligned.m8n8.x4.shared.b16 {%0,%1,%2,%3}, [%4];"
        : "=r"(r[0]), "=r"(r[1]), "=r"(r[2]), "=r"(r[3]) : "r"(addr));
}
__device__ __forceinline__ void mma16816(float d[4], const uint32_t a[4], uint32_t b0, uint32_t b1) {
    asm volatile("mma.sync.aligned.m16n8k16.row.col.f32.bf16.bf16.f32 "
        "{%0,%1,%2,%3}, {%4,%5,%6,%7}, {%8,%9}, {%0,%1,%2,%3};"
        : "+f"(d[0]), "+f"(d[1]), "+f"(d[2]), "+f"(d[3])
        : "r"(a[0]), "r"(a[1]), "r"(a[2]), "r"(a[3]), "r"(b0), "r"(b1));
}
__device__ __forceinline__ void cpasync16(uint32_t dst, const void* src) {
    asm volatile("cp.async.cg.shared.global [%0], [%1], 16;" :: "r"(dst), "l"(src));
}
#define CP_COMMIT() asm volatile("cp.async.commit_group;" ::: "memory")

__device__ __forceinline__ float fast_tanh(float x) {
    return 1.0f - __fdividef(2.0f, __expf(2.0f * x) + 1.0f);
}

// mma over one 32-row A fragment against 4 n8 blocks
__device__ __forceinline__ void mma_row(float accRow[4][4], const uint32_t A[4],
                                        const uint32_t W0[4], const uint32_t W1[4]) {
    mma16816(accRow[0], A, W0[0], W0[1]);
    mma16816(accRow[1], A, W0[2], W0[3]);
    mma16816(accRow[2], A, W1[0], W1[1]);
    mma16816(accRow[3], A, W1[2], W1[3]);
}

// ---------------- GEMM mainloop (64x64 CTA tile, K=1536 in 24 chunks) ----------------
template <typename AFUN>
__device__ __forceinline__ void gemm_core(char* sm, uint32_t sb, int tid, AFUN afun,
                                          const __nv_bfloat16* __restrict__ whi,
                                          const __nv_bfloat16* __restrict__ wlo,
                                          int bn, float acc[2][4][4]) {
    int lane = tid & 31, wrp = tid >> 5;
    int warpm = wrp >> 1, warpn = wrp & 1;
    uint32_t a_off = (uint32_t)((warpm * 32 + (lane & 15)) * 128 + ((lane >> 4) & 1) * 16);
    uint32_t b_off = (uint32_t)((warpn * 32 + ((lane >> 4) & 1) * 8 + (lane & 7)) * 128 +
                                ((lane >> 3) & 1) * 16);
    int arow = tid >> 1;          // A row this thread loads (0..63)
    int acol = (tid & 1) * 32;    // starting float column (0 or 32)

    auto issueW = [&](int c) {
        int k0 = c * 64;
        uint32_t wh = sb + W_HI(c % 3);
        #pragma unroll
        for (int j = 0; j < 4; j++) {
            int u = tid + 128 * j;
            int row = u >> 3, kk = u & 7;
            size_t goff = (size_t)(bn + row) * PT + k0 + kk * 8;
            uint32_t d1 = wh + swz((uint32_t)(row * 128 + kk * 16));
            cpasync16(d1, whi + goff);
            cpasync16(d1 + 8192, wlo + goff);
        }
        CP_COMMIT();
    };
    auto loadA = [&](int c, float4 ar[8]) {
        const float* ab; size_t astr;
        afun(c, ab, astr);
        const float* p = ab + (size_t)arow * astr + acol;
        #pragma unroll
        for (int i = 0; i < 8; i++) ar[i] = *reinterpret_cast<const float4*>(p + i * 4);
    };
    auto storeA = [&](int c, const float4 ar[8]) {
        uint32_t base = (uint32_t)A_HI(c & 1);
        #pragma unroll
        for (int i = 0; i < 8; i++) {
            float4 v = ar[i];
            __nv_bfloat16 hx = __float2bfloat16(v.x), hy = __float2bfloat16(v.y);
            __nv_bfloat16 hz = __float2bfloat16(v.z), hw = __float2bfloat16(v.w);
            __nv_bfloat16 lx = __float2bfloat16(v.x - __bfloat162float(hx));
            __nv_bfloat16 ly = __float2bfloat16(v.y - __bfloat162float(hy));
            __nv_bfloat16 lz = __float2bfloat16(v.z - __bfloat162float(hz));
            __nv_bfloat16 lw = __float2bfloat16(v.w - __bfloat162float(hw));
            uint2 h2 = make_uint2(
                (uint32_t)__bfloat16_as_ushort(hx) | ((uint32_t)__bfloat16_as_ushort(hy) << 16),
                (uint32_t)__bfloat16_as_ushort(hz) | ((uint32_t)__bfloat16_as_ushort(hw) << 16));
            uint2 l2 = make_uint2(
                (uint32_t)__bfloat16_as_ushort(lx) | ((uint32_t)__bfloat16_as_ushort(ly) << 16),
                (uint32_t)__bfloat16_as_ushort(lz) | ((uint32_t)__bfloat16_as_ushort(lw) << 16));
            uint32_t off = swz((uint32_t)(arow * 128 + acol * 2 + i * 8));
            *reinterpret_cast<uint2*>(sm + base + off) = h2;
            *reinterpret_cast<uint2*>(sm + base + 8192 + off) = l2;
        }
    };

    // prologue
    issueW(0);
    issueW(1);
    { float4 ar[8]; loadA(0, ar); storeA(0, ar); }

    for (int c = 0; c < NCHUNK; c++) {
        float4 ar[8];
        bool hn = (c + 1 < NCHUNK);
        if (hn) loadA(c + 1, ar);                              // issue LDGs early
        if (c < NCHUNK - 1) asm volatile("cp.async.wait_group 1;" ::: "memory");
        else                asm volatile("cp.async.wait_group 0;" ::: "memory");
        __syncthreads();                                       // W(c), A(c) visible; buffers free
        if (c + 2 < NCHUNK) issueW(c + 2);

        uint32_t ah = sb + A_HI(c & 1), al = ah + 8192;
        uint32_t wh = sb + W_HI(c % 3), wl = wh + 8192;
        #pragma unroll
        for (int ks = 0; ks < 4; ks++) {
            uint32_t Ah0[4], Ah1[4], Al0[4], Al1[4], Wh0[4], Wh1[4], Wl0[4], Wl1[4];
            uint32_t ao = a_off + ks * 32, bo = b_off + ks * 32;
            ldmx4(Ah0, ah + swz(ao)); ldmx4(Ah1, ah + swz(ao + 2048));
            ldmx4(Al0, al + swz(ao)); ldmx4(Al1, al + swz(ao + 2048));
            ldmx4(Wh0, wh + swz(bo)); ldmx4(Wh1, wh + swz(bo + 2048));
            ldmx4(Wl0, wl + swz(bo)); ldmx4(Wl1, wl + swz(bo + 2048));
            mma_row(acc[0], Ah0, Wh0, Wh1);
            mma_row(acc[1], Ah1, Wh0, Wh1);
            mma_row(acc[0], Al0, Wh0, Wh1);
            mma_row(acc[1], Al1, Wh0, Wh1);
            mma_row(acc[0], Ah0, Wl0, Wl1);
            mma_row(acc[1], Ah1, Wl0, Wl1);
        }
        if (hn) storeA(c + 1, ar);     // into the buffer NOT read this iter; sync at next top
    }
}

// ---------------- pack: fuse biases, split weights to bf16 hi/lo ----------------
__global__ void pack_kernel(const float* __restrict__ W_rec1, const float* __restrict__ b_rec1,
                            const float* __restrict__ W_rec2, const float* __restrict__ b_rec2,
                            const float* __restrict__ W_12,   const float* __restrict__ b_12,
                            const float* __restrict__ W_21,   const float* __restrict__ b_21,
                            const float* __restrict__ W_in1,  const float* __restrict__ b_in1,
                            const float* __restrict__ W_in2,  const float* __restrict__ b_in2,
                            const float* __restrict__ W_out) {
    int idx = blockIdx.x * blockDim.x + threadIdx.x;
    int stride = gridDim.x * blockDim.x;
    for (int i = idx; i < PT * PT; i += stride) {
        int n = i / PT, k = i % PT;
        float v;
        if (n < P1) v = (k < P1) ? W_rec1[n * P1 + k] : W_21[n * P2 + (k - P1)];
        else {
            int n2 = n - P1;
            v = (k < P1) ? W_12[n2 * P1 + k] : W_rec2[n2 * P2 + (k - P1)];
        }
        __nv_bfloat16 h = __float2bfloat16(v);
        g_Whi[i] = h;
        g_Wlo[i] = __float2bfloat16(v - __bfloat162float(h));
    }
    for (int i = idx; i < O * PT; i += stride) {
        float v = W_out[i];
        __nv_bfloat16 h = __float2bfloat16(v);
        g_Wouthi[i] = h;
        g_Woutlo[i] = __float2bfloat16(v - __bfloat162float(h));
    }
    for (int n = idx; n < PT; n += stride) {
        if (n < P1) {
            g_bias[n] = b_rec1[n] + b_21[n] + b_in1[n];
            g_win[2 * n]     = W_in1[2 * n];
            g_win[2 * n + 1] = W_in1[2 * n + 1];
        } else {
            int n2 = n - P1;
            g_bias[n] = b_rec2[n2] + b_12[n2] + b_in2[n2];
            g_win[2 * n]     = W_in2[2 * n2];
            g_win[2 * n + 1] = W_in2[2 * n2 + 1];
        }
    }
}

// ---------------- init: h0 = place @ [W_h1;W_h2].T (fp32 SIMT, tiny) ----------------
__global__ void init_kernel(const float* __restrict__ place,
                            const float* __restrict__ Wh1,
                            const float* __restrict__ Wh2) {
    __shared__ float As[16][65];
    __shared__ float Ws[16][65];
    int tid = threadIdx.x;
    int bn = blockIdx.x * 64;
    int bm = blockIdx.y * 64;
    float acc[4][4] = {};
    for (int k0 = 0; k0 < O; k0 += 16) {
        #pragma unroll
        for (int i = 0; i < 4; i++) {
            int lin = tid + 256 * i;
            int r = lin >> 4, c = lin & 15;
            As[c][r] = place[(bm + r) * O + k0 + c];
            int n = bn + r;
            Ws[c][r] = (n < P1) ? Wh1[n * O + k0 + c] : Wh2[(n - P1) * O + k0 + c];
        }
        __syncthreads();
        #pragma unroll
        for (int c = 0; c < 16; c++) {
            float af[4], wf[4];
            int ty = tid >> 4, tx = tid & 15;
            #pragma unroll
            for (int j = 0; j < 4; j++) { af[j] = As[c][ty * 4 + j]; wf[j] = Ws[c][tx * 4 + j]; }
            #pragma unroll
            for (int a = 0; a < 4; a++)
                #pragma unroll
                for (int b2 = 0; b2 < 4; b2++)
                    acc[a][b2] = fmaf(af[a], wf[b2], acc[a][b2]);
        }
        __syncthreads();
    }
    int ty = tid >> 4, tx = tid & 15;
    #pragma unroll
    for (int a = 0; a < 4; a++)
        #pragma unroll
        for (int b2 = 0; b2 < 4; b2++)
            g_h0[(bm + ty * 4 + a) * PT + bn + tx * 4 + b2] = acc[a][b2];
}

// ---------------- step kernel ----------------
__global__ void __launch_bounds__(128)
step_kernel(int step, const float* __restrict__ inputs,
            float* __restrict__ oh1, float* __restrict__ oh2) {
    extern __shared__ char smraw[];
    char* sm = (char*)(((uintptr_t)smraw + 1023) & ~(uintptr_t)1023);
    uint32_t sb = smem_u32(sm);
    int tid = threadIdx.x;
    int bn = blockIdx.x * 64;
    int bm = blockIdx.y * 64;

    float* bias_s = reinterpret_cast<float*>(sm + SM_BIAS);
    float* win_s  = reinterpret_cast<float*>(sm + SM_WIN);
    if (tid < 64) bias_s[tid] = g_bias[bn + tid];
    win_s[tid] = g_win[2 * bn + tid];
    // (first __syncthreads inside gemm_core covers these)

    float acc[2][4][4] = {};
    auto afun = [&](int c, const float*& ab, size_t& astr) {
        int k0 = c * 64;
        if (step == 0)    { ab = g_h0 + (size_t)bm * PT + k0;                        astr = PT; }
        else if (k0 < P1) { ab = oh1 + ((size_t)bm * T + step - 1) * P1 + k0;        astr = (size_t)T * P1; }
        else              { ab = oh2 + ((size_t)bm * T + step - 1) * P2 + (k0 - P1); astr = (size_t)T * P2; }
    };
    gemm_core(sm, sb, tid, afun, g_Whi, g_Wlo, bn, acc);

    int lane = tid & 31, wrp = tid >> 5;
    int warpm = wrp >> 1, warpn = wrp & 1;
    float alpha = (bn < P1) ? 0.1f : 0.05f;
    float oma = 1.0f - alpha;

    #pragma unroll
    for (int mi = 0; mi < 2; mi++) {
        #pragma unroll
        for (int half = 0; half < 2; half++) {
            int r = bm + warpm * 32 + mi * 16 + (lane >> 2) + half * 8;
            float2 xv = *reinterpret_cast<const float2*>(inputs + ((size_t)r * T + step) * 2);
            const float* hrow;
            float* orow;
            if (bn < P1) {
                hrow = (step == 0) ? g_h0 + (size_t)r * PT + bn
                                   : oh1 + ((size_t)r * T + step - 1) * P1 + bn;
                orow = oh1 + ((size_t)r * T + step) * P1 + bn;
            } else {
                hrow = (step == 0) ? g_h0 + (size_t)r * PT + bn
                                   : oh2 + ((size_t)r * T + step - 1) * P2 + (bn - P1);
                orow = oh2 + ((size_t)r * T + step) * P2 + (bn - P1);
            }
            #pragma unroll
            for (int nj = 0; nj < 4; nj++) {
                int cc = warpn * 32 + nj * 8 + 2 * (lane & 3);
                float2 h2 = *reinterpret_cast<const float2*>(hrow + cc);
                float v0 = acc[mi][nj][half * 2 + 0] + bias_s[cc] +
                           xv.x * win_s[2 * cc] + xv.y * win_s[2 * cc + 1];
                float v1 = acc[mi][nj][half * 2 + 1] + bias_s[cc + 1] +
                           xv.x * win_s[2 * cc + 2] + xv.y * win_s[2 * cc + 3];
                float2 o2;
                o2.x = oma * h2.x + alpha * fast_tanh(v0);
                o2.y = oma * h2.y + alpha * fast_tanh(v1);
                *reinterpret_cast<float2*>(orow + cc) = o2;
            }
        }
    }
}

// ---------------- output projection kernel ----------------
__global__ void __launch_bounds__(128)
out_kernel(const float* __restrict__ oh1, const float* __restrict__ oh2,
           float* __restrict__ out2) {
    extern __shared__ char smraw[];
    char* sm = (char*)(((uintptr_t)smraw + 1023) & ~(uintptr_t)1023);
    uint32_t sb = smem_u32(sm);
    int tid = threadIdx.x;
    int bn = blockIdx.x * 64;      // over O
    int bm = blockIdx.y * 64;      // over B*T

    float acc[2][4][4] = {};
    auto afun = [&](int c, const float*& ab, size_t& astr) {
        int k0 = c * 64;
        if (k0 < P1) { ab = oh1 + (size_t)bm * P1 + k0;        astr = P1; }
        else         { ab = oh2 + (size_t)bm * P2 + (k0 - P1); astr = P2; }
    };
    gemm_core(sm, sb, tid, afun, g_Wouthi, g_Woutlo, bn, acc);

    int lane = tid & 31, wrp = tid >> 5;
    int warpm = wrp >> 1, warpn = wrp & 1;
    #pragma unroll
    for (int mi = 0; mi < 2; mi++) {
        #pragma unroll
        for (int half = 0; half < 2; half++) {
            size_t m = (size_t)bm + warpm * 32 + mi * 16 + (lane >> 2) + half * 8;
            #pragma unroll
            for (int nj = 0; nj < 4; nj++) {
                int cc = warpn * 32 + nj * 8 + 2 * (lane & 3);
                float2 o2;
                o2.x = acc[mi][nj][half * 2 + 0];
                o2.y = acc[mi][nj][half * 2 + 1];
                *reinterpret_cast<float2*>(out2 + m * O + bn + cc) = o2;
            }
        }
    }
}

// ---------------- host ----------------
extern "C" void kernel_launch(void* const* d_in, const int* in_sizes, int n_in,
                              void* d_out, int out_size) {
    const float* inputs  = (const float*)d_in[0];
    const float* place0  = (const float*)d_in[1];
    const float* W_in1   = (const float*)d_in[2];
    const float* b_in1   = (const float*)d_in[3];
    const float* W_in2   = (const float*)d_in[4];
    const float* b_in2   = (const float*)d_in[5];
    const float* W_rec1  = (const float*)d_in[6];
    const float* b_rec1  = (const float*)d_in[7];
    const float* W_rec2  = (const float*)d_in[8];
    const float* b_rec2  = (const float*)d_in[9];
    const float* W_12    = (const float*)d_in[10];
    const float* b_12    = (const float*)d_in[11];
    const float* W_21    = (const float*)d_in[12];
    const float* b_21    = (const float*)d_in[13];
    const float* W_out   = (const float*)d_in[14];
    const float* W_h1    = (const float*)d_in[15];
    const float* W_h2    = (const float*)d_in[16];

    float* oh1  = (float*)d_out;
    float* oh2  = oh1 + (size_t)B * T * P1;
    float* out2 = oh2 + (size_t)B * T * P2;

    static bool attr_set = false;
    if (!attr_set) {
        cudaFuncSetAttribute(step_kernel, cudaFuncAttributeMaxDynamicSharedMemorySize, SM_REQ);
        cudaFuncSetAttribute(out_kernel,  cudaFuncAttributeMaxDynamicSharedMemorySize, SM_REQ);
        attr_set = true;
    }

    pack_kernel<<<256, 256>>>(W_rec1, b_rec1, W_rec2, b_rec2,
                              W_12, b_12, W_21, b_21,
                              W_in1, b_in1, W_in2, b_in2, W_out);

    {
        dim3 grid(PT / 64, B / 64);
        init_kernel<<<grid, 256>>>(place0, W_h1, W_h2);
    }

    {
        dim3 grid(PT / 64, B / 64);   // 24 x 4 = 96 CTAs
        for (int t = 0; t < T; t++)
            step_kernel<<<grid, 128, SM_REQ>>>(t, inputs, oh1, oh2);
    }

    {
        dim3 grid(O / 64, (B * T) / 64);  // 8 x 800
        out_kernel<<<grid, 128, SM_REQ>>>(oh1, oh2, out2);
    }
}

// round 4
// speedup vs baseline: 3.1963x; 1.1547x over previous
#include <cuda_runtime.h>
#include <cuda_bf16.h>
#include <cstdint>

#define B 256
#define T 200
#define P1 1024
#define P2 512
#define PT 1536
#define O 512
#define NCHUNK 24        // K chunks of 64

// ---------------- device scratch ----------------
__device__ float g_bias[PT];
__device__ float g_win[2 * PT];
__device__ float g_h0[B * PT];
__device__ __nv_bfloat16 g_Whi[PT * PT];
__device__ __nv_bfloat16 g_Wlo[PT * PT];
__device__ __nv_bfloat16 g_Wouthi[O * PT];
__device__ __nv_bfloat16 g_Woutlo[O * PT];

// ---------------- smem layout (offsets from 1024-aligned base) ----------------
#define SM_BIAS 0              // 64 floats
#define SM_WIN  256            // 128 floats
#define SM_AB   1024
#define A_HI(b) (SM_AB + (b) * 16384)          // hi 8KB, lo at +8192
#define SM_WB   (SM_AB + 2 * 16384)
#define W_HI(b) (SM_WB + (b) * 16384)          // hi 8KB, lo at +8192
#define SM_USED (SM_WB + 3 * 16384)
#define SM_REQ  (SM_USED + 1024)

// ---------------- helpers ----------------
__device__ __forceinline__ uint32_t smem_u32(const void* p) {
    uint32_t a;
    asm("{ .reg .u64 t; cvta.to.shared.u64 t, %1; cvt.u32.u64 %0, t; }" : "=r"(a) : "l"(p));
    return a;
}
__device__ __forceinline__ uint32_t swz(uint32_t o) { return o ^ ((o >> 3) & 0x70); }

__device__ __forceinline__ void ldmx4(uint32_t r[4], uint32_t addr) {
    asm volatile("ldmatrix.sync.aligned.m8n8.x4.shared.b16 {%0,%1,%2,%3}, [%4];"
        : "=r"(r[0]), "=r"(r[1]), "=r"(r[2]), "=r"(r[3]) : "r"(addr));
}
__device__ __forceinline__ void mma16816(float d[4], const uint32_t a[4], uint32_t b0, uint32_t b1) {
    asm volatile("mma.sync.aligned.m16n8k16.row.col.f32.bf16.bf16.f32 "
        "{%0,%1,%2,%3}, {%4,%5,%6,%7}, {%8,%9}, {%0,%1,%2,%3};"
        : "+f"(d[0]), "+f"(d[1]), "+f"(d[2]), "+f"(d[3])
        : "r"(a[0]), "r"(a[1]), "r"(a[2]), "r"(a[3]), "r"(b0), "r"(b1));
}
__device__ __forceinline__ void cpasync16(uint32_t dst, const void* src) {
    asm volatile("cp.async.cg.shared.global [%0], [%1], 16;" :: "r"(dst), "l"(src));
}
#define CP_COMMIT() asm volatile("cp.async.commit_group;" ::: "memory")

__device__ __forceinline__ float fast_tanh(float x) {
    return 1.0f - __fdividef(2.0f, __expf(2.0f * x) + 1.0f);
}

// ---------------- GEMM mainloop (64x64 CTA tile, 256 threads, 8 warps 4x2) ----------------
template <typename AFUN>
__device__ __forceinline__ void gemm_core(char* sm, uint32_t sb, int tid, AFUN afun,
                                          const __nv_bfloat16* __restrict__ whi,
                                          const __nv_bfloat16* __restrict__ wlo,
                                          int bn, float acc[4][4]) {
    int lane = tid & 31, wrp = tid >> 5;
    int warpm = wrp & 3;          // 0..3 -> 16 rows each
    int warpn = wrp >> 2;         // 0..1 -> 32 cols each
    uint32_t a_off = (uint32_t)((warpm * 16 + (lane & 15)) * 128 + ((lane >> 4) & 1) * 16);
    uint32_t b_off = (uint32_t)((warpn * 32 + ((lane >> 4) & 1) * 8 + (lane & 7)) * 128 +
                                ((lane >> 3) & 1) * 16);
    int arow = tid >> 2;            // 0..63
    int acol = (tid & 3) * 16;      // float col 0/16/32/48

    auto issueW = [&](int c) {
        int k0 = c * 64;
        uint32_t wh = sb + W_HI(c % 3);
        #pragma unroll
        for (int j = 0; j < 2; j++) {
            int u = tid + 256 * j;
            int row = u >> 3, kk = u & 7;
            size_t goff = (size_t)(bn + row) * PT + k0 + kk * 8;
            uint32_t d1 = wh + swz((uint32_t)(row * 128 + kk * 16));
            cpasync16(d1, whi + goff);
            cpasync16(d1 + 8192, wlo + goff);
        }
        CP_COMMIT();
    };
    auto loadA = [&](int c, float4 ar[4]) {
        const float* ab; size_t astr;
        afun(c, ab, astr);
        const float* p = ab + (size_t)arow * astr + acol;
        #pragma unroll
        for (int i = 0; i < 4; i++) ar[i] = *reinterpret_cast<const float4*>(p + i * 4);
    };
    auto storeA = [&](int c, const float4 ar[4]) {
        uint32_t base = (uint32_t)A_HI(c & 1);
        #pragma unroll
        for (int i = 0; i < 4; i++) {
            float4 v = ar[i];
            __nv_bfloat16 hx = __float2bfloat16(v.x), hy = __float2bfloat16(v.y);
            __nv_bfloat16 hz = __float2bfloat16(v.z), hw = __float2bfloat16(v.w);
            __nv_bfloat16 lx = __float2bfloat16(v.x - __bfloat162float(hx));
            __nv_bfloat16 ly = __float2bfloat16(v.y - __bfloat162float(hy));
            __nv_bfloat16 lz = __float2bfloat16(v.z - __bfloat162float(hz));
            __nv_bfloat16 lw = __float2bfloat16(v.w - __bfloat162float(hw));
            uint2 h2 = make_uint2(
                (uint32_t)__bfloat16_as_ushort(hx) | ((uint32_t)__bfloat16_as_ushort(hy) << 16),
                (uint32_t)__bfloat16_as_ushort(hz) | ((uint32_t)__bfloat16_as_ushort(hw) << 16));
            uint2 l2 = make_uint2(
                (uint32_t)__bfloat16_as_ushort(lx) | ((uint32_t)__bfloat16_as_ushort(ly) << 16),
                (uint32_t)__bfloat16_as_ushort(lz) | ((uint32_t)__bfloat16_as_ushort(lw) << 16));
            uint32_t off = swz((uint32_t)(arow * 128 + acol * 2 + i * 8));
            *reinterpret_cast<uint2*>(sm + base + off) = h2;
            *reinterpret_cast<uint2*>(sm + base + 8192 + off) = l2;
        }
    };

    // prologue
    issueW(0);
    issueW(1);
    { float4 ar[4]; loadA(0, ar); storeA(0, ar); }

    for (int c = 0; c < NCHUNK; c++) {
        float4 ar[4];
        bool hn = (c + 1 < NCHUNK);
        if (hn) loadA(c + 1, ar);                              // issue LDGs early
        if (c < NCHUNK - 1) asm volatile("cp.async.wait_group 1;" ::: "memory");
        else                asm volatile("cp.async.wait_group 0;" ::: "memory");
        __syncthreads();                                       // W(c), A(c) visible; buffers free
        if (c + 2 < NCHUNK) issueW(c + 2);

        uint32_t ah = sb + A_HI(c & 1), al = ah + 8192;
        uint32_t wh = sb + W_HI(c % 3), wl = wh + 8192;
        #pragma unroll
        for (int ks = 0; ks < 4; ks++) {
            uint32_t Ah[4], Al[4], Wh0[4], Wh1[4], Wl0[4], Wl1[4];
            uint32_t ao = a_off + ks * 32, bo = b_off + ks * 32;
            ldmx4(Ah, ah + swz(ao));
            ldmx4(Al, al + swz(ao));
            ldmx4(Wh0, wh + swz(bo)); ldmx4(Wh1, wh + swz(bo + 2048));
            ldmx4(Wl0, wl + swz(bo)); ldmx4(Wl1, wl + swz(bo + 2048));
            // pass 1: Ahi * Whi
            mma16816(acc[0], Ah, Wh0[0], Wh0[1]);
            mma16816(acc[1], Ah, Wh0[2], Wh0[3]);
            mma16816(acc[2], Ah, Wh1[0], Wh1[1]);
            mma16816(acc[3], Ah, Wh1[2], Wh1[3]);
            // pass 2: Alo * Whi
            mma16816(acc[0], Al, Wh0[0], Wh0[1]);
            mma16816(acc[1], Al, Wh0[2], Wh0[3]);
            mma16816(acc[2], Al, Wh1[0], Wh1[1]);
            mma16816(acc[3], Al, Wh1[2], Wh1[3]);
            // pass 3: Ahi * Wlo
            mma16816(acc[0], Ah, Wl0[0], Wl0[1]);
            mma16816(acc[1], Ah, Wl0[2], Wl0[3]);
            mma16816(acc[2], Ah, Wl1[0], Wl1[1]);
            mma16816(acc[3], Ah, Wl1[2], Wl1[3]);
        }
        if (hn) storeA(c + 1, ar);     // into the buffer NOT read this iter; sync at next top
    }
}

// ---------------- pack: fuse biases, split weights to bf16 hi/lo ----------------
__global__ void pack_kernel(const float* __restrict__ W_rec1, const float* __restrict__ b_rec1,
                            const float* __restrict__ W_rec2, const float* __restrict__ b_rec2,
                            const float* __restrict__ W_12,   const float* __restrict__ b_12,
                            const float* __restrict__ W_21,   const float* __restrict__ b_21,
                            const float* __restrict__ W_in1,  const float* __restrict__ b_in1,
                            const float* __restrict__ W_in2,  const float* __restrict__ b_in2,
                            const float* __restrict__ W_out) {
    int idx = blockIdx.x * blockDim.x + threadIdx.x;
    int stride = gridDim.x * blockDim.x;
    for (int i = idx; i < PT * PT; i += stride) {
        int n = i / PT, k = i % PT;
        float v;
        if (n < P1) v = (k < P1) ? W_rec1[n * P1 + k] : W_21[n * P2 + (k - P1)];
        else {
            int n2 = n - P1;
            v = (k < P1) ? W_12[n2 * P1 + k] : W_rec2[n2 * P2 + (k - P1)];
        }
        __nv_bfloat16 h = __float2bfloat16(v);
        g_Whi[i] = h;
        g_Wlo[i] = __float2bfloat16(v - __bfloat162float(h));
    }
    for (int i = idx; i < O * PT; i += stride) {
        float v = W_out[i];
        __nv_bfloat16 h = __float2bfloat16(v);
        g_Wouthi[i] = h;
        g_Woutlo[i] = __float2bfloat16(v - __bfloat162float(h));
    }
    for (int n = idx; n < PT; n += stride) {
        if (n < P1) {
            g_bias[n] = b_rec1[n] + b_21[n] + b_in1[n];
            g_win[2 * n]     = W_in1[2 * n];
            g_win[2 * n + 1] = W_in1[2 * n + 1];
        } else {
            int n2 = n - P1;
            g_bias[n] = b_rec2[n2] + b_12[n2] + b_in2[n2];
            g_win[2 * n]     = W_in2[2 * n2];
            g_win[2 * n + 1] = W_in2[2 * n2 + 1];
        }
    }
}

// ---------------- init: h0 = place @ [W_h1;W_h2].T (fp32 SIMT, tiny) ----------------
__global__ void init_kernel(const float* __restrict__ place,
                            const float* __restrict__ Wh1,
                            const float* __restrict__ Wh2) {
    __shared__ float As[16][65];
    __shared__ float Ws[16][65];
    int tid = threadIdx.x;
    int bn = blockIdx.x * 64;
    int bm = blockIdx.y * 64;
    float acc[4][4] = {};
    for (int k0 = 0; k0 < O; k0 += 16) {
        #pragma unroll
        for (int i = 0; i < 4; i++) {
            int lin = tid + 256 * i;
            int r = lin >> 4, c = lin & 15;
            As[c][r] = place[(bm + r) * O + k0 + c];
            int n = bn + r;
            Ws[c][r] = (n < P1) ? Wh1[n * O + k0 + c] : Wh2[(n - P1) * O + k0 + c];
        }
        __syncthreads();
        #pragma unroll
        for (int c = 0; c < 16; c++) {
            float af[4], wf[4];
            int ty = tid >> 4, tx = tid & 15;
            #pragma unroll
            for (int j = 0; j < 4; j++) { af[j] = As[c][ty * 4 + j]; wf[j] = Ws[c][tx * 4 + j]; }
            #pragma unroll
            for (int a = 0; a < 4; a++)
                #pragma unroll
                for (int b2 = 0; b2 < 4; b2++)
                    acc[a][b2] = fmaf(af[a], wf[b2], acc[a][b2]);
        }
        __syncthreads();
    }
    int ty = tid >> 4, tx = tid & 15;
    #pragma unroll
    for (int a = 0; a < 4; a++)
        #pragma unroll
        for (int b2 = 0; b2 < 4; b2++)
            g_h0[(bm + ty * 4 + a) * PT + bn + tx * 4 + b2] = acc[a][b2];
}

// ---------------- step kernel ----------------
__global__ void __launch_bounds__(256)
step_kernel(int step, const float* __restrict__ inputs,
            float* __restrict__ oh1, float* __restrict__ oh2) {
    extern __shared__ char smraw[];
    char* sm = (char*)(((uintptr_t)smraw + 1023) & ~(uintptr_t)1023);
    uint32_t sb = smem_u32(sm);
    int tid = threadIdx.x;
    int bn = blockIdx.x * 64;
    int bm = blockIdx.y * 64;

    float* bias_s = reinterpret_cast<float*>(sm + SM_BIAS);
    float* win_s  = reinterpret_cast<float*>(sm + SM_WIN);
    if (tid < 64) bias_s[tid] = g_bias[bn + tid];
    if (tid < 128) win_s[tid] = g_win[2 * bn + tid];
    // (first __syncthreads inside gemm_core covers these)

    float acc[4][4] = {};
    auto afun = [&](int c, const float*& ab, size_t& astr) {
        int k0 = c * 64;
        if (step == 0)    { ab = g_h0 + (size_t)bm * PT + k0;                        astr = PT; }
        else if (k0 < P1) { ab = oh1 + ((size_t)bm * T + step - 1) * P1 + k0;        astr = (size_t)T * P1; }
        else              { ab = oh2 + ((size_t)bm * T + step - 1) * P2 + (k0 - P1); astr = (size_t)T * P2; }
    };
    gemm_core(sm, sb, tid, afun, g_Whi, g_Wlo, bn, acc);

    int lane = tid & 31, wrp = tid >> 5;
    int warpm = wrp & 3, warpn = wrp >> 2;
    float alpha = (bn < P1) ? 0.1f : 0.05f;
    float oma = 1.0f - alpha;

    #pragma unroll
    for (int half = 0; half < 2; half++) {
        int r = bm + warpm * 16 + (lane >> 2) + half * 8;
        float2 xv = *reinterpret_cast<const float2*>(inputs + ((size_t)r * T + step) * 2);
        const float* hrow;
        float* orow;
        if (bn < P1) {
            hrow = (step == 0) ? g_h0 + (size_t)r * PT + bn
                               : oh1 + ((size_t)r * T + step - 1) * P1 + bn;
            orow = oh1 + ((size_t)r * T + step) * P1 + bn;
        } else {
            hrow = (step == 0) ? g_h0 + (size_t)r * PT + bn
                               : oh2 + ((size_t)r * T + step - 1) * P2 + (bn - P1);
            orow = oh2 + ((size_t)r * T + step) * P2 + (bn - P1);
        }
        #pragma unroll
        for (int nj = 0; nj < 4; nj++) {
            int cc = warpn * 32 + nj * 8 + 2 * (lane & 3);
            float2 h2 = *reinterpret_cast<const float2*>(hrow + cc);
            float v0 = acc[nj][half * 2 + 0] + bias_s[cc] +
                       xv.x * win_s[2 * cc] + xv.y * win_s[2 * cc + 1];
            float v1 = acc[nj][half * 2 + 1] + bias_s[cc + 1] +
                       xv.x * win_s[2 * cc + 2] + xv.y * win_s[2 * cc + 3];
            float2 o2;
            o2.x = oma * h2.x + alpha * fast_tanh(v0);
            o2.y = oma * h2.y + alpha * fast_tanh(v1);
            *reinterpret_cast<float2*>(orow + cc) = o2;
        }
    }
}

// ---------------- output projection kernel ----------------
__global__ void __launch_bounds__(256)
out_kernel(const float* __restrict__ oh1, const float* __restrict__ oh2,
           float* __restrict__ out2) {
    extern __shared__ char smraw[];
    char* sm = (char*)(((uintptr_t)smraw + 1023) & ~(uintptr_t)1023);
    uint32_t sb = smem_u32(sm);
    int tid = threadIdx.x;
    int bn = blockIdx.x * 64;      // over O
    int bm = blockIdx.y * 64;      // over B*T

    float acc[4][4] = {};
    auto afun = [&](int c, const float*& ab, size_t& astr) {
        int k0 = c * 64;
        if (k0 < P1) { ab = oh1 + (size_t)bm * P1 + k0;        astr = P1; }
        else         { ab = oh2 + (size_t)bm * P2 + (k0 - P1); astr = P2; }
    };
    gemm_core(sm, sb, tid, afun, g_Wouthi, g_Woutlo, bn, acc);

    int lane = tid & 31, wrp = tid >> 5;
    int warpm = wrp & 3, warpn = wrp >> 2;
    #pragma unroll
    for (int half = 0; half < 2; half++) {
        size_t m = (size_t)bm + warpm * 16 + (lane >> 2) + half * 8;
        #pragma unroll
        for (int nj = 0; nj < 4; nj++) {
            int cc = warpn * 32 + nj * 8 + 2 * (lane & 3);
            float2 o2;
            o2.x = acc[nj][half * 2 + 0];
            o2.y = acc[nj][half * 2 + 1];
            *reinterpret_cast<float2*>(out2 + m * O + bn + cc) = o2;
        }
    }
}

// ---------------- host ----------------
extern "C" void kernel_launch(void* const* d_in, const int* in_sizes, int n_in,
                              void* d_out, int out_size) {
    const float* inputs  = (const float*)d_in[0];
    const float* place0  = (const float*)d_in[1];
    const float* W_in1   = (const float*)d_in[2];
    const float* b_in1   = (const float*)d_in[3];
    const float* W_in2   = (const float*)d_in[4];
    const float* b_in2   = (const float*)d_in[5];
    const float* W_rec1  = (const float*)d_in[6];
    const float* b_rec1  = (const float*)d_in[7];
    const float* W_rec2  = (const float*)d_in[8];
    const float* b_rec2  = (const float*)d_in[9];
    const float* W_12    = (const float*)d_in[10];
    const float* b_12    = (const float*)d_in[11];
    const float* W_21    = (const float*)d_in[12];
    const float* b_21    = (const float*)d_in[13];
    const float* W_out   = (const float*)d_in[14];
    const float* W_h1    = (const float*)d_in[15];
    const float* W_h2    = (const float*)d_in[16];

    float* oh1  = (float*)d_out;
    float* oh2  = oh1 + (size_t)B * T * P1;
    float* out2 = oh2 + (size_t)B * T * P2;

    static bool attr_set = false;
    if (!attr_set) {
        cudaFuncSetAttribute(step_kernel, cudaFuncAttributeMaxDynamicSharedMemorySize, SM_REQ);
        cudaFuncSetAttribute(out_kernel,  cudaFuncAttributeMaxDynamicSharedMemorySize, SM_REQ);
        attr_set = true;
    }

    pack_kernel<<<256, 256>>>(W_rec1, b_rec1, W_rec2, b_rec2,
                              W_12, b_12, W_21, b_21,
                              W_in1, b_in1, W_in2, b_in2, W_out);

    {
        dim3 grid(PT / 64, B / 64);
        init_kernel<<<grid, 256>>>(place0, W_h1, W_h2);
    }

    {
        dim3 grid(PT / 64, B / 64);   // 24 x 4 = 96 CTAs
        for (int t = 0; t < T; t++)
            step_kernel<<<grid, 256, SM_REQ>>>(t, inputs, oh1, oh2);
    }

    {
        dim3 grid(O / 64, (B * T) / 64);  // 8 x 800
        out_kernel<<<grid, 256, SM_REQ>>>(oh1, oh2, out2);
    }
}

// round 5
// speedup vs baseline: 5.7136x; 1.7876x over previous
#include <cuda_runtime.h>
#include <cuda_bf16.h>
#include <cstdint>

#define B 256
#define T 200
#define P1 1024
#define P2 512
#define PT 1536
#define O 512
#define NCHUNK 24        // K chunks of 64 (out_kernel)

#define NCTAS 144
#define KSPLIT 6
#define KPC 256          // K per CTA in persistent kernel

// ---------------- device scratch ----------------
__device__ float g_bias[PT];
__device__ float g_win[2 * PT];
__device__ float g_h0[B * PT];
__device__ __nv_bfloat16 g_hsplit[2 * B * PT];     // hi plane, lo plane
__device__ float g_part[KSPLIT * B * PT];          // split-K partials
__device__ __nv_bfloat16 g_Whi[PT * PT];
__device__ __nv_bfloat16 g_Wlo[PT * PT];
__device__ __nv_bfloat16 g_Wouthi[O * PT];
__device__ __nv_bfloat16 g_Woutlo[O * PT];
__device__ unsigned g_cnt;
__device__ unsigned g_gen;

// ---------------- smem layout: out_kernel (gemm_core) ----------------
#define SM_AB   1024
#define A_HI(b) (SM_AB + (b) * 16384)
#define SM_WB   (SM_AB + 2 * 16384)
#define W_HI(b) (SM_WB + (b) * 16384)
#define SM_USED (SM_WB + 3 * 16384)
#define SM_REQ  (SM_USED + 1024)

// ---------------- smem layout: persistent rnn kernel ----------------
#define PW_CH(c)  ((c) * 16384)                 // W chunk c: hi 8KB, lo +8192 (4 chunks)
#define PA_BUF(b) (65536 + (b) * 65536)         // A buf: hi 32KB, lo +32768 (2 bufs)
#define PSM_REQ   (65536 + 2 * 65536 + 1024)

// ---------------- helpers ----------------
__device__ __forceinline__ uint32_t smem_u32(const void* p) {
    uint32_t a;
    asm("{ .reg .u64 t; cvta.to.shared.u64 t, %1; cvt.u32.u64 %0, t; }" : "=r"(a) : "l"(p));
    return a;
}
__device__ __forceinline__ uint32_t swz(uint32_t o) { return o ^ ((o >> 3) & 0x70); }

__device__ __forceinline__ void ldmx4(uint32_t r[4], uint32_t addr) {
    asm volatile("ldmatrix.sync.aligned.m8n8.x4.shared.b16 {%0,%1,%2,%3}, [%4];"
        : "=r"(r[0]), "=r"(r[1]), "=r"(r[2]), "=r"(r[3]) : "r"(addr));
}
__device__ __forceinline__ void mma16816(float d[4], const uint32_t a[4], uint32_t b0, uint32_t b1) {
    asm volatile("mma.sync.aligned.m16n8k16.row.col.f32.bf16.bf16.f32 "
        "{%0,%1,%2,%3}, {%4,%5,%6,%7}, {%8,%9}, {%0,%1,%2,%3};"
        : "+f"(d[0]), "+f"(d[1]), "+f"(d[2]), "+f"(d[3])
        : "r"(a[0]), "r"(a[1]), "r"(a[2]), "r"(a[3]), "r"(b0), "r"(b1));
}
__device__ __forceinline__ void cpasync16(uint32_t dst, const void* src) {
    asm volatile("cp.async.cg.shared.global [%0], [%1], 16;" :: "r"(dst), "l"(src));
}
#define CP_COMMIT() asm volatile("cp.async.commit_group;" ::: "memory")

__device__ __forceinline__ float fast_tanh(float x) {
    return 1.0f - __fdividef(2.0f, __expf(2.0f * x) + 1.0f);
}

// grid-wide sense-reversing barrier (all NCTAS co-resident: 1 CTA/SM)
__device__ __forceinline__ void grid_bar(int tid) {
    __syncthreads();
    if (tid == 0) {
        __threadfence();
        unsigned gen = atomicAdd(&g_gen, 0u);           // read BEFORE arriving
        if (atomicAdd(&g_cnt, 1u) == NCTAS - 1u) {
            atomicExch(&g_cnt, 0u);
            __threadfence();
            atomicAdd(&g_gen, 1u);
        } else {
            while (*((volatile unsigned*)&g_gen) == gen) {}
        }
        __threadfence();
    }
    __syncthreads();
}

// ---------------- pack: fuse biases, split weights to bf16 hi/lo ----------------
__global__ void pack_kernel(const float* __restrict__ W_rec1, const float* __restrict__ b_rec1,
                            const float* __restrict__ W_rec2, const float* __restrict__ b_rec2,
                            const float* __restrict__ W_12,   const float* __restrict__ b_12,
                            const float* __restrict__ W_21,   const float* __restrict__ b_21,
                            const float* __restrict__ W_in1,  const float* __restrict__ b_in1,
                            const float* __restrict__ W_in2,  const float* __restrict__ b_in2,
                            const float* __restrict__ W_out) {
    int idx = blockIdx.x * blockDim.x + threadIdx.x;
    int stride = gridDim.x * blockDim.x;
    for (int i = idx; i < PT * PT; i += stride) {
        int n = i / PT, k = i % PT;
        float v;
        if (n < P1) v = (k < P1) ? W_rec1[n * P1 + k] : W_21[n * P2 + (k - P1)];
        else {
            int n2 = n - P1;
            v = (k < P1) ? W_12[n2 * P1 + k] : W_rec2[n2 * P2 + (k - P1)];
        }
        __nv_bfloat16 h = __float2bfloat16(v);
        g_Whi[i] = h;
        g_Wlo[i] = __float2bfloat16(v - __bfloat162float(h));
    }
    for (int i = idx; i < O * PT; i += stride) {
        float v = W_out[i];
        __nv_bfloat16 h = __float2bfloat16(v);
        g_Wouthi[i] = h;
        g_Woutlo[i] = __float2bfloat16(v - __bfloat162float(h));
    }
    for (int n = idx; n < PT; n += stride) {
        if (n < P1) {
            g_bias[n] = b_rec1[n] + b_21[n] + b_in1[n];
            g_win[2 * n]     = W_in1[2 * n];
            g_win[2 * n + 1] = W_in1[2 * n + 1];
        } else {
            int n2 = n - P1;
            g_bias[n] = b_rec2[n2] + b_12[n2] + b_in2[n2];
            g_win[2 * n]     = W_in2[2 * n2];
            g_win[2 * n + 1] = W_in2[2 * n2 + 1];
        }
    }
}

// ---------------- init: h0 = place @ [W_h1;W_h2].T + write split ----------------
__global__ void init_kernel(const float* __restrict__ place,
                            const float* __restrict__ Wh1,
                            const float* __restrict__ Wh2) {
    __shared__ float As[16][65];
    __shared__ float Ws[16][65];
    int tid = threadIdx.x;
    int bn = blockIdx.x * 64;
    int bm = blockIdx.y * 64;
    float acc[4][4] = {};
    for (int k0 = 0; k0 < O; k0 += 16) {
        #pragma unroll
        for (int i = 0; i < 4; i++) {
            int lin = tid + 256 * i;
            int r = lin >> 4, c = lin & 15;
            As[c][r] = place[(bm + r) * O + k0 + c];
            int n = bn + r;
            Ws[c][r] = (n < P1) ? Wh1[n * O + k0 + c] : Wh2[(n - P1) * O + k0 + c];
        }
        __syncthreads();
        #pragma unroll
        for (int c = 0; c < 16; c++) {
            float af[4], wf[4];
            int ty = tid >> 4, tx = tid & 15;
            #pragma unroll
            for (int j = 0; j < 4; j++) { af[j] = As[c][ty * 4 + j]; wf[j] = Ws[c][tx * 4 + j]; }
            #pragma unroll
            for (int a = 0; a < 4; a++)
                #pragma unroll
                for (int b2 = 0; b2 < 4; b2++)
                    acc[a][b2] = fmaf(af[a], wf[b2], acc[a][b2]);
        }
        __syncthreads();
    }
    int ty = tid >> 4, tx = tid & 15;
    #pragma unroll
    for (int a = 0; a < 4; a++)
        #pragma unroll
        for (int b2 = 0; b2 < 4; b2++) {
            float v = acc[a][b2];
            size_t off = (size_t)(bm + ty * 4 + a) * PT + bn + tx * 4 + b2;
            g_h0[off] = v;
            __nv_bfloat16 h = __float2bfloat16(v);
            g_hsplit[off] = h;
            g_hsplit[(size_t)B * PT + off] = __float2bfloat16(v - __bfloat162float(h));
        }
}

// ---------------- persistent RNN kernel: 200 steps, W resident in SMEM ----------------
__global__ void __launch_bounds__(256)
rnn_kernel(const float* __restrict__ inputs,
           float* __restrict__ oh1, float* __restrict__ oh2) {
    extern __shared__ char smraw[];
    char* sm = (char*)(((uintptr_t)smraw + 1023) & ~(uintptr_t)1023);
    uint32_t sb = smem_u32(sm);
    int tid = threadIdx.x;
    int cta = blockIdx.x;
    int nt = cta / KSPLIT;          // 0..23  N tile
    int ksp = cta % KSPLIT;         // 0..5   K split
    int bn = nt * 64;
    int kbase = ksp * KPC;

    // ---- load resident W slice (64 n x 256 k, hi+lo) once ----
    for (int c = 0; c < 4; c++) {
        int k0 = kbase + c * 64;
        #pragma unroll
        for (int j = 0; j < 2; j++) {
            int u = tid + 256 * j;
            int row = u >> 3, kk = u & 7;
            size_t goff = (size_t)(bn + row) * PT + k0 + kk * 8;
            uint32_t d1 = sb + PW_CH(c) + swz((uint32_t)(row * 128 + kk * 16));
            cpasync16(d1, g_Whi + goff);
            cpasync16(d1 + 8192, g_Wlo + goff);
        }
    }
    CP_COMMIT();
    asm volatile("cp.async.wait_group 0;" ::: "memory");
    __syncthreads();

    int lane = tid & 31, wrp = tid >> 5;
    int warpm = wrp & 3, warpn = wrp >> 2;     // warp tile 64m x 32n
    uint32_t b_off = (uint32_t)((warpn * 32 + ((lane >> 4) & 1) * 8 + (lane & 7)) * 128 +
                                ((lane >> 3) & 1) * 16);
    const __nv_bfloat16* hs_hi = g_hsplit;
    const __nv_bfloat16* hs_lo = g_hsplit + (size_t)B * PT;
    float* pbase = g_part + (size_t)ksp * B * PT;

    for (int t = 0; t < T; t++) {
        // ===== phase A: partial GEMM over this CTA's K slice =====
        float acc[4][4][4] = {};
        auto issueA = [&](int c) {
            uint32_t dst = sb + PA_BUF(c & 1);
            int k0 = kbase + c * 64;
            #pragma unroll
            for (int j = 0; j < 8; j++) {
                int u = tid + 256 * j;
                int row = u >> 3, kk = u & 7;
                size_t soff = (size_t)row * PT + k0 + kk * 8;
                uint32_t d1 = dst + swz((uint32_t)(row * 128 + kk * 16));
                cpasync16(d1, hs_hi + soff);
                cpasync16(d1 + 32768, hs_lo + soff);
            }
            CP_COMMIT();
        };
        issueA(0);
        #pragma unroll
        for (int c = 0; c < 4; c++) {
            asm volatile("cp.async.wait_group 0;" ::: "memory");
            __syncthreads();
            if (c + 1 < 4) issueA(c + 1);
            uint32_t ah = sb + PA_BUF(c & 1), al = ah + 32768;
            uint32_t wh = sb + PW_CH(c), wl = wh + 8192;
            #pragma unroll
            for (int kk = 0; kk < 4; kk++) {
                uint32_t Wh0[4], Wh1[4], Wl0[4], Wl1[4];
                uint32_t bo = b_off + kk * 32;
                ldmx4(Wh0, wh + swz(bo)); ldmx4(Wh1, wh + swz(bo + 2048));
                ldmx4(Wl0, wl + swz(bo)); ldmx4(Wl1, wl + swz(bo + 2048));
                #pragma unroll
                for (int mf = 0; mf < 4; mf++) {
                    uint32_t Ah[4], Al[4];
                    uint32_t ao = (uint32_t)((warpm * 64 + mf * 16 + (lane & 15)) * 128 +
                                             ((lane >> 4) & 1) * 16 + kk * 32);
                    ldmx4(Ah, ah + swz(ao));
                    ldmx4(Al, al + swz(ao));
                    mma16816(acc[mf][0], Ah, Wh0[0], Wh0[1]);
                    mma16816(acc[mf][1], Ah, Wh0[2], Wh0[3]);
                    mma16816(acc[mf][2], Ah, Wh1[0], Wh1[1]);
                    mma16816(acc[mf][3], Ah, Wh1[2], Wh1[3]);
                    mma16816(acc[mf][0], Al, Wh0[0], Wh0[1]);
                    mma16816(acc[mf][1], Al, Wh0[2], Wh0[3]);
                    mma16816(acc[mf][2], Al, Wh1[0], Wh1[1]);
                    mma16816(acc[mf][3], Al, Wh1[2], Wh1[3]);
                    mma16816(acc[mf][0], Ah, Wl0[0], Wl0[1]);
                    mma16816(acc[mf][1], Ah, Wl0[2], Wl0[3]);
                    mma16816(acc[mf][2], Ah, Wl1[0], Wl1[1]);
                    mma16816(acc[mf][3], Ah, Wl1[2], Wl1[3]);
                }
            }
        }
        // store partials
        #pragma unroll
        for (int mf = 0; mf < 4; mf++) {
            int m0 = warpm * 64 + mf * 16 + (lane >> 2);
            #pragma unroll
            for (int nf = 0; nf < 4; nf++) {
                int n = bn + warpn * 32 + nf * 8 + (lane & 3) * 2;
                *reinterpret_cast<float2*>(pbase + (size_t)m0 * PT + n) =
                    make_float2(acc[mf][nf][0], acc[mf][nf][1]);
                *reinterpret_cast<float2*>(pbase + (size_t)(m0 + 8) * PT + n) =
                    make_float2(acc[mf][nf][2], acc[mf][nf][3]);
            }
        }
        grid_bar(tid);

        // ===== phase B: reduce partials + epilogue =====
        for (int e = cta * 256 + tid; e < (B * PT) / 4; e += NCTAS * 256) {
            int m = e / (PT / 4);
            int n = (e - m * (PT / 4)) * 4;
            float4 s = __ldcg(reinterpret_cast<const float4*>(g_part + (size_t)m * PT + n));
            #pragma unroll
            for (int kq = 1; kq < KSPLIT; kq++) {
                float4 p = __ldcg(reinterpret_cast<const float4*>(
                    g_part + ((size_t)kq * B + m) * PT + n));
                s.x += p.x; s.y += p.y; s.z += p.z; s.w += p.w;
            }
            float2 xv = *reinterpret_cast<const float2*>(inputs + ((size_t)m * T + t) * 2);
            float4 bs = *reinterpret_cast<const float4*>(g_bias + n);
            float4 w01 = *reinterpret_cast<const float4*>(g_win + 2 * n);
            float4 w23 = *reinterpret_cast<const float4*>(g_win + 2 * n + 4);
            float a0 = s.x + bs.x + xv.x * w01.x + xv.y * w01.y;
            float a1 = s.y + bs.y + xv.x * w01.z + xv.y * w01.w;
            float a2 = s.z + bs.z + xv.x * w23.x + xv.y * w23.y;
            float a3 = s.w + bs.w + xv.x * w23.z + xv.y * w23.w;
            float alpha = (n < P1) ? 0.1f : 0.05f;
            float oma = 1.0f - alpha;
            const float* hp;
            float* op;
            if (n < P1) {
                hp = (t == 0) ? g_h0 + (size_t)m * PT + n
                              : oh1 + ((size_t)m * T + t - 1) * P1 + n;
                op = oh1 + ((size_t)m * T + t) * P1 + n;
            } else {
                hp = (t == 0) ? g_h0 + (size_t)m * PT + n
                              : oh2 + ((size_t)m * T + t - 1) * P2 + (n - P1);
                op = oh2 + ((size_t)m * T + t) * P2 + (n - P1);
            }
            float4 h4 = *reinterpret_cast<const float4*>(hp);
            float4 nh;
            nh.x = oma * h4.x + alpha * fast_tanh(a0);
            nh.y = oma * h4.y + alpha * fast_tanh(a1);
            nh.z = oma * h4.z + alpha * fast_tanh(a2);
            nh.w = oma * h4.w + alpha * fast_tanh(a3);
            *reinterpret_cast<float4*>(op) = nh;
            // write persistent hi/lo split for next step's A operand
            __nv_bfloat16 hx = __float2bfloat16(nh.x), hy = __float2bfloat16(nh.y);
            __nv_bfloat16 hz = __float2bfloat16(nh.z), hw = __float2bfloat16(nh.w);
            uint2 hv = make_uint2(
                (uint32_t)__bfloat16_as_ushort(hx) | ((uint32_t)__bfloat16_as_ushort(hy) << 16),
                (uint32_t)__bfloat16_as_ushort(hz) | ((uint32_t)__bfloat16_as_ushort(hw) << 16));
            __nv_bfloat16 lx = __float2bfloat16(nh.x - __bfloat162float(hx));
            __nv_bfloat16 ly = __float2bfloat16(nh.y - __bfloat162float(hy));
            __nv_bfloat16 lz = __float2bfloat16(nh.z - __bfloat162float(hz));
            __nv_bfloat16 lw = __float2bfloat16(nh.w - __bfloat162float(hw));
            uint2 lv = make_uint2(
                (uint32_t)__bfloat16_as_ushort(lx) | ((uint32_t)__bfloat16_as_ushort(ly) << 16),
                (uint32_t)__bfloat16_as_ushort(lz) | ((uint32_t)__bfloat16_as_ushort(lw) << 16));
            size_t hoff = (size_t)m * PT + n;
            *reinterpret_cast<uint2*>(reinterpret_cast<char*>(g_hsplit) + hoff * 2) = hv;
            *reinterpret_cast<uint2*>(reinterpret_cast<char*>(g_hsplit) +
                                      ((size_t)B * PT + hoff) * 2) = lv;
        }
        grid_bar(tid);
    }
}

// ---------------- GEMM mainloop for out_kernel (64x64 tile, 256 thr) ----------------
template <typename AFUN>
__device__ __forceinline__ void gemm_core(char* sm, uint32_t sb, int tid, AFUN afun,
                                          const __nv_bfloat16* __restrict__ whi,
                                          const __nv_bfloat16* __restrict__ wlo,
                                          int bn, float acc[4][4]) {
    int lane = tid & 31, wrp = tid >> 5;
    int warpm = wrp & 3;
    int warpn = wrp >> 2;
    uint32_t a_off = (uint32_t)((warpm * 16 + (lane & 15)) * 128 + ((lane >> 4) & 1) * 16);
    uint32_t b_off = (uint32_t)((warpn * 32 + ((lane >> 4) & 1) * 8 + (lane & 7)) * 128 +
                                ((lane >> 3) & 1) * 16);
    int arow = tid >> 2;
    int acol = (tid & 3) * 16;

    auto issueW = [&](int c) {
        int k0 = c * 64;
        uint32_t wh = sb + W_HI(c % 3);
        #pragma unroll
        for (int j = 0; j < 2; j++) {
            int u = tid + 256 * j;
            int row = u >> 3, kk = u & 7;
            size_t goff = (size_t)(bn + row) * PT + k0 + kk * 8;
            uint32_t d1 = wh + swz((uint32_t)(row * 128 + kk * 16));
            cpasync16(d1, whi + goff);
            cpasync16(d1 + 8192, wlo + goff);
        }
        CP_COMMIT();
    };
    auto loadA = [&](int c, float4 ar[4]) {
        const float* ab; size_t astr;
        afun(c, ab, astr);
        const float* p = ab + (size_t)arow * astr + acol;
        #pragma unroll
        for (int i = 0; i < 4; i++) ar[i] = *reinterpret_cast<const float4*>(p + i * 4);
    };
    auto storeA = [&](int c, const float4 ar[4]) {
        uint32_t base = (uint32_t)A_HI(c & 1);
        #pragma unroll
        for (int i = 0; i < 4; i++) {
            float4 v = ar[i];
            __nv_bfloat16 hx = __float2bfloat16(v.x), hy = __float2bfloat16(v.y);
            __nv_bfloat16 hz = __float2bfloat16(v.z), hw = __float2bfloat16(v.w);
            __nv_bfloat16 lx = __float2bfloat16(v.x - __bfloat162float(hx));
            __nv_bfloat16 ly = __float2bfloat16(v.y - __bfloat162float(hy));
            __nv_bfloat16 lz = __float2bfloat16(v.z - __bfloat162float(hz));
            __nv_bfloat16 lw = __float2bfloat16(v.w - __bfloat162float(hw));
            uint2 h2 = make_uint2(
                (uint32_t)__bfloat16_as_ushort(hx) | ((uint32_t)__bfloat16_as_ushort(hy) << 16),
                (uint32_t)__bfloat16_as_ushort(hz) | ((uint32_t)__bfloat16_as_ushort(hw) << 16));
            uint2 l2 = make_uint2(
                (uint32_t)__bfloat16_as_ushort(lx) | ((uint32_t)__bfloat16_as_ushort(ly) << 16),
                (uint32_t)__bfloat16_as_ushort(lz) | ((uint32_t)__bfloat16_as_ushort(lw) << 16));
            uint32_t off = swz((uint32_t)(arow * 128 + acol * 2 + i * 8));
            *reinterpret_cast<uint2*>(sm + base + off) = h2;
            *reinterpret_cast<uint2*>(sm + base + 8192 + off) = l2;
        }
    };

    issueW(0);
    issueW(1);
    { float4 ar[4]; loadA(0, ar); storeA(0, ar); }

    for (int c = 0; c < NCHUNK; c++) {
        float4 ar[4];
        bool hn = (c + 1 < NCHUNK);
        if (hn) loadA(c + 1, ar);
        if (c < NCHUNK - 1) asm volatile("cp.async.wait_group 1;" ::: "memory");
        else                asm volatile("cp.async.wait_group 0;" ::: "memory");
        __syncthreads();
        if (c + 2 < NCHUNK) issueW(c + 2);

        uint32_t ah = sb + A_HI(c & 1), al = ah + 8192;
        uint32_t wh = sb + W_HI(c % 3), wl = wh + 8192;
        #pragma unroll
        for (int ks = 0; ks < 4; ks++) {
            uint32_t Ah[4], Al[4], Wh0[4], Wh1[4], Wl0[4], Wl1[4];
            uint32_t ao = a_off + ks * 32, bo = b_off + ks * 32;
            ldmx4(Ah, ah + swz(ao));
            ldmx4(Al, al + swz(ao));
            ldmx4(Wh0, wh + swz(bo)); ldmx4(Wh1, wh + swz(bo + 2048));
            ldmx4(Wl0, wl + swz(bo)); ldmx4(Wl1, wl + swz(bo + 2048));
            mma16816(acc[0], Ah, Wh0[0], Wh0[1]);
            mma16816(acc[1], Ah, Wh0[2], Wh0[3]);
            mma16816(acc[2], Ah, Wh1[0], Wh1[1]);
            mma16816(acc[3], Ah, Wh1[2], Wh1[3]);
            mma16816(acc[0], Al, Wh0[0], Wh0[1]);
            mma16816(acc[1], Al, Wh0[2], Wh0[3]);
            mma16816(acc[2], Al, Wh1[0], Wh1[1]);
            mma16816(acc[3], Al, Wh1[2], Wh1[3]);
            mma16816(acc[0], Ah, Wl0[0], Wl0[1]);
            mma16816(acc[1], Ah, Wl0[2], Wl0[3]);
            mma16816(acc[2], Ah, Wl1[0], Wl1[1]);
            mma16816(acc[3], Ah, Wl1[2], Wl1[3]);
        }
        if (hn) storeA(c + 1, ar);
    }
}

// ---------------- output projection kernel ----------------
__global__ void __launch_bounds__(256)
out_kernel(const float* __restrict__ oh1, const float* __restrict__ oh2,
           float* __restrict__ out2) {
    extern __shared__ char smraw[];
    char* sm = (char*)(((uintptr_t)smraw + 1023) & ~(uintptr_t)1023);
    uint32_t sb = smem_u32(sm);
    int tid = threadIdx.x;
    int bn = blockIdx.x * 64;
    int bm = blockIdx.y * 64;

    float acc[4][4] = {};
    auto afun = [&](int c, const float*& ab, size_t& astr) {
        int k0 = c * 64;
        if (k0 < P1) { ab = oh1 + (size_t)bm * P1 + k0;        astr = P1; }
        else         { ab = oh2 + (size_t)bm * P2 + (k0 - P1); astr = P2; }
    };
    gemm_core(sm, sb, tid, afun, g_Wouthi, g_Woutlo, bn, acc);

    int lane = tid & 31, wrp = tid >> 5;
    int warpm = wrp & 3, warpn = wrp >> 2;
    #pragma unroll
    for (int half = 0; half < 2; half++) {
        size_t m = (size_t)bm + warpm * 16 + (lane >> 2) + half * 8;
        #pragma unroll
        for (int nj = 0; nj < 4; nj++) {
            int cc = warpn * 32 + nj * 8 + 2 * (lane & 3);
            float2 o2;
            o2.x = acc[nj][half * 2 + 0];
            o2.y = acc[nj][half * 2 + 1];
            *reinterpret_cast<float2*>(out2 + m * O + bn + cc) = o2;
        }
    }
}

// ---------------- host ----------------
extern "C" void kernel_launch(void* const* d_in, const int* in_sizes, int n_in,
                              void* d_out, int out_size) {
    const float* inputs  = (const float*)d_in[0];
    const float* place0  = (const float*)d_in[1];
    const float* W_in1   = (const float*)d_in[2];
    const float* b_in1   = (const float*)d_in[3];
    const float* W_in2   = (const float*)d_in[4];
    const float* b_in2   = (const float*)d_in[5];
    const float* W_rec1  = (const float*)d_in[6];
    const float* b_rec1  = (const float*)d_in[7];
    const float* W_rec2  = (const float*)d_in[8];
    const float* b_rec2  = (const float*)d_in[9];
    const float* W_12    = (const float*)d_in[10];
    const float* b_12    = (const float*)d_in[11];
    const float* W_21    = (const float*)d_in[12];
    const float* b_21    = (const float*)d_in[13];
    const float* W_out   = (const float*)d_in[14];
    const float* W_h1    = (const float*)d_in[15];
    const float* W_h2    = (const float*)d_in[16];

    float* oh1  = (float*)d_out;
    float* oh2  = oh1 + (size_t)B * T * P1;
    float* out2 = oh2 + (size_t)B * T * P2;

    cudaFuncSetAttribute(rnn_kernel, cudaFuncAttributeMaxDynamicSharedMemorySize, PSM_REQ);
    cudaFuncSetAttribute(out_kernel, cudaFuncAttributeMaxDynamicSharedMemorySize, SM_REQ);

    pack_kernel<<<256, 256>>>(W_rec1, b_rec1, W_rec2, b_rec2,
                              W_12, b_12, W_21, b_21,
                              W_in1, b_in1, W_in2, b_in2, W_out);

    {
        dim3 grid(PT / 64, B / 64);
        init_kernel<<<grid, 256>>>(place0, W_h1, W_h2);
    }

    rnn_kernel<<<NCTAS, 256, PSM_REQ>>>(inputs, oh1, oh2);

    {
        dim3 grid(O / 64, (B * T) / 64);  // 8 x 800
        out_kernel<<<grid, 256, SM_REQ>>>(oh1, oh2, out2);
    }
}

// round 6
// speedup vs baseline: 5.8687x; 1.0272x over previous
#include <cuda_runtime.h>
#include <cuda_bf16.h>
#include <cstdint>

#define B 256
#define T 200
#define P1 1024
#define P2 512
#define PT 1536
#define O 512
#define NCHUNK 24        // K chunks of 64

#define NCTAS 144
#define KSPLIT 6
#define KPC 256          // K per CTA in persistent kernel

// ---------------- device scratch ----------------
__device__ float g_bias[PT];
__device__ float g_win[2 * PT];
__device__ float g_h0[B * PT];
__device__ __nv_bfloat16 g_h0hi[B * PT];
__device__ __nv_bfloat16 g_h0lo[B * PT];
__device__ __nv_bfloat16 g_histhi[(size_t)B * T * PT];   // bf16 hi history
__device__ __nv_bfloat16 g_histlo[(size_t)B * T * PT];   // bf16 lo history
__device__ float g_part[KSPLIT * B * PT];                // split-K partials
__device__ __nv_bfloat16 g_Whi[PT * PT];
__device__ __nv_bfloat16 g_Wlo[PT * PT];
__device__ __nv_bfloat16 g_Wouthi[O * PT];
__device__ __nv_bfloat16 g_Woutlo[O * PT];
__device__ unsigned g_cnt;
__device__ unsigned g_gen;

// ---------------- smem layout: persistent rnn kernel ----------------
#define PW_CH(c)  ((c) * 16384)                 // W chunk c: hi 8KB, lo +8192 (4 chunks)
#define PA_BUF(b) (65536 + (b) * 65536)         // A buf: hi 32KB, lo +32768 (2 bufs)
#define PSM_REQ   (65536 + 2 * 65536 + 1024)

// ---------------- smem layout: out_kernel ----------------
#define OA(b)    ((b) * 32768)                  // A buf: hi 16KB, lo +16384 (3 bufs)
#define OW(b)    (98304 + (b) * 16384)          // W buf: hi 8KB, lo +8192 (3 bufs)
#define OSM_REQ  (98304 + 3 * 16384 + 1024)

// ---------------- helpers ----------------
__device__ __forceinline__ uint32_t smem_u32(const void* p) {
    uint32_t a;
    asm("{ .reg .u64 t; cvta.to.shared.u64 t, %1; cvt.u32.u64 %0, t; }" : "=r"(a) : "l"(p));
    return a;
}
__device__ __forceinline__ uint32_t swz(uint32_t o) { return o ^ ((o >> 3) & 0x70); }

__device__ __forceinline__ void ldmx4(uint32_t r[4], uint32_t addr) {
    asm volatile("ldmatrix.sync.aligned.m8n8.x4.shared.b16 {%0,%1,%2,%3}, [%4];"
        : "=r"(r[0]), "=r"(r[1]), "=r"(r[2]), "=r"(r[3]) : "r"(addr));
}
__device__ __forceinline__ void mma16816(float d[4], const uint32_t a[4], uint32_t b0, uint32_t b1) {
    asm volatile("mma.sync.aligned.m16n8k16.row.col.f32.bf16.bf16.f32 "
        "{%0,%1,%2,%3}, {%4,%5,%6,%7}, {%8,%9}, {%0,%1,%2,%3};"
        : "+f"(d[0]), "+f"(d[1]), "+f"(d[2]), "+f"(d[3])
        : "r"(a[0]), "r"(a[1]), "r"(a[2]), "r"(a[3]), "r"(b0), "r"(b1));
}
__device__ __forceinline__ void cpasync16(uint32_t dst, const void* src) {
    asm volatile("cp.async.cg.shared.global [%0], [%1], 16;" :: "r"(dst), "l"(src));
}
#define CP_COMMIT() asm volatile("cp.async.commit_group;" ::: "memory")

__device__ __forceinline__ float fast_tanh(float x) {
    return 1.0f - __fdividef(2.0f, __expf(2.0f * x) + 1.0f);
}

// grid-wide sense-reversing barrier (all NCTAS co-resident: 1 CTA/SM)
__device__ __forceinline__ void grid_bar(int tid) {
    __syncthreads();
    if (tid == 0) {
        __threadfence();
        unsigned gen = atomicAdd(&g_gen, 0u);
        if (atomicAdd(&g_cnt, 1u) == NCTAS - 1u) {
            atomicExch(&g_cnt, 0u);
            __threadfence();
            atomicAdd(&g_gen, 1u);
        } else {
            while (*((volatile unsigned*)&g_gen) == gen) {}
        }
        __threadfence();
    }
    __syncthreads();
}

// ---------------- pack: fuse biases, split weights to bf16 hi/lo ----------------
__global__ void pack_kernel(const float* __restrict__ W_rec1, const float* __restrict__ b_rec1,
                            const float* __restrict__ W_rec2, const float* __restrict__ b_rec2,
                            const float* __restrict__ W_12,   const float* __restrict__ b_12,
                            const float* __restrict__ W_21,   const float* __restrict__ b_21,
                            const float* __restrict__ W_in1,  const float* __restrict__ b_in1,
                            const float* __restrict__ W_in2,  const float* __restrict__ b_in2,
                            const float* __restrict__ W_out) {
    int idx = blockIdx.x * blockDim.x + threadIdx.x;
    int stride = gridDim.x * blockDim.x;
    for (int i = idx; i < PT * PT; i += stride) {
        int n = i / PT, k = i % PT;
        float v;
        if (n < P1) v = (k < P1) ? W_rec1[n * P1 + k] : W_21[n * P2 + (k - P1)];
        else {
            int n2 = n - P1;
            v = (k < P1) ? W_12[n2 * P1 + k] : W_rec2[n2 * P2 + (k - P1)];
        }
        __nv_bfloat16 h = __float2bfloat16(v);
        g_Whi[i] = h;
        g_Wlo[i] = __float2bfloat16(v - __bfloat162float(h));
    }
    for (int i = idx; i < O * PT; i += stride) {
        float v = W_out[i];
        __nv_bfloat16 h = __float2bfloat16(v);
        g_Wouthi[i] = h;
        g_Woutlo[i] = __float2bfloat16(v - __bfloat162float(h));
    }
    for (int n = idx; n < PT; n += stride) {
        if (n < P1) {
            g_bias[n] = b_rec1[n] + b_21[n] + b_in1[n];
            g_win[2 * n]     = W_in1[2 * n];
            g_win[2 * n + 1] = W_in1[2 * n + 1];
        } else {
            int n2 = n - P1;
            g_bias[n] = b_rec2[n2] + b_12[n2] + b_in2[n2];
            g_win[2 * n]     = W_in2[2 * n2];
            g_win[2 * n + 1] = W_in2[2 * n2 + 1];
        }
    }
}

// ---------------- init: h0 = place @ [W_h1;W_h2].T + write split ----------------
__global__ void init_kernel(const float* __restrict__ place,
                            const float* __restrict__ Wh1,
                            const float* __restrict__ Wh2) {
    __shared__ float As[16][65];
    __shared__ float Ws[16][65];
    int tid = threadIdx.x;
    int bn = blockIdx.x * 64;
    int bm = blockIdx.y * 64;
    float acc[4][4] = {};
    for (int k0 = 0; k0 < O; k0 += 16) {
        #pragma unroll
        for (int i = 0; i < 4; i++) {
            int lin = tid + 256 * i;
            int r = lin >> 4, c = lin & 15;
            As[c][r] = place[(bm + r) * O + k0 + c];
            int n = bn + r;
            Ws[c][r] = (n < P1) ? Wh1[n * O + k0 + c] : Wh2[(n - P1) * O + k0 + c];
        }
        __syncthreads();
        #pragma unroll
        for (int c = 0; c < 16; c++) {
            float af[4], wf[4];
            int ty = tid >> 4, tx = tid & 15;
            #pragma unroll
            for (int j = 0; j < 4; j++) { af[j] = As[c][ty * 4 + j]; wf[j] = Ws[c][tx * 4 + j]; }
            #pragma unroll
            for (int a = 0; a < 4; a++)
                #pragma unroll
                for (int b2 = 0; b2 < 4; b2++)
                    acc[a][b2] = fmaf(af[a], wf[b2], acc[a][b2]);
        }
        __syncthreads();
    }
    int ty = tid >> 4, tx = tid & 15;
    #pragma unroll
    for (int a = 0; a < 4; a++)
        #pragma unroll
        for (int b2 = 0; b2 < 4; b2++) {
            float v = acc[a][b2];
            size_t off = (size_t)(bm + ty * 4 + a) * PT + bn + tx * 4 + b2;
            g_h0[off] = v;
            __nv_bfloat16 h = __float2bfloat16(v);
            g_h0hi[off] = h;
            g_h0lo[off] = __float2bfloat16(v - __bfloat162float(h));
        }
}

// ---------------- persistent RNN kernel: 200 steps, W resident in SMEM ----------------
__global__ void __launch_bounds__(256)
rnn_kernel(const float* __restrict__ inputs,
           float* __restrict__ oh1, float* __restrict__ oh2) {
    extern __shared__ char smraw[];
    char* sm = (char*)(((uintptr_t)smraw + 1023) & ~(uintptr_t)1023);
    uint32_t sb = smem_u32(sm);
    int tid = threadIdx.x;
    int cta = blockIdx.x;
    int nt = cta / KSPLIT;          // 0..23  N tile
    int ksp = cta % KSPLIT;         // 0..5   K split
    int bn = nt * 64;
    int kbase = ksp * KPC;

    // ---- load resident W slice (64 n x 256 k, hi+lo) once ----
    for (int c = 0; c < 4; c++) {
        int k0 = kbase + c * 64;
        #pragma unroll
        for (int j = 0; j < 2; j++) {
            int u = tid + 256 * j;
            int row = u >> 3, kk = u & 7;
            size_t goff = (size_t)(bn + row) * PT + k0 + kk * 8;
            uint32_t d1 = sb + PW_CH(c) + swz((uint32_t)(row * 128 + kk * 16));
            cpasync16(d1, g_Whi + goff);
            cpasync16(d1 + 8192, g_Wlo + goff);
        }
    }
    CP_COMMIT();
    asm volatile("cp.async.wait_group 0;" ::: "memory");
    __syncthreads();

    int lane = tid & 31, wrp = tid >> 5;
    int warpm = wrp & 3, warpn = wrp >> 2;     // warp tile 64m x 32n
    uint32_t b_off = (uint32_t)((warpn * 32 + ((lane >> 4) & 1) * 8 + (lane & 7)) * 128 +
                                ((lane >> 3) & 1) * 16);
    float* pbase = g_part + (size_t)ksp * B * PT;

    for (int t = 0; t < T; t++) {
        // ===== phase A: partial GEMM over this CTA's K slice =====
        const __nv_bfloat16* ahi;
        const __nv_bfloat16* alo;
        size_t astr;
        if (t == 0) { ahi = g_h0hi; alo = g_h0lo; astr = PT; }
        else {
            ahi = g_histhi + (size_t)(t - 1) * PT;
            alo = g_histlo + (size_t)(t - 1) * PT;
            astr = (size_t)T * PT;
        }
        float acc[4][4][4] = {};
        auto issueA = [&](int c) {
            uint32_t dst = sb + PA_BUF(c & 1);
            int k0 = kbase + c * 64;
            #pragma unroll
            for (int j = 0; j < 8; j++) {
                int u = tid + 256 * j;
                int row = u >> 3, kk = u & 7;
                size_t soff = (size_t)row * astr + k0 + kk * 8;
                uint32_t d1 = dst + swz((uint32_t)(row * 128 + kk * 16));
                cpasync16(d1, ahi + soff);
                cpasync16(d1 + 32768, alo + soff);
            }
            CP_COMMIT();
        };
        issueA(0);
        #pragma unroll
        for (int c = 0; c < 4; c++) {
            asm volatile("cp.async.wait_group 0;" ::: "memory");
            __syncthreads();
            if (c + 1 < 4) issueA(c + 1);
            uint32_t ah = sb + PA_BUF(c & 1), al = ah + 32768;
            uint32_t wh = sb + PW_CH(c), wl = wh + 8192;
            #pragma unroll
            for (int kk = 0; kk < 4; kk++) {
                uint32_t Wh0[4], Wh1[4], Wl0[4], Wl1[4];
                uint32_t bo = b_off + kk * 32;
                ldmx4(Wh0, wh + swz(bo)); ldmx4(Wh1, wh + swz(bo + 2048));
                ldmx4(Wl0, wl + swz(bo)); ldmx4(Wl1, wl + swz(bo + 2048));
                #pragma unroll
                for (int mf = 0; mf < 4; mf++) {
                    uint32_t Ah[4], Al[4];
                    uint32_t ao = (uint32_t)((warpm * 64 + mf * 16 + (lane & 15)) * 128 +
                                             ((lane >> 4) & 1) * 16 + kk * 32);
                    ldmx4(Ah, ah + swz(ao));
                    ldmx4(Al, al + swz(ao));
                    mma16816(acc[mf][0], Ah, Wh0[0], Wh0[1]);
                    mma16816(acc[mf][1], Ah, Wh0[2], Wh0[3]);
                    mma16816(acc[mf][2], Ah, Wh1[0], Wh1[1]);
                    mma16816(acc[mf][3], Ah, Wh1[2], Wh1[3]);
                    mma16816(acc[mf][0], Al, Wh0[0], Wh0[1]);
                    mma16816(acc[mf][1], Al, Wh0[2], Wh0[3]);
                    mma16816(acc[mf][2], Al, Wh1[0], Wh1[1]);
                    mma16816(acc[mf][3], Al, Wh1[2], Wh1[3]);
                    mma16816(acc[mf][0], Ah, Wl0[0], Wl0[1]);
                    mma16816(acc[mf][1], Ah, Wl0[2], Wl0[3]);
                    mma16816(acc[mf][2], Ah, Wl1[0], Wl1[1]);
                    mma16816(acc[mf][3], Ah, Wl1[2], Wl1[3]);
                }
            }
        }
        // store partials
        #pragma unroll
        for (int mf = 0; mf < 4; mf++) {
            int m0 = warpm * 64 + mf * 16 + (lane >> 2);
            #pragma unroll
            for (int nf = 0; nf < 4; nf++) {
                int n = bn + warpn * 32 + nf * 8 + (lane & 3) * 2;
                *reinterpret_cast<float2*>(pbase + (size_t)m0 * PT + n) =
                    make_float2(acc[mf][nf][0], acc[mf][nf][1]);
                *reinterpret_cast<float2*>(pbase + (size_t)(m0 + 8) * PT + n) =
                    make_float2(acc[mf][nf][2], acc[mf][nf][3]);
            }
        }
        grid_bar(tid);

        // ===== phase B: reduce partials + epilogue =====
        for (int e = cta * 256 + tid; e < (B * PT) / 4; e += NCTAS * 256) {
            int m = e / (PT / 4);
            int n = (e - m * (PT / 4)) * 4;
            float4 s = __ldcg(reinterpret_cast<const float4*>(g_part + (size_t)m * PT + n));
            #pragma unroll
            for (int kq = 1; kq < KSPLIT; kq++) {
                float4 p = __ldcg(reinterpret_cast<const float4*>(
                    g_part + ((size_t)kq * B + m) * PT + n));
                s.x += p.x; s.y += p.y; s.z += p.z; s.w += p.w;
            }
            float2 xv = *reinterpret_cast<const float2*>(inputs + ((size_t)m * T + t) * 2);
            float4 bs = *reinterpret_cast<const float4*>(g_bias + n);
            float4 w01 = *reinterpret_cast<const float4*>(g_win + 2 * n);
            float4 w23 = *reinterpret_cast<const float4*>(g_win + 2 * n + 4);
            float a0 = s.x + bs.x + xv.x * w01.x + xv.y * w01.y;
            float a1 = s.y + bs.y + xv.x * w01.z + xv.y * w01.w;
            float a2 = s.z + bs.z + xv.x * w23.x + xv.y * w23.y;
            float a3 = s.w + bs.w + xv.x * w23.z + xv.y * w23.w;
            float alpha = (n < P1) ? 0.1f : 0.05f;
            float oma = 1.0f - alpha;
            const float* hp;
            float* op;
            if (n < P1) {
                hp = (t == 0) ? g_h0 + (size_t)m * PT + n
                              : oh1 + ((size_t)m * T + t - 1) * P1 + n;
                op = oh1 + ((size_t)m * T + t) * P1 + n;
            } else {
                hp = (t == 0) ? g_h0 + (size_t)m * PT + n
                              : oh2 + ((size_t)m * T + t - 1) * P2 + (n - P1);
                op = oh2 + ((size_t)m * T + t) * P2 + (n - P1);
            }
            float4 h4 = *reinterpret_cast<const float4*>(hp);
            float4 nh;
            nh.x = oma * h4.x + alpha * fast_tanh(a0);
            nh.y = oma * h4.y + alpha * fast_tanh(a1);
            nh.z = oma * h4.z + alpha * fast_tanh(a2);
            nh.w = oma * h4.w + alpha * fast_tanh(a3);
            *reinterpret_cast<float4*>(op) = nh;
            // write persistent hi/lo split history (also consumed by out_kernel)
            __nv_bfloat16 hx = __float2bfloat16(nh.x), hy = __float2bfloat16(nh.y);
            __nv_bfloat16 hz = __float2bfloat16(nh.z), hw = __float2bfloat16(nh.w);
            uint2 hv = make_uint2(
                (uint32_t)__bfloat16_as_ushort(hx) | ((uint32_t)__bfloat16_as_ushort(hy) << 16),
                (uint32_t)__bfloat16_as_ushort(hz) | ((uint32_t)__bfloat16_as_ushort(hw) << 16));
            __nv_bfloat16 lx = __float2bfloat16(nh.x - __bfloat162float(hx));
            __nv_bfloat16 ly = __float2bfloat16(nh.y - __bfloat162float(hy));
            __nv_bfloat16 lz = __float2bfloat16(nh.z - __bfloat162float(hz));
            __nv_bfloat16 lw = __float2bfloat16(nh.w - __bfloat162float(hw));
            uint2 lv = make_uint2(
                (uint32_t)__bfloat16_as_ushort(lx) | ((uint32_t)__bfloat16_as_ushort(ly) << 16),
                (uint32_t)__bfloat16_as_ushort(lz) | ((uint32_t)__bfloat16_as_ushort(lw) << 16));
            size_t hoff = ((size_t)m * T + t) * PT + n;
            *reinterpret_cast<uint2*>(reinterpret_cast<char*>(g_histhi) + hoff * 2) = hv;
            *reinterpret_cast<uint2*>(reinterpret_cast<char*>(g_histlo) + hoff * 2) = lv;
        }
        grid_bar(tid);
    }
}

// ---------------- output projection: reads pre-split history ----------------
// CTA tile 128m x 64n, warp tile 32m x 32n (8 warps, 4x2), 3-stage cp.async pipeline
__global__ void __launch_bounds__(256)
out_kernel(float* __restrict__ out2) {
    extern __shared__ char smraw[];
    char* sm = (char*)(((uintptr_t)smraw + 1023) & ~(uintptr_t)1023);
    uint32_t sb = smem_u32(sm);
    int tid = threadIdx.x;
    int bn = blockIdx.x * 64;      // over O
    int bm = blockIdx.y * 128;     // over B*T

    int lane = tid & 31, wrp = tid >> 5;
    int warpm = wrp & 3, warpn = wrp >> 2;
    uint32_t b_off = (uint32_t)((warpn * 32 + ((lane >> 4) & 1) * 8 + (lane & 7)) * 128 +
                                ((lane >> 3) & 1) * 16);

    auto issueAW = [&](int c) {
        int k0 = c * 64;
        int buf = c % 3;
        // A: 128 rows x 64 cols, hi+lo
        uint32_t da = sb + OA(buf);
        #pragma unroll
        for (int j = 0; j < 4; j++) {
            int u = tid + 256 * j;
            int row = u >> 3, kk = u & 7;
            size_t soff = (size_t)(bm + row) * PT + k0 + kk * 8;
            uint32_t d1 = da + swz((uint32_t)(row * 128 + kk * 16));
            cpasync16(d1, g_histhi + soff);
            cpasync16(d1 + 16384, g_histlo + soff);
        }
        // W: 64 rows x 64 cols, hi+lo
        uint32_t dw = sb + OW(buf);
        #pragma unroll
        for (int j = 0; j < 2; j++) {
            int u = tid + 256 * j;
            int row = u >> 3, kk = u & 7;
            size_t goff = (size_t)(bn + row) * PT + k0 + kk * 8;
            uint32_t d1 = dw + swz((uint32_t)(row * 128 + kk * 16));
            cpasync16(d1, g_Wouthi + goff);
            cpasync16(d1 + 8192, g_Woutlo + goff);
        }
        CP_COMMIT();
    };

    float acc[2][4][4] = {};
    issueAW(0);
    issueAW(1);
    for (int c = 0; c < NCHUNK; c++) {
        if (c < NCHUNK - 1) asm volatile("cp.async.wait_group 1;" ::: "memory");
        else                asm volatile("cp.async.wait_group 0;" ::: "memory");
        __syncthreads();
        if (c + 2 < NCHUNK) issueAW(c + 2);

        uint32_t ah = sb + OA(c % 3), al = ah + 16384;
        uint32_t wh = sb + OW(c % 3), wl = wh + 8192;
        #pragma unroll
        for (int kk = 0; kk < 4; kk++) {
            uint32_t Wh0[4], Wh1[4], Wl0[4], Wl1[4];
            uint32_t bo = b_off + kk * 32;
            ldmx4(Wh0, wh + swz(bo)); ldmx4(Wh1, wh + swz(bo + 2048));
            ldmx4(Wl0, wl + swz(bo)); ldmx4(Wl1, wl + swz(bo + 2048));
            #pragma unroll
            for (int mf = 0; mf < 2; mf++) {
                uint32_t Ah[4], Al[4];
                uint32_t ao = (uint32_t)((warpm * 32 + mf * 16 + (lane & 15)) * 128 +
                                         ((lane >> 4) & 1) * 16 + kk * 32);
                ldmx4(Ah, ah + swz(ao));
                ldmx4(Al, al + swz(ao));
                mma16816(acc[mf][0], Ah, Wh0[0], Wh0[1]);
                mma16816(acc[mf][1], Ah, Wh0[2], Wh0[3]);
                mma16816(acc[mf][2], Ah, Wh1[0], Wh1[1]);
                mma16816(acc[mf][3], Ah, Wh1[2], Wh1[3]);
                mma16816(acc[mf][0], Al, Wh0[0], Wh0[1]);
                mma16816(acc[mf][1], Al, Wh0[2], Wh0[3]);
                mma16816(acc[mf][2], Al, Wh1[0], Wh1[1]);
                mma16816(acc[mf][3], Al, Wh1[2], Wh1[3]);
                mma16816(acc[mf][0], Ah, Wl0[0], Wl0[1]);
                mma16816(acc[mf][1], Ah, Wl0[2], Wl0[3]);
                mma16816(acc[mf][2], Ah, Wl1[0], Wl1[1]);
                mma16816(acc[mf][3], Ah, Wl1[2], Wl1[3]);
            }
        }
    }

    #pragma unroll
    for (int mf = 0; mf < 2; mf++) {
        #pragma unroll
        for (int half = 0; half < 2; half++) {
            size_t m = (size_t)bm + warpm * 32 + mf * 16 + (lane >> 2) + half * 8;
            #pragma unroll
            for (int nj = 0; nj < 4; nj++) {
                int cc = warpn * 32 + nj * 8 + 2 * (lane & 3);
                float2 o2;
                o2.x = acc[mf][nj][half * 2 + 0];
                o2.y = acc[mf][nj][half * 2 + 1];
                *reinterpret_cast<float2*>(out2 + m * O + bn + cc) = o2;
            }
        }
    }
}

// ---------------- host ----------------
extern "C" void kernel_launch(void* const* d_in, const int* in_sizes, int n_in,
                              void* d_out, int out_size) {
    const float* inputs  = (const float*)d_in[0];
    const float* place0  = (const float*)d_in[1];
    const float* W_in1   = (const float*)d_in[2];
    const float* b_in1   = (const float*)d_in[3];
    const float* W_in2   = (const float*)d_in[4];
    const float* b_in2   = (const float*)d_in[5];
    const float* W_rec1  = (const float*)d_in[6];
    const float* b_rec1  = (const float*)d_in[7];
    const float* W_rec2  = (const float*)d_in[8];
    const float* b_rec2  = (const float*)d_in[9];
    const float* W_12    = (const float*)d_in[10];
    const float* b_12    = (const float*)d_in[11];
    const float* W_21    = (const float*)d_in[12];
    const float* b_21    = (const float*)d_in[13];
    const float* W_out   = (const float*)d_in[14];
    const float* W_h1    = (const float*)d_in[15];
    const float* W_h2    = (const float*)d_in[16];

    float* oh1  = (float*)d_out;
    float* oh2  = oh1 + (size_t)B * T * P1;
    float* out2 = oh2 + (size_t)B * T * P2;

    cudaFuncSetAttribute(rnn_kernel, cudaFuncAttributeMaxDynamicSharedMemorySize, PSM_REQ);
    cudaFuncSetAttribute(out_kernel, cudaFuncAttributeMaxDynamicSharedMemorySize, OSM_REQ);

    pack_kernel<<<256, 256>>>(W_rec1, b_rec1, W_rec2, b_rec2,
                              W_12, b_12, W_21, b_21,
                              W_in1, b_in1, W_in2, b_in2, W_out);

    {
        dim3 grid(PT / 64, B / 64);
        init_kernel<<<grid, 256>>>(place0, W_h1, W_h2);
    }

    rnn_kernel<<<NCTAS, 256, PSM_REQ>>>(inputs, oh1, oh2);

    {
        dim3 grid(O / 64, (B * T) / 128);  // 8 x 400
        out_kernel<<<grid, 256, OSM_REQ>>>(out2);
    }
}

// round 7
// speedup vs baseline: 6.7444x; 1.1492x over previous
#include <cuda_runtime.h>
#include <cuda_bf16.h>
#include <cstdint>

#define B 256
#define T 200
#define P1 1024
#define P2 512
#define PT 1536
#define O 512
#define NCHUNK 24        // K chunks of 64 (out_kernel)

#define NCTAS 144
#define KSPLIT 3
#define KPC 512          // K per CTA in persistent kernel
#define NGRP 48          // 24 n-tiles x 2 m-tiles

// ---------------- device scratch ----------------
__device__ float g_bias[PT];
__device__ float g_win[2 * PT];
__device__ float g_h0[B * PT];
__device__ __nv_bfloat16 g_h0hi[B * PT];
__device__ __nv_bfloat16 g_h0lo[B * PT];
__device__ __nv_bfloat16 g_histhi[(size_t)B * T * PT];   // bf16 hi history
__device__ __nv_bfloat16 g_histlo[(size_t)B * T * PT];   // bf16 lo history
__device__ float g_part[KSPLIT * B * PT];                // split-K partials
__device__ __nv_bfloat16 g_Whi[PT * PT];
__device__ __nv_bfloat16 g_Wlo[PT * PT];
__device__ __nv_bfloat16 g_Wouthi[O * PT];
__device__ __nv_bfloat16 g_Woutlo[O * PT];
__device__ unsigned g_cnt;
__device__ unsigned g_gen;
__device__ unsigned g_tc[NGRP];          // per-tile-group cumulative counters

// ---------------- smem layout: persistent rnn kernel ----------------
#define PW_CH(c)  ((c) * 16384)                  // W chunk c: hi 8KB, lo +8192 (8 chunks)
#define PA_BUF(b) (131072 + (b) * 32768)         // A buf: hi 16KB, lo +16384 (2 bufs)
#define PSM_REQ   (131072 + 2 * 32768 + 1024)

// ---------------- smem layout: out_kernel ----------------
#define OA(b)    ((b) * 32768)                   // A buf: hi 16KB, lo +16384 (3 bufs)
#define OW(b)    (98304 + (b) * 16384)           // W buf: hi 8KB, lo +8192 (3 bufs)
#define OSM_REQ  (98304 + 3 * 16384 + 1024)

// ---------------- helpers ----------------
__device__ __forceinline__ uint32_t smem_u32(const void* p) {
    uint32_t a;
    asm("{ .reg .u64 t; cvta.to.shared.u64 t, %1; cvt.u32.u64 %0, t; }" : "=r"(a) : "l"(p));
    return a;
}
__device__ __forceinline__ uint32_t swz(uint32_t o) { return o ^ ((o >> 3) & 0x70); }

__device__ __forceinline__ void ldmx4(uint32_t r[4], uint32_t addr) {
    asm volatile("ldmatrix.sync.aligned.m8n8.x4.shared.b16 {%0,%1,%2,%3}, [%4];"
        : "=r"(r[0]), "=r"(r[1]), "=r"(r[2]), "=r"(r[3]) : "r"(addr));
}
__device__ __forceinline__ void mma16816(float d[4], const uint32_t a[4], uint32_t b0, uint32_t b1) {
    asm volatile("mma.sync.aligned.m16n8k16.row.col.f32.bf16.bf16.f32 "
        "{%0,%1,%2,%3}, {%4,%5,%6,%7}, {%8,%9}, {%0,%1,%2,%3};"
        : "+f"(d[0]), "+f"(d[1]), "+f"(d[2]), "+f"(d[3])
        : "r"(a[0]), "r"(a[1]), "r"(a[2]), "r"(a[3]), "r"(b0), "r"(b1));
}
__device__ __forceinline__ void cpasync16(uint32_t dst, const void* src) {
    asm volatile("cp.async.cg.shared.global [%0], [%1], 16;" :: "r"(dst), "l"(src));
}
#define CP_COMMIT() asm volatile("cp.async.commit_group;" ::: "memory")

__device__ __forceinline__ float fast_tanh(float x) {
    return 1.0f - __fdividef(2.0f, __expf(2.0f * x) + 1.0f);
}

// grid-wide sense-reversing barrier (all NCTAS co-resident: 1 CTA/SM)
__device__ __forceinline__ void grid_bar(int tid) {
    __syncthreads();
    if (tid == 0) {
        __threadfence();
        unsigned gen = atomicAdd(&g_gen, 0u);
        if (atomicAdd(&g_cnt, 1u) == NCTAS - 1u) {
            atomicExch(&g_cnt, 0u);
            __threadfence();
            atomicAdd(&g_gen, 1u);
        } else {
            while (*((volatile unsigned*)&g_gen) == gen) {}
        }
        __threadfence();
    }
    __syncthreads();
}

// ---------------- pack: fuse biases, split weights, reset sync state ----------------
__global__ void pack_kernel(const float* __restrict__ W_rec1, const float* __restrict__ b_rec1,
                            const float* __restrict__ W_rec2, const float* __restrict__ b_rec2,
                            const float* __restrict__ W_12,   const float* __restrict__ b_12,
                            const float* __restrict__ W_21,   const float* __restrict__ b_21,
                            const float* __restrict__ W_in1,  const float* __restrict__ b_in1,
                            const float* __restrict__ W_in2,  const float* __restrict__ b_in2,
                            const float* __restrict__ W_out) {
    int idx = blockIdx.x * blockDim.x + threadIdx.x;
    int stride = gridDim.x * blockDim.x;
    if (idx < NGRP) g_tc[idx] = 0;
    if (idx == 0) { g_cnt = 0; }
    for (int i = idx; i < PT * PT; i += stride) {
        int n = i / PT, k = i % PT;
        float v;
        if (n < P1) v = (k < P1) ? W_rec1[n * P1 + k] : W_21[n * P2 + (k - P1)];
        else {
            int n2 = n - P1;
            v = (k < P1) ? W_12[n2 * P1 + k] : W_rec2[n2 * P2 + (k - P1)];
        }
        __nv_bfloat16 h = __float2bfloat16(v);
        g_Whi[i] = h;
        g_Wlo[i] = __float2bfloat16(v - __bfloat162float(h));
    }
    for (int i = idx; i < O * PT; i += stride) {
        float v = W_out[i];
        __nv_bfloat16 h = __float2bfloat16(v);
        g_Wouthi[i] = h;
        g_Woutlo[i] = __float2bfloat16(v - __bfloat162float(h));
    }
    for (int n = idx; n < PT; n += stride) {
        if (n < P1) {
            g_bias[n] = b_rec1[n] + b_21[n] + b_in1[n];
            g_win[2 * n]     = W_in1[2 * n];
            g_win[2 * n + 1] = W_in1[2 * n + 1];
        } else {
            int n2 = n - P1;
            g_bias[n] = b_rec2[n2] + b_12[n2] + b_in2[n2];
            g_win[2 * n]     = W_in2[2 * n2];
            g_win[2 * n + 1] = W_in2[2 * n2 + 1];
        }
    }
}

// ---------------- init: h0 = place @ [W_h1;W_h2].T + write split ----------------
__global__ void init_kernel(const float* __restrict__ place,
                            const float* __restrict__ Wh1,
                            const float* __restrict__ Wh2) {
    __shared__ float As[16][65];
    __shared__ float Ws[16][65];
    int tid = threadIdx.x;
    int bn = blockIdx.x * 64;
    int bm = blockIdx.y * 64;
    float acc[4][4] = {};
    for (int k0 = 0; k0 < O; k0 += 16) {
        #pragma unroll
        for (int i = 0; i < 4; i++) {
            int lin = tid + 256 * i;
            int r = lin >> 4, c = lin & 15;
            As[c][r] = place[(bm + r) * O + k0 + c];
            int n = bn + r;
            Ws[c][r] = (n < P1) ? Wh1[n * O + k0 + c] : Wh2[(n - P1) * O + k0 + c];
        }
        __syncthreads();
        #pragma unroll
        for (int c = 0; c < 16; c++) {
            float af[4], wf[4];
            int ty = tid >> 4, tx = tid & 15;
            #pragma unroll
            for (int j = 0; j < 4; j++) { af[j] = As[c][ty * 4 + j]; wf[j] = Ws[c][tx * 4 + j]; }
            #pragma unroll
            for (int a = 0; a < 4; a++)
                #pragma unroll
                for (int b2 = 0; b2 < 4; b2++)
                    acc[a][b2] = fmaf(af[a], wf[b2], acc[a][b2]);
        }
        __syncthreads();
    }
    int ty = tid >> 4, tx = tid & 15;
    #pragma unroll
    for (int a = 0; a < 4; a++)
        #pragma unroll
        for (int b2 = 0; b2 < 4; b2++) {
            float v = acc[a][b2];
            size_t off = (size_t)(bm + ty * 4 + a) * PT + bn + tx * 4 + b2;
            g_h0[off] = v;
            __nv_bfloat16 h = __float2bfloat16(v);
            g_h0hi[off] = h;
            g_h0lo[off] = __float2bfloat16(v - __bfloat162float(h));
        }
}

// ---------------- persistent RNN kernel ----------------
// 144 CTAs = 24 n-tiles(64) x 2 m-tiles(128) x 3 k-splits(512)
// W slice resident in SMEM; per-tile group sync for reduction; 1 global barrier/step
__global__ void __launch_bounds__(256)
rnn_kernel(const float* __restrict__ inputs,
           float* __restrict__ oh1, float* __restrict__ oh2) {
    extern __shared__ char smraw[];
    char* sm = (char*)(((uintptr_t)smraw + 1023) & ~(uintptr_t)1023);
    uint32_t sb = smem_u32(sm);
    int tid = threadIdx.x;
    int cta = blockIdx.x;
    int nt = cta / 6;
    int rem = cta % 6;
    int mt = rem / 3;
    int ksp = rem % 3;
    int bn = nt * 64;
    int bm = mt * 128;
    int kbase = ksp * KPC;
    int grp = nt * 2 + mt;

    // ---- load resident W slice (64 n x 512 k, hi+lo = 128KB) once ----
    for (int c = 0; c < 8; c++) {
        int k0 = kbase + c * 64;
        #pragma unroll
        for (int j = 0; j < 2; j++) {
            int u = tid + 256 * j;
            int row = u >> 3, kk = u & 7;
            size_t goff = (size_t)(bn + row) * PT + k0 + kk * 8;
            uint32_t d1 = sb + PW_CH(c) + swz((uint32_t)(row * 128 + kk * 16));
            cpasync16(d1, g_Whi + goff);
            cpasync16(d1 + 8192, g_Wlo + goff);
        }
    }
    CP_COMMIT();
    asm volatile("cp.async.wait_group 0;" ::: "memory");
    __syncthreads();

    int lane = tid & 31, wrp = tid >> 5;
    int warpm = wrp & 3, warpn = wrp >> 2;     // warp tile 32m x 32n over 128x64
    uint32_t b_off = (uint32_t)((warpn * 32 + ((lane >> 4) & 1) * 8 + (lane & 7)) * 128 +
                                ((lane >> 3) & 1) * 16);
    float* pbase = g_part + (size_t)ksp * B * PT;

    for (int t = 0; t < T; t++) {
        // ===== phase A: partial GEMM (128m x 64n x 512k) =====
        const __nv_bfloat16* ahi;
        const __nv_bfloat16* alo;
        size_t astr;
        if (t == 0) { ahi = g_h0hi; alo = g_h0lo; astr = PT; }
        else {
            ahi = g_histhi + (size_t)(t - 1) * PT;
            alo = g_histlo + (size_t)(t - 1) * PT;
            astr = (size_t)T * PT;
        }
        float acc[2][4][4] = {};
        auto issueA = [&](int c) {
            uint32_t dst = sb + PA_BUF(c & 1);
            int k0 = kbase + c * 64;
            #pragma unroll
            for (int j = 0; j < 4; j++) {
                int u = tid + 256 * j;
                int row = u >> 3, kk = u & 7;
                size_t soff = (size_t)(bm + row) * astr + k0 + kk * 8;
                uint32_t d1 = dst + swz((uint32_t)(row * 128 + kk * 16));
                cpasync16(d1, ahi + soff);
                cpasync16(d1 + 16384, alo + soff);
            }
            CP_COMMIT();
        };
        issueA(0);
        #pragma unroll
        for (int c = 0; c < 8; c++) {
            asm volatile("cp.async.wait_group 0;" ::: "memory");
            __syncthreads();
            if (c + 1 < 8) issueA(c + 1);
            uint32_t ah = sb + PA_BUF(c & 1), al = ah + 16384;
            uint32_t wh = sb + PW_CH(c), wl = wh + 8192;
            #pragma unroll
            for (int kk = 0; kk < 4; kk++) {
                uint32_t Wh0[4], Wh1[4], Wl0[4], Wl1[4];
                uint32_t bo = b_off + kk * 32;
                ldmx4(Wh0, wh + swz(bo)); ldmx4(Wh1, wh + swz(bo + 2048));
                ldmx4(Wl0, wl + swz(bo)); ldmx4(Wl1, wl + swz(bo + 2048));
                #pragma unroll
                for (int mf = 0; mf < 2; mf++) {
                    uint32_t Ah[4], Al[4];
                    uint32_t ao = (uint32_t)((warpm * 32 + mf * 16 + (lane & 15)) * 128 +
                                             ((lane >> 4) & 1) * 16 + kk * 32);
                    ldmx4(Ah, ah + swz(ao));
                    ldmx4(Al, al + swz(ao));
                    mma16816(acc[mf][0], Ah, Wh0[0], Wh0[1]);
                    mma16816(acc[mf][1], Ah, Wh0[2], Wh0[3]);
                    mma16816(acc[mf][2], Ah, Wh1[0], Wh1[1]);
                    mma16816(acc[mf][3], Ah, Wh1[2], Wh1[3]);
                    mma16816(acc[mf][0], Al, Wh0[0], Wh0[1]);
                    mma16816(acc[mf][1], Al, Wh0[2], Wh0[3]);
                    mma16816(acc[mf][2], Al, Wh1[0], Wh1[1]);
                    mma16816(acc[mf][3], Al, Wh1[2], Wh1[3]);
                    mma16816(acc[mf][0], Ah, Wl0[0], Wl0[1]);
                    mma16816(acc[mf][1], Ah, Wl0[2], Wl0[3]);
                    mma16816(acc[mf][2], Ah, Wl1[0], Wl1[1]);
                    mma16816(acc[mf][3], Ah, Wl1[2], Wl1[3]);
                }
            }
        }
        // store partials for this k-split
        #pragma unroll
        for (int mf = 0; mf < 2; mf++) {
            int m0 = bm + warpm * 32 + mf * 16 + (lane >> 2);
            #pragma unroll
            for (int nf = 0; nf < 4; nf++) {
                int n = bn + warpn * 32 + nf * 8 + (lane & 3) * 2;
                *reinterpret_cast<float2*>(pbase + (size_t)m0 * PT + n) =
                    make_float2(acc[mf][nf][0], acc[mf][nf][1]);
                *reinterpret_cast<float2*>(pbase + (size_t)(m0 + 8) * PT + n) =
                    make_float2(acc[mf][nf][2], acc[mf][nf][3]);
            }
        }

        // ===== group sync: wait for the 3 k-split CTAs of this tile =====
        __threadfence();
        __syncthreads();
        if (tid == 0) {
            atomicAdd(&g_tc[grp], 1u);
            unsigned target = 3u * (unsigned)(t + 1);
            while (atomicAdd(&g_tc[grp], 0u) < target) {}
        }
        __syncthreads();
        __threadfence();

        // ===== phase B: reduce own tile (128m x 64n) + epilogue =====
        for (int e = ksp * 256 + tid; e < 2048; e += 768) {
            int m = bm + (e >> 4);
            int n = bn + ((e & 15) << 2);
            float4 s = __ldcg(reinterpret_cast<const float4*>(g_part + (size_t)m * PT + n));
            #pragma unroll
            for (int kq = 1; kq < KSPLIT; kq++) {
                float4 p = __ldcg(reinterpret_cast<const float4*>(
                    g_part + ((size_t)kq * B + m) * PT + n));
                s.x += p.x; s.y += p.y; s.z += p.z; s.w += p.w;
            }
            float2 xv = *reinterpret_cast<const float2*>(inputs + ((size_t)m * T + t) * 2);
            float4 bs = *reinterpret_cast<const float4*>(g_bias + n);
            float4 w01 = *reinterpret_cast<const float4*>(g_win + 2 * n);
            float4 w23 = *reinterpret_cast<const float4*>(g_win + 2 * n + 4);
            float a0 = s.x + bs.x + xv.x * w01.x + xv.y * w01.y;
            float a1 = s.y + bs.y + xv.x * w01.z + xv.y * w01.w;
            float a2 = s.z + bs.z + xv.x * w23.x + xv.y * w23.y;
            float a3 = s.w + bs.w + xv.x * w23.z + xv.y * w23.w;
            float alpha = (n < P1) ? 0.1f : 0.05f;
            float oma = 1.0f - alpha;
            const float* hp;
            float* op;
            if (n < P1) {
                hp = (t == 0) ? g_h0 + (size_t)m * PT + n
                              : oh1 + ((size_t)m * T + t - 1) * P1 + n;
                op = oh1 + ((size_t)m * T + t) * P1 + n;
            } else {
                hp = (t == 0) ? g_h0 + (size_t)m * PT + n
                              : oh2 + ((size_t)m * T + t - 1) * P2 + (n - P1);
                op = oh2 + ((size_t)m * T + t) * P2 + (n - P1);
            }
            float4 h4 = *reinterpret_cast<const float4*>(hp);
            float4 nh;
            nh.x = oma * h4.x + alpha * fast_tanh(a0);
            nh.y = oma * h4.y + alpha * fast_tanh(a1);
            nh.z = oma * h4.z + alpha * fast_tanh(a2);
            nh.w = oma * h4.w + alpha * fast_tanh(a3);
            *reinterpret_cast<float4*>(op) = nh;
            // persistent hi/lo split history (also consumed by out_kernel)
            __nv_bfloat16 hx = __float2bfloat16(nh.x), hy = __float2bfloat16(nh.y);
            __nv_bfloat16 hz = __float2bfloat16(nh.z), hw = __float2bfloat16(nh.w);
            uint2 hv = make_uint2(
                (uint32_t)__bfloat16_as_ushort(hx) | ((uint32_t)__bfloat16_as_ushort(hy) << 16),
                (uint32_t)__bfloat16_as_ushort(hz) | ((uint32_t)__bfloat16_as_ushort(hw) << 16));
            __nv_bfloat16 lx = __float2bfloat16(nh.x - __bfloat162float(hx));
            __nv_bfloat16 ly = __float2bfloat16(nh.y - __bfloat162float(hy));
            __nv_bfloat16 lz = __float2bfloat16(nh.z - __bfloat162float(hz));
            __nv_bfloat16 lw = __float2bfloat16(nh.w - __bfloat162float(hw));
            uint2 lv = make_uint2(
                (uint32_t)__bfloat16_as_ushort(lx) | ((uint32_t)__bfloat16_as_ushort(ly) << 16),
                (uint32_t)__bfloat16_as_ushort(lz) | ((uint32_t)__bfloat16_as_ushort(lw) << 16));
            size_t hoff = ((size_t)m * T + t) * PT + n;
            *reinterpret_cast<uint2*>(reinterpret_cast<char*>(g_histhi) + hoff * 2) = hv;
            *reinterpret_cast<uint2*>(reinterpret_cast<char*>(g_histlo) + hoff * 2) = lv;
        }

        // ===== single global barrier: h(t) published =====
        grid_bar(tid);
    }
}

// ---------------- output projection: reads pre-split history ----------------
__global__ void __launch_bounds__(256)
out_kernel(float* __restrict__ out2) {
    extern __shared__ char smraw[];
    char* sm = (char*)(((uintptr_t)smraw + 1023) & ~(uintptr_t)1023);
    uint32_t sb = smem_u32(sm);
    int tid = threadIdx.x;
    int bn = blockIdx.x * 64;      // over O
    int bm = blockIdx.y * 128;     // over B*T

    int lane = tid & 31, wrp = tid >> 5;
    int warpm = wrp & 3, warpn = wrp >> 2;
    uint32_t b_off = (uint32_t)((warpn * 32 + ((lane >> 4) & 1) * 8 + (lane & 7)) * 128 +
                                ((lane >> 3) & 1) * 16);

    auto issueAW = [&](int c) {
        int k0 = c * 64;
        int buf = c % 3;
        uint32_t da = sb + OA(buf);
        #pragma unroll
        for (int j = 0; j < 4; j++) {
            int u = tid + 256 * j;
            int row = u >> 3, kk = u & 7;
            size_t soff = (size_t)(bm + row) * PT + k0 + kk * 8;
            uint32_t d1 = da + swz((uint32_t)(row * 128 + kk * 16));
            cpasync16(d1, g_histhi + soff);
            cpasync16(d1 + 16384, g_histlo + soff);
        }
        uint32_t dw = sb + OW(buf);
        #pragma unroll
        for (int j = 0; j < 2; j++) {
            int u = tid + 256 * j;
            int row = u >> 3, kk = u & 7;
            size_t goff = (size_t)(bn + row) * PT + k0 + kk * 8;
            uint32_t d1 = dw + swz((uint32_t)(row * 128 + kk * 16));
            cpasync16(d1, g_Wouthi + goff);
            cpasync16(d1 + 8192, g_Woutlo + goff);
        }
        CP_COMMIT();
    };

    float acc[2][4][4] = {};
    issueAW(0);
    issueAW(1);
    for (int c = 0; c < NCHUNK; c++) {
        if (c < NCHUNK - 1) asm volatile("cp.async.wait_group 1;" ::: "memory");
        else                asm volatile("cp.async.wait_group 0;" ::: "memory");
        __syncthreads();
        if (c + 2 < NCHUNK) issueAW(c + 2);

        uint32_t ah = sb + OA(c % 3), al = ah + 16384;
        uint32_t wh = sb + OW(c % 3), wl = wh + 8192;
        #pragma unroll
        for (int kk = 0; kk < 4; kk++) {
            uint32_t Wh0[4], Wh1[4], Wl0[4], Wl1[4];
            uint32_t bo = b_off + kk * 32;
            ldmx4(Wh0, wh + swz(bo)); ldmx4(Wh1, wh + swz(bo + 2048));
            ldmx4(Wl0, wl + swz(bo)); ldmx4(Wl1, wl + swz(bo + 2048));
            #pragma unroll
            for (int mf = 0; mf < 2; mf++) {
                uint32_t Ah[4], Al[4];
                uint32_t ao = (uint32_t)((warpm * 32 + mf * 16 + (lane & 15)) * 128 +
                                         ((lane >> 4) & 1) * 16 + kk * 32);
                ldmx4(Ah, ah + swz(ao));
                ldmx4(Al, al + swz(ao));
                mma16816(acc[mf][0], Ah, Wh0[0], Wh0[1]);
                mma16816(acc[mf][1], Ah, Wh0[2], Wh0[3]);
                mma16816(acc[mf][2], Ah, Wh1[0], Wh1[1]);
                mma16816(acc[mf][3], Ah, Wh1[2], Wh1[3]);
                mma16816(acc[mf][0], Al, Wh0[0], Wh0[1]);
                mma16816(acc[mf][1], Al, Wh0[2], Wh0[3]);
                mma16816(acc[mf][2], Al, Wh1[0], Wh1[1]);
                mma16816(acc[mf][3], Al, Wh1[2], Wh1[3]);
                mma16816(acc[mf][0], Ah, Wl0[0], Wl0[1]);
                mma16816(acc[mf][1], Ah, Wl0[2], Wl0[3]);
                mma16816(acc[mf][2], Ah, Wl1[0], Wl1[1]);
                mma16816(acc[mf][3], Ah, Wl1[2], Wl1[3]);
            }
        }
    }

    #pragma unroll
    for (int mf = 0; mf < 2; mf++) {
        #pragma unroll
        for (int half = 0; half < 2; half++) {
            size_t m = (size_t)bm + warpm * 32 + mf * 16 + (lane >> 2) + half * 8;
            #pragma unroll
            for (int nj = 0; nj < 4; nj++) {
                int cc = warpn * 32 + nj * 8 + 2 * (lane & 3);
                float2 o2;
                o2.x = acc[mf][nj][half * 2 + 0];
                o2.y = acc[mf][nj][half * 2 + 1];
                *reinterpret_cast<float2*>(out2 + m * O + bn + cc) = o2;
            }
        }
    }
}

// ---------------- host ----------------
extern "C" void kernel_launch(void* const* d_in, const int* in_sizes, int n_in,
                              void* d_out, int out_size) {
    const float* inputs  = (const float*)d_in[0];
    const float* place0  = (const float*)d_in[1];
    const float* W_in1   = (const float*)d_in[2];
    const float* b_in1   = (const float*)d_in[3];
    const float* W_in2   = (const float*)d_in[4];
    const float* b_in2   = (const float*)d_in[5];
    const float* W_rec1  = (const float*)d_in[6];
    const float* b_rec1  = (const float*)d_in[7];
    const float* W_rec2  = (const float*)d_in[8];
    const float* b_rec2  = (const float*)d_in[9];
    const float* W_12    = (const float*)d_in[10];
    const float* b_12    = (const float*)d_in[11];
    const float* W_21    = (const float*)d_in[12];
    const float* b_21    = (const float*)d_in[13];
    const float* W_out   = (const float*)d_in[14];
    const float* W_h1    = (const float*)d_in[15];
    const float* W_h2    = (const float*)d_in[16];

    float* oh1  = (float*)d_out;
    float* oh2  = oh1 + (size_t)B * T * P1;
    float* out2 = oh2 + (size_t)B * T * P2;

    cudaFuncSetAttribute(rnn_kernel, cudaFuncAttributeMaxDynamicSharedMemorySize, PSM_REQ);
    cudaFuncSetAttribute(out_kernel, cudaFuncAttributeMaxDynamicSharedMemorySize, OSM_REQ);

    pack_kernel<<<256, 256>>>(W_rec1, b_rec1, W_rec2, b_rec2,
                              W_12, b_12, W_21, b_21,
                              W_in1, b_in1, W_in2, b_in2, W_out);

    {
        dim3 grid(PT / 64, B / 64);
        init_kernel<<<grid, 256>>>(place0, W_h1, W_h2);
    }

    rnn_kernel<<<NCTAS, 256, PSM_REQ>>>(inputs, oh1, oh2);

    {
        dim3 grid(O / 64, (B * T) / 128);  // 8 x 400
        out_kernel<<<grid, 256, OSM_REQ>>>(out2);
    }
}

// round 10
// speedup vs baseline: 6.9429x; 1.0294x over previous
#include <cuda_runtime.h>
#include <cuda_bf16.h>
#include <cstdint>

#define B 256
#define T 200
#define P1 1024
#define P2 512
#define PT 1536
#define O 512
#define NCHUNK 24        // K chunks of 64 (out_kernel)

#define NCTAS 144
#define KSPLIT 3
#define KPC 512          // K per CTA in persistent kernel
#define NGRP 48          // 24 n-tiles x 2 m-tiles

// ---------------- device scratch ----------------
__device__ float g_bias[PT];
__device__ float g_win[2 * PT];
__device__ float g_h0[B * PT];
__device__ __nv_bfloat16 g_h0hi[B * PT];
__device__ __nv_bfloat16 g_h0lo[B * PT];
__device__ __nv_bfloat16 g_histhi[(size_t)B * T * PT];   // bf16 hi history
__device__ __nv_bfloat16 g_histlo[(size_t)B * T * PT];   // bf16 lo history
__device__ float g_part[KSPLIT * B * PT];                // split-K partials
__device__ __nv_bfloat16 g_Whi[PT * PT];
__device__ __nv_bfloat16 g_Wlo[PT * PT];
__device__ __nv_bfloat16 g_Wouthi[O * PT];
__device__ __nv_bfloat16 g_Woutlo[O * PT];
__device__ unsigned g_cnt;
__device__ unsigned g_gen;
__device__ unsigned g_tc[NGRP];          // per-tile-group cumulative counters

// ---------------- smem layout: persistent rnn kernel ----------------
#define PW_CH(c)  ((c) * 16384)                  // W chunk c: hi 8KB, lo +8192 (8 chunks)
#define PA_BUF(b) (131072 + (b) * 32768)         // A buf: hi 16KB, lo +16384 (2 bufs)
#define PSM_REQ   (131072 + 2 * 32768 + 1024)

// ---------------- smem layout: out_kernel (128x128 tile) ----------------
#define OA(b)    ((b) * 32768)                   // A buf: hi 16KB, lo +16384 (3 bufs)
#define OW(b)    (98304 + (b) * 32768)           // W buf: hi 16KB, lo +16384 (3 bufs)
#define OSM_REQ  (98304 + 3 * 32768 + 1024)

// ---------------- helpers ----------------
__device__ __forceinline__ uint32_t smem_u32(const void* p) {
    uint32_t a;
    asm("{ .reg .u64 t; cvta.to.shared.u64 t, %1; cvt.u32.u64 %0, t; }" : "=r"(a) : "l"(p));
    return a;
}
__device__ __forceinline__ uint32_t swz(uint32_t o) { return o ^ ((o >> 3) & 0x70); }

__device__ __forceinline__ void ldmx4(uint32_t r[4], uint32_t addr) {
    asm volatile("ldmatrix.sync.aligned.m8n8.x4.shared.b16 {%0,%1,%2,%3}, [%4];"
        : "=r"(r[0]), "=r"(r[1]), "=r"(r[2]), "=r"(r[3]) : "r"(addr));
}
__device__ __forceinline__ void mma16816(float d[4], const uint32_t a[4], uint32_t b0, uint32_t b1) {
    asm volatile("mma.sync.aligned.m16n8k16.row.col.f32.bf16.bf16.f32 "
        "{%0,%1,%2,%3}, {%4,%5,%6,%7}, {%8,%9}, {%0,%1,%2,%3};"
        : "+f"(d[0]), "+f"(d[1]), "+f"(d[2]), "+f"(d[3])
        : "r"(a[0]), "r"(a[1]), "r"(a[2]), "r"(a[3]), "r"(b0), "r"(b1));
}
__device__ __forceinline__ void cpasync16(uint32_t dst, const void* src) {
    asm volatile("cp.async.cg.shared.global [%0], [%1], 16;" :: "r"(dst), "l"(src));
}
#define CP_COMMIT() asm volatile("cp.async.commit_group;" ::: "memory")

__device__ __forceinline__ float fast_tanh(float x) {
    return 1.0f - __fdividef(2.0f, __expf(2.0f * x) + 1.0f);
}

// grid-wide sense-reversing barrier (all NCTAS co-resident: 1 CTA/SM)
__device__ __forceinline__ void grid_bar(int tid) {
    __syncthreads();
    if (tid == 0) {
        __threadfence();
        unsigned gen = atomicAdd(&g_gen, 0u);
        if (atomicAdd(&g_cnt, 1u) == NCTAS - 1u) {
            atomicExch(&g_cnt, 0u);
            __threadfence();
            atomicAdd(&g_gen, 1u);
        } else {
            while (*((volatile unsigned*)&g_gen) == gen) {}
        }
        __threadfence();
    }
    __syncthreads();
}

// ---------------- pack: one CTA per weight row; fuse biases, split to bf16 hi/lo ----------------
__global__ void __launch_bounds__(256)
pack_kernel(const float* __restrict__ W_rec1, const float* __restrict__ b_rec1,
            const float* __restrict__ W_rec2, const float* __restrict__ b_rec2,
            const float* __restrict__ W_12,   const float* __restrict__ b_12,
            const float* __restrict__ W_21,   const float* __restrict__ b_21,
            const float* __restrict__ W_in1,  const float* __restrict__ b_in1,
            const float* __restrict__ W_in2,  const float* __restrict__ b_in2,
            const float* __restrict__ W_out) {
    int n = blockIdx.x;      // 0..1535
    int tid = threadIdx.x;

    if (n == 0 && tid < NGRP) g_tc[tid] = 0;
    if (n == 0 && tid == 0) g_cnt = 0;

    // Wcat row n: [W_rec1|W_21 ; W_12|W_rec2]
    const float* s1 = (n < P1) ? (W_rec1 + (size_t)n * P1) : (W_12 + (size_t)(n - P1) * P1);
    const float* s2 = (n < P1) ? (W_21 + (size_t)n * P2)   : (W_rec2 + (size_t)(n - P1) * P2);
    for (int k = tid; k < P1; k += 256) {
        float v = s1[k];
        __nv_bfloat16 h = __float2bfloat16(v);
        g_Whi[(size_t)n * PT + k] = h;
        g_Wlo[(size_t)n * PT + k] = __float2bfloat16(v - __bfloat162float(h));
    }
    for (int k = tid; k < P2; k += 256) {
        float v = s2[k];
        __nv_bfloat16 h = __float2bfloat16(v);
        g_Whi[(size_t)n * PT + P1 + k] = h;
        g_Wlo[(size_t)n * PT + P1 + k] = __float2bfloat16(v - __bfloat162float(h));
    }
    // Wout row n (rows 0..O-1)
    if (n < O) {
        for (int k = tid; k < PT; k += 256) {
            float v = W_out[(size_t)n * PT + k];
            __nv_bfloat16 h = __float2bfloat16(v);
            g_Wouthi[(size_t)n * PT + k] = h;
            g_Woutlo[(size_t)n * PT + k] = __float2bfloat16(v - __bfloat162float(h));
        }
    }
    // bias + input weights for unit n
    if (tid == 0) {
        if (n < P1) {
            g_bias[n] = b_rec1[n] + b_21[n] + b_in1[n];
            g_win[2 * n]     = W_in1[2 * n];
            g_win[2 * n + 1] = W_in1[2 * n + 1];
        } else {
            int n2 = n - P1;
            g_bias[n] = b_rec2[n2] + b_12[n2] + b_in2[n2];
            g_win[2 * n]     = W_in2[2 * n2];
            g_win[2 * n + 1] = W_in2[2 * n2 + 1];
        }
    }
}

// ---------------- init: h0 = place @ [W_h1;W_h2].T + write split ----------------
__global__ void init_kernel(const float* __restrict__ place,
                            const float* __restrict__ Wh1,
                            const float* __restrict__ Wh2) {
    __shared__ float As[16][65];
    __shared__ float Ws[16][65];
    int tid = threadIdx.x;
    int bn = blockIdx.x * 64;
    int bm = blockIdx.y * 64;
    float acc[4][4] = {};
    for (int k0 = 0; k0 < O; k0 += 16) {
        #pragma unroll
        for (int i = 0; i < 4; i++) {
            int lin = tid + 256 * i;
            int r = lin >> 4, c = lin & 15;
            As[c][r] = place[(bm + r) * O + k0 + c];
            int n = bn + r;
            Ws[c][r] = (n < P1) ? Wh1[n * O + k0 + c] : Wh2[(n - P1) * O + k0 + c];
        }
        __syncthreads();
        #pragma unroll
        for (int c = 0; c < 16; c++) {
            float af[4], wf[4];
            int ty = tid >> 4, tx = tid & 15;
            #pragma unroll
            for (int j = 0; j < 4; j++) { af[j] = As[c][ty * 4 + j]; wf[j] = Ws[c][tx * 4 + j]; }
            #pragma unroll
            for (int a = 0; a < 4; a++)
                #pragma unroll
                for (int b2 = 0; b2 < 4; b2++)
                    acc[a][b2] = fmaf(af[a], wf[b2], acc[a][b2]);
        }
        __syncthreads();
    }
    int ty = tid >> 4, tx = tid & 15;
    #pragma unroll
    for (int a = 0; a < 4; a++)
        #pragma unroll
        for (int b2 = 0; b2 < 4; b2++) {
            float v = acc[a][b2];
            size_t off = (size_t)(bm + ty * 4 + a) * PT + bn + tx * 4 + b2;
            g_h0[off] = v;
            __nv_bfloat16 h = __float2bfloat16(v);
            g_h0hi[off] = h;
            g_h0lo[off] = __float2bfloat16(v - __bfloat162float(h));
        }
}

// ---------------- persistent RNN kernel (R7 proven structure) ----------------
// 144 CTAs = 24 n-tiles(64) x 2 m-tiles(128) x 3 k-splits(512)
// W slice resident in SMEM; per-tile group sync for reduction; 1 global barrier/step
__global__ void __launch_bounds__(256)
rnn_kernel(const float* __restrict__ inputs,
           float* __restrict__ oh1, float* __restrict__ oh2) {
    extern __shared__ char smraw[];
    char* sm = (char*)(((uintptr_t)smraw + 1023) & ~(uintptr_t)1023);
    uint32_t sb = smem_u32(sm);
    int tid = threadIdx.x;
    int cta = blockIdx.x;
    int nt = cta / 6;
    int rem = cta % 6;
    int mt = rem / 3;
    int ksp = rem % 3;
    int bn = nt * 64;
    int bm = mt * 128;
    int kbase = ksp * KPC;
    int grp = nt * 2 + mt;

    // ---- load resident W slice (64 n x 512 k, hi+lo = 128KB) once ----
    for (int c = 0; c < 8; c++) {
        int k0 = kbase + c * 64;
        #pragma unroll
        for (int j = 0; j < 2; j++) {
            int u = tid + 256 * j;
            int row = u >> 3, kk = u & 7;
            size_t goff = (size_t)(bn + row) * PT + k0 + kk * 8;
            uint32_t d1 = sb + PW_CH(c) + swz((uint32_t)(row * 128 + kk * 16));
            cpasync16(d1, g_Whi + goff);
            cpasync16(d1 + 8192, g_Wlo + goff);
        }
    }
    CP_COMMIT();
    asm volatile("cp.async.wait_group 0;" ::: "memory");
    __syncthreads();

    int lane = tid & 31, wrp = tid >> 5;
    int warpm = wrp & 3, warpn = wrp >> 2;     // warp tile 32m x 32n over 128x64
    uint32_t b_off = (uint32_t)((warpn * 32 + ((lane >> 4) & 1) * 8 + (lane & 7)) * 128 +
                                ((lane >> 3) & 1) * 16);
    float* pbase = g_part + (size_t)ksp * B * PT;

    for (int t = 0; t < T; t++) {
        // ===== phase A: partial GEMM (128m x 64n x 512k) =====
        const __nv_bfloat16* ahi;
        const __nv_bfloat16* alo;
        size_t astr;
        if (t == 0) { ahi = g_h0hi; alo = g_h0lo; astr = PT; }
        else {
            ahi = g_histhi + (size_t)(t - 1) * PT;
            alo = g_histlo + (size_t)(t - 1) * PT;
            astr = (size_t)T * PT;
        }
        float acc[2][4][4] = {};
        auto issueA = [&](int c) {
            uint32_t dst = sb + PA_BUF(c & 1);
            int k0 = kbase + c * 64;
            #pragma unroll
            for (int j = 0; j < 4; j++) {
                int u = tid + 256 * j;
                int row = u >> 3, kk = u & 7;
                size_t soff = (size_t)(bm + row) * astr + k0 + kk * 8;
                uint32_t d1 = dst + swz((uint32_t)(row * 128 + kk * 16));
                cpasync16(d1, ahi + soff);
                cpasync16(d1 + 16384, alo + soff);
            }
            CP_COMMIT();
        };
        issueA(0);
        #pragma unroll
        for (int c = 0; c < 8; c++) {
            asm volatile("cp.async.wait_group 0;" ::: "memory");
            __syncthreads();
            if (c + 1 < 8) issueA(c + 1);
            uint32_t ah = sb + PA_BUF(c & 1), al = ah + 16384;
            uint32_t wh = sb + PW_CH(c), wl = wh + 8192;
            #pragma unroll
            for (int kk = 0; kk < 4; kk++) {
                uint32_t Wh0[4], Wh1[4], Wl0[4], Wl1[4];
                uint32_t bo = b_off + kk * 32;
                ldmx4(Wh0, wh + swz(bo)); ldmx4(Wh1, wh + swz(bo + 2048));
                ldmx4(Wl0, wl + swz(bo)); ldmx4(Wl1, wl + swz(bo + 2048));
                #pragma unroll
                for (int mf = 0; mf < 2; mf++) {
                    uint32_t Ah[4], Al[4];
                    uint32_t ao = (uint32_t)((warpm * 32 + mf * 16 + (lane & 15)) * 128 +
                                             ((lane >> 4) & 1) * 16 + kk * 32);
                    ldmx4(Ah, ah + swz(ao));
                    ldmx4(Al, al + swz(ao));
                    mma16816(acc[mf][0], Ah, Wh0[0], Wh0[1]);
                    mma16816(acc[mf][1], Ah, Wh0[2], Wh0[3]);
                    mma16816(acc[mf][2], Ah, Wh1[0], Wh1[1]);
                    mma16816(acc[mf][3], Ah, Wh1[2], Wh1[3]);
                    mma16816(acc[mf][0], Al, Wh0[0], Wh0[1]);
                    mma16816(acc[mf][1], Al, Wh0[2], Wh0[3]);
                    mma16816(acc[mf][2], Al, Wh1[0], Wh1[1]);
                    mma16816(acc[mf][3], Al, Wh1[2], Wh1[3]);
                    mma16816(acc[mf][0], Ah, Wl0[0], Wl0[1]);
                    mma16816(acc[mf][1], Ah, Wl0[2], Wl0[3]);
                    mma16816(acc[mf][2], Ah, Wl1[0], Wl1[1]);
                    mma16816(acc[mf][3], Ah, Wl1[2], Wl1[3]);
                }
            }
        }
        // store partials for this k-split
        #pragma unroll
        for (int mf = 0; mf < 2; mf++) {
            int m0 = bm + warpm * 32 + mf * 16 + (lane >> 2);
            #pragma unroll
            for (int nf = 0; nf < 4; nf++) {
                int n = bn + warpn * 32 + nf * 8 + (lane & 3) * 2;
                *reinterpret_cast<float2*>(pbase + (size_t)m0 * PT + n) =
                    make_float2(acc[mf][nf][0], acc[mf][nf][1]);
                *reinterpret_cast<float2*>(pbase + (size_t)(m0 + 8) * PT + n) =
                    make_float2(acc[mf][nf][2], acc[mf][nf][3]);
            }
        }

        // ===== group sync: wait for the 3 k-split CTAs of this tile =====
        __threadfence();
        __syncthreads();
        if (tid == 0) {
            atomicAdd(&g_tc[grp], 1u);
            unsigned target = 3u * (unsigned)(t + 1);
            while (atomicAdd(&g_tc[grp], 0u) < target) {}
        }
        __syncthreads();
        __threadfence();

        // ===== phase B: reduce own tile (128m x 64n) + epilogue =====
        for (int e = ksp * 256 + tid; e < 2048; e += 768) {
            int m = bm + (e >> 4);
            int n = bn + ((e & 15) << 2);
            float4 s = __ldcg(reinterpret_cast<const float4*>(g_part + (size_t)m * PT + n));
            #pragma unroll
            for (int kq = 1; kq < KSPLIT; kq++) {
                float4 p = __ldcg(reinterpret_cast<const float4*>(
                    g_part + ((size_t)kq * B + m) * PT + n));
                s.x += p.x; s.y += p.y; s.z += p.z; s.w += p.w;
            }
            float2 xv = *reinterpret_cast<const float2*>(inputs + ((size_t)m * T + t) * 2);
            float4 bs = *reinterpret_cast<const float4*>(g_bias + n);
            float4 w01 = *reinterpret_cast<const float4*>(g_win + 2 * n);
            float4 w23 = *reinterpret_cast<const float4*>(g_win + 2 * n + 4);
            float a0 = s.x + bs.x + xv.x * w01.x + xv.y * w01.y;
            float a1 = s.y + bs.y + xv.x * w01.z + xv.y * w01.w;
            float a2 = s.z + bs.z + xv.x * w23.x + xv.y * w23.y;
            float a3 = s.w + bs.w + xv.x * w23.z + xv.y * w23.w;
            float alpha = (n < P1) ? 0.1f : 0.05f;
            float oma = 1.0f - alpha;
            const float* hp;
            float* op;
            if (n < P1) {
                hp = (t == 0) ? g_h0 + (size_t)m * PT + n
                              : oh1 + ((size_t)m * T + t - 1) * P1 + n;
                op = oh1 + ((size_t)m * T + t) * P1 + n;
            } else {
                hp = (t == 0) ? g_h0 + (size_t)m * PT + n
                              : oh2 + ((size_t)m * T + t - 1) * P2 + (n - P1);
                op = oh2 + ((size_t)m * T + t) * P2 + (n - P1);
            }
            float4 h4 = *reinterpret_cast<const float4*>(hp);
            float4 nh;
            nh.x = oma * h4.x + alpha * fast_tanh(a0);
            nh.y = oma * h4.y + alpha * fast_tanh(a1);
            nh.z = oma * h4.z + alpha * fast_tanh(a2);
            nh.w = oma * h4.w + alpha * fast_tanh(a3);
            *reinterpret_cast<float4*>(op) = nh;
            // persistent hi/lo split history (consumed by phase A and out_kernel)
            __nv_bfloat16 hx = __float2bfloat16(nh.x), hy = __float2bfloat16(nh.y);
            __nv_bfloat16 hz = __float2bfloat16(nh.z), hw = __float2bfloat16(nh.w);
            uint2 hv = make_uint2(
                (uint32_t)__bfloat16_as_ushort(hx) | ((uint32_t)__bfloat16_as_ushort(hy) << 16),
                (uint32_t)__bfloat16_as_ushort(hz) | ((uint32_t)__bfloat16_as_ushort(hw) << 16));
            __nv_bfloat16 lx = __float2bfloat16(nh.x - __bfloat162float(hx));
            __nv_bfloat16 ly = __float2bfloat16(nh.y - __bfloat162float(hy));
            __nv_bfloat16 lz = __float2bfloat16(nh.z - __bfloat162float(hz));
            __nv_bfloat16 lw = __float2bfloat16(nh.w - __bfloat162float(hw));
            uint2 lv = make_uint2(
                (uint32_t)__bfloat16_as_ushort(lx) | ((uint32_t)__bfloat16_as_ushort(ly) << 16),
                (uint32_t)__bfloat16_as_ushort(lz) | ((uint32_t)__bfloat16_as_ushort(lw) << 16));
            size_t hoff = ((size_t)m * T + t) * PT + n;
            *reinterpret_cast<uint2*>(reinterpret_cast<char*>(g_histhi) + hoff * 2) = hv;
            *reinterpret_cast<uint2*>(reinterpret_cast<char*>(g_histlo) + hoff * 2) = lv;
        }

        // ===== single global barrier: h(t) published =====
        grid_bar(tid);
    }
}

// ---------------- output projection: 128x128 tile, reads pre-split history ----------------
__global__ void __launch_bounds__(256)
out_kernel(float* __restrict__ out2) {
    extern __shared__ char smraw[];
    char* sm = (char*)(((uintptr_t)smraw + 1023) & ~(uintptr_t)1023);
    uint32_t sb = smem_u32(sm);
    int tid = threadIdx.x;
    int bn = blockIdx.x * 128;     // over O (4 tiles)
    int bm = blockIdx.y * 128;     // over B*T (400 tiles)

    int lane = tid & 31, wrp = tid >> 5;
    int warpm = wrp & 3, warpn = wrp >> 2;   // warp tile 32m x 64n
    uint32_t b_off = (uint32_t)((warpn * 64 + ((lane >> 4) & 1) * 8 + (lane & 7)) * 128 +
                                ((lane >> 3) & 1) * 16);

    auto issueAW = [&](int c) {
        int k0 = c * 64;
        int buf = c % 3;
        // A: 128 rows x 64 k, hi+lo
        uint32_t da = sb + OA(buf);
        #pragma unroll
        for (int j = 0; j < 4; j++) {
            int u = tid + 256 * j;
            int row = u >> 3, kk = u & 7;
            size_t soff = (size_t)(bm + row) * PT + k0 + kk * 8;
            uint32_t d1 = da + swz((uint32_t)(row * 128 + kk * 16));
            cpasync16(d1, g_histhi + soff);
            cpasync16(d1 + 16384, g_histlo + soff);
        }
        // W: 128 rows x 64 k, hi+lo
        uint32_t dw = sb + OW(buf);
        #pragma unroll
        for (int j = 0; j < 4; j++) {
            int u = tid + 256 * j;
            int row = u >> 3, kk = u & 7;
            size_t goff = (size_t)(bn + row) * PT + k0 + kk * 8;
            uint32_t d1 = dw + swz((uint32_t)(row * 128 + kk * 16));
            cpasync16(d1, g_Wouthi + goff);
            cpasync16(d1 + 16384, g_Woutlo + goff);
        }
        CP_COMMIT();
    };

    float acc[2][8][4] = {};
    issueAW(0);
    issueAW(1);
    for (int c = 0; c < NCHUNK; c++) {
        if (c < NCHUNK - 1) asm volatile("cp.async.wait_group 1;" ::: "memory");
        else                asm volatile("cp.async.wait_group 0;" ::: "memory");
        __syncthreads();
        if (c + 2 < NCHUNK) issueAW(c + 2);

        uint32_t ah = sb + OA(c % 3), al = ah + 16384;
        uint32_t wh = sb + OW(c % 3), wl = wh + 16384;
        #pragma unroll
        for (int kk = 0; kk < 4; kk++) {
            uint32_t WhA[4], WhB[4], WhC[4], WhD[4];
            uint32_t WlA[4], WlB[4], WlC[4], WlD[4];
            uint32_t bo = b_off + kk * 32;
            ldmx4(WhA, wh + swz(bo));        ldmx4(WhB, wh + swz(bo + 2048));
            ldmx4(WhC, wh + swz(bo + 4096)); ldmx4(WhD, wh + swz(bo + 6144));
            ldmx4(WlA, wl + swz(bo));        ldmx4(WlB, wl + swz(bo + 2048));
            ldmx4(WlC, wl + swz(bo + 4096)); ldmx4(WlD, wl + swz(bo + 6144));
            #pragma unroll
            for (int mf = 0; mf < 2; mf++) {
                uint32_t Ah[4], Al[4];
                uint32_t ao = (uint32_t)((warpm * 32 + mf * 16 + (lane & 15)) * 128 +
                                         ((lane >> 4) & 1) * 16 + kk * 32);
                ldmx4(Ah, ah + swz(ao));
                ldmx4(Al, al + swz(ao));
                // pass 1: Ahi x Whi
                mma16816(acc[mf][0], Ah, WhA[0], WhA[1]); mma16816(acc[mf][1], Ah, WhA[2], WhA[3]);
                mma16816(acc[mf][2], Ah, WhB[0], WhB[1]); mma16816(acc[mf][3], Ah, WhB[2], WhB[3]);
                mma16816(acc[mf][4], Ah, WhC[0], WhC[1]); mma16816(acc[mf][5], Ah, WhC[2], WhC[3]);
                mma16816(acc[mf][6], Ah, WhD[0], WhD[1]); mma16816(acc[mf][7], Ah, WhD[2], WhD[3]);
                // pass 2: Alo x Whi
                mma16816(acc[mf][0], Al, WhA[0], WhA[1]); mma16816(acc[mf][1], Al, WhA[2], WhA[3]);
                mma16816(acc[mf][2], Al, WhB[0], WhB[1]); mma16816(acc[mf][3], Al, WhB[2], WhB[3]);
                mma16816(acc[mf][4], Al, WhC[0], WhC[1]); mma16816(acc[mf][5], Al, WhC[2], WhC[3]);
                mma16816(acc[mf][6], Al, WhD[0], WhD[1]); mma16816(acc[mf][7], Al, WhD[2], WhD[3]);
                // pass 3: Ahi x Wlo
                mma16816(acc[mf][0], Ah, WlA[0], WlA[1]); mma16816(acc[mf][1], Ah, WlA[2], WlA[3]);
                mma16816(acc[mf][2], Ah, WlB[0], WlB[1]); mma16816(acc[mf][3], Ah, WlB[2], WlB[3]);
                mma16816(acc[mf][4], Ah, WlC[0], WlC[1]); mma16816(acc[mf][5], Ah, WlC[2], WlC[3]);
                mma16816(acc[mf][6], Ah, WlD[0], WlD[1]); mma16816(acc[mf][7], Ah, WlD[2], WlD[3]);
            }
        }
    }

    #pragma unroll
    for (int mf = 0; mf < 2; mf++) {
        #pragma unroll
        for (int half = 0; half < 2; half++) {
            size_t m = (size_t)bm + warpm * 32 + mf * 16 + (lane >> 2) + half * 8;
            #pragma unroll
            for (int nj = 0; nj < 8; nj++) {
                int cc = warpn * 64 + nj * 8 + 2 * (lane & 3);
                float2 o2;
                o2.x = acc[mf][nj][half * 2 + 0];
                o2.y = acc[mf][nj][half * 2 + 1];
                *reinterpret_cast<float2*>(out2 + m * O + bn + cc) = o2;
            }
        }
    }
}

// ---------------- host ----------------
extern "C" void kernel_launch(void* const* d_in, const int* in_sizes, int n_in,
                              void* d_out, int out_size) {
    const float* inputs  = (const float*)d_in[0];
    const float* place0  = (const float*)d_in[1];
    const float* W_in1   = (const float*)d_in[2];
    const float* b_in1   = (const float*)d_in[3];
    const float* W_in2   = (const float*)d_in[4];
    const float* b_in2   = (const float*)d_in[5];
    const float* W_rec1  = (const float*)d_in[6];
    const float* b_rec1  = (const float*)d_in[7];
    const float* W_rec2  = (const float*)d_in[8];
    const float* b_rec2  = (const float*)d_in[9];
    const float* W_12    = (const float*)d_in[10];
    const float* b_12    = (const float*)d_in[11];
    const float* W_21    = (const float*)d_in[12];
    const float* b_21    = (const float*)d_in[13];
    const float* W_out   = (const float*)d_in[14];
    const float* W_h1    = (const float*)d_in[15];
    const float* W_h2    = (const float*)d_in[16];

    float* oh1  = (float*)d_out;
    float* oh2  = oh1 + (size_t)B * T * P1;
    float* out2 = oh2 + (size_t)B * T * P2;

    cudaFuncSetAttribute(rnn_kernel, cudaFuncAttributeMaxDynamicSharedMemorySize, PSM_REQ);
    cudaFuncSetAttribute(out_kernel, cudaFuncAttributeMaxDynamicSharedMemorySize, OSM_REQ);

    pack_kernel<<<PT, 256>>>(W_rec1, b_rec1, W_rec2, b_rec2,
                             W_12, b_12, W_21, b_21,
                             W_in1, b_in1, W_in2, b_in2, W_out);

    {
        dim3 grid(PT / 64, B / 64);
        init_kernel<<<grid, 256>>>(place0, W_h1, W_h2);
    }

    rnn_kernel<<<NCTAS, 256, PSM_REQ>>>(inputs, oh1, oh2);

    {
        dim3 grid(O / 128, (B * T) / 128);  // 4 x 400
        out_kernel<<<grid, 256, OSM_REQ>>>(out2);
    }
}

// round 11
// speedup vs baseline: 6.9993x; 1.0081x over previous
#include <cuda_runtime.h>
#include <cuda_bf16.h>
#include <cstdint>

#define B 256
#define T 200
#define P1 1024
#define P2 512
#define PT 1536
#define O 512
#define NCHUNK 24        // K chunks of 64 (out_kernel)

#define NCTAS 144
#define KSPLIT 3
#define KPC 512          // K per CTA in persistent kernel
#define NGRP 48          // 24 n-tiles x 2 m-tiles

// ---------------- device scratch ----------------
__device__ float g_bias[PT];
__device__ float g_win[2 * PT];
__device__ float g_h0[B * PT];
__device__ __nv_bfloat16 g_h0hi[B * PT];
__device__ __nv_bfloat16 g_h0lo[B * PT];
__device__ __nv_bfloat16 g_histhi[(size_t)B * T * PT];   // bf16 hi history
__device__ __nv_bfloat16 g_histlo[(size_t)B * T * PT];   // bf16 lo history
__device__ float g_part[KSPLIT * B * PT];                // split-K partials
__device__ __nv_bfloat16 g_Whi[PT * PT];
__device__ __nv_bfloat16 g_Wlo[PT * PT];
__device__ __nv_bfloat16 g_Wouthi[O * PT];
__device__ __nv_bfloat16 g_Woutlo[O * PT];
__device__ unsigned g_cnt;
__device__ unsigned g_gen;
__device__ unsigned g_tc[NGRP];          // per-tile-group cumulative counters

// ---------------- smem layout: persistent rnn kernel ----------------
#define PW_CH(c)  ((c) * 16384)                  // W chunk c: hi 8KB, lo +8192 (8 chunks)
#define PA_BUF(b) (131072 + (b) * 32768)         // A buf: hi 16KB, lo +16384 (2 bufs)
#define PSM_REQ   (131072 + 2 * 32768 + 1024)

// ---------------- smem layout: out_kernel (128x128 tile) ----------------
#define OA(b)    ((b) * 32768)                   // A buf: hi 16KB, lo +16384 (3 bufs)
#define OW(b)    (98304 + (b) * 32768)           // W buf: hi 16KB, lo +16384 (3 bufs)
#define OSM_REQ  (98304 + 3 * 32768 + 1024)

// ---------------- helpers ----------------
__device__ __forceinline__ uint32_t smem_u32(const void* p) {
    uint32_t a;
    asm("{ .reg .u64 t; cvta.to.shared.u64 t, %1; cvt.u32.u64 %0, t; }" : "=r"(a) : "l"(p));
    return a;
}
__device__ __forceinline__ uint32_t swz(uint32_t o) { return o ^ ((o >> 3) & 0x70); }

__device__ __forceinline__ void ldmx4(uint32_t r[4], uint32_t addr) {
    asm volatile("ldmatrix.sync.aligned.m8n8.x4.shared.b16 {%0,%1,%2,%3}, [%4];"
        : "=r"(r[0]), "=r"(r[1]), "=r"(r[2]), "=r"(r[3]) : "r"(addr));
}
__device__ __forceinline__ void mma16816(float d[4], const uint32_t a[4], uint32_t b0, uint32_t b1) {
    asm volatile("mma.sync.aligned.m16n8k16.row.col.f32.bf16.bf16.f32 "
        "{%0,%1,%2,%3}, {%4,%5,%6,%7}, {%8,%9}, {%0,%1,%2,%3};"
        : "+f"(d[0]), "+f"(d[1]), "+f"(d[2]), "+f"(d[3])
        : "r"(a[0]), "r"(a[1]), "r"(a[2]), "r"(a[3]), "r"(b0), "r"(b1));
}
__device__ __forceinline__ void cpasync16(uint32_t dst, const void* src) {
    asm volatile("cp.async.cg.shared.global [%0], [%1], 16;" :: "r"(dst), "l"(src));
}
#define CP_COMMIT() asm volatile("cp.async.commit_group;" ::: "memory")

__device__ __forceinline__ float fast_tanh(float x) {
    return 1.0f - __fdividef(2.0f, __expf(2.0f * x) + 1.0f);
}

// grid-wide sense-reversing barrier (all NCTAS co-resident: 1 CTA/SM)
__device__ __forceinline__ void grid_bar(int tid) {
    __syncthreads();
    if (tid == 0) {
        __threadfence();
        unsigned gen = atomicAdd(&g_gen, 0u);
        if (atomicAdd(&g_cnt, 1u) == NCTAS - 1u) {
            atomicExch(&g_cnt, 0u);
            __threadfence();
            atomicAdd(&g_gen, 1u);
        } else {
            while (*((volatile unsigned*)&g_gen) == gen) {}
        }
        __threadfence();
    }
    __syncthreads();
}

// ---------------- pack: one CTA per weight row; fuse biases, split to bf16 hi/lo ----------------
__global__ void __launch_bounds__(256)
pack_kernel(const float* __restrict__ W_rec1, const float* __restrict__ b_rec1,
            const float* __restrict__ W_rec2, const float* __restrict__ b_rec2,
            const float* __restrict__ W_12,   const float* __restrict__ b_12,
            const float* __restrict__ W_21,   const float* __restrict__ b_21,
            const float* __restrict__ W_in1,  const float* __restrict__ b_in1,
            const float* __restrict__ W_in2,  const float* __restrict__ b_in2,
            const float* __restrict__ W_out) {
    int n = blockIdx.x;      // 0..1535
    int tid = threadIdx.x;

    if (n == 0 && tid < NGRP) g_tc[tid] = 0;
    if (n == 0 && tid == 0) g_cnt = 0;

    // Wcat row n: [W_rec1|W_21 ; W_12|W_rec2]
    const float* s1 = (n < P1) ? (W_rec1 + (size_t)n * P1) : (W_12 + (size_t)(n - P1) * P1);
    const float* s2 = (n < P1) ? (W_21 + (size_t)n * P2)   : (W_rec2 + (size_t)(n - P1) * P2);
    for (int k = tid; k < P1; k += 256) {
        float v = s1[k];
        __nv_bfloat16 h = __float2bfloat16(v);
        g_Whi[(size_t)n * PT + k] = h;
        g_Wlo[(size_t)n * PT + k] = __float2bfloat16(v - __bfloat162float(h));
    }
    for (int k = tid; k < P2; k += 256) {
        float v = s2[k];
        __nv_bfloat16 h = __float2bfloat16(v);
        g_Whi[(size_t)n * PT + P1 + k] = h;
        g_Wlo[(size_t)n * PT + P1 + k] = __float2bfloat16(v - __bfloat162float(h));
    }
    // Wout row n (rows 0..O-1)
    if (n < O) {
        for (int k = tid; k < PT; k += 256) {
            float v = W_out[(size_t)n * PT + k];
            __nv_bfloat16 h = __float2bfloat16(v);
            g_Wouthi[(size_t)n * PT + k] = h;
            g_Woutlo[(size_t)n * PT + k] = __float2bfloat16(v - __bfloat162float(h));
        }
    }
    // bias + input weights for unit n
    if (tid == 0) {
        if (n < P1) {
            g_bias[n] = b_rec1[n] + b_21[n] + b_in1[n];
            g_win[2 * n]     = W_in1[2 * n];
            g_win[2 * n + 1] = W_in1[2 * n + 1];
        } else {
            int n2 = n - P1;
            g_bias[n] = b_rec2[n2] + b_12[n2] + b_in2[n2];
            g_win[2 * n]     = W_in2[2 * n2];
            g_win[2 * n + 1] = W_in2[2 * n2 + 1];
        }
    }
}

// ---------------- init: h0 = place @ [W_h1;W_h2].T + write split ----------------
__global__ void init_kernel(const float* __restrict__ place,
                            const float* __restrict__ Wh1,
                            const float* __restrict__ Wh2) {
    __shared__ float As[16][65];
    __shared__ float Ws[16][65];
    int tid = threadIdx.x;
    int bn = blockIdx.x * 64;
    int bm = blockIdx.y * 64;
    float acc[4][4] = {};
    for (int k0 = 0; k0 < O; k0 += 16) {
        #pragma unroll
        for (int i = 0; i < 4; i++) {
            int lin = tid + 256 * i;
            int r = lin >> 4, c = lin & 15;
            As[c][r] = place[(bm + r) * O + k0 + c];
            int n = bn + r;
            Ws[c][r] = (n < P1) ? Wh1[n * O + k0 + c] : Wh2[(n - P1) * O + k0 + c];
        }
        __syncthreads();
        #pragma unroll
        for (int c = 0; c < 16; c++) {
            float af[4], wf[4];
            int ty = tid >> 4, tx = tid & 15;
            #pragma unroll
            for (int j = 0; j < 4; j++) { af[j] = As[c][ty * 4 + j]; wf[j] = Ws[c][tx * 4 + j]; }
            #pragma unroll
            for (int a = 0; a < 4; a++)
                #pragma unroll
                for (int b2 = 0; b2 < 4; b2++)
                    acc[a][b2] = fmaf(af[a], wf[b2], acc[a][b2]);
        }
        __syncthreads();
    }
    int ty = tid >> 4, tx = tid & 15;
    #pragma unroll
    for (int a = 0; a < 4; a++)
        #pragma unroll
        for (int b2 = 0; b2 < 4; b2++) {
            float v = acc[a][b2];
            size_t off = (size_t)(bm + ty * 4 + a) * PT + bn + tx * 4 + b2;
            g_h0[off] = v;
            __nv_bfloat16 h = __float2bfloat16(v);
            g_h0hi[off] = h;
            g_h0lo[off] = __float2bfloat16(v - __bfloat162float(h));
        }
}

// ---------------- persistent RNN kernel (R7 proven sync + rotation + MLP phase B) ----------------
// 144 CTAs = 24 n-tiles(64) x 2 m-tiles(128) x 3 k-splits(512)
__global__ void __launch_bounds__(256)
rnn_kernel(const float* __restrict__ inputs,
           float* __restrict__ oh1, float* __restrict__ oh2) {
    extern __shared__ char smraw[];
    char* sm = (char*)(((uintptr_t)smraw + 1023) & ~(uintptr_t)1023);
    uint32_t sb = smem_u32(sm);
    int tid = threadIdx.x;
    int cta = blockIdx.x;
    int nt = cta / 6;
    int rem = cta % 6;
    int mt = rem / 3;
    int ksp = rem % 3;
    int bn = nt * 64;
    int bm = mt * 128;
    int kbase = ksp * KPC;
    int grp = nt * 2 + mt;
    int rot = cta & 7;               // per-CTA chunk rotation (decorrelate bursts)

    // ---- load resident W slice (64 n x 512 k, hi+lo = 128KB) once ----
    for (int c = 0; c < 8; c++) {
        int k0 = kbase + c * 64;
        #pragma unroll
        for (int j = 0; j < 2; j++) {
            int u = tid + 256 * j;
            int row = u >> 3, kk = u & 7;
            size_t goff = (size_t)(bn + row) * PT + k0 + kk * 8;
            uint32_t d1 = sb + PW_CH(c) + swz((uint32_t)(row * 128 + kk * 16));
            cpasync16(d1, g_Whi + goff);
            cpasync16(d1 + 8192, g_Wlo + goff);
        }
    }
    CP_COMMIT();
    asm volatile("cp.async.wait_group 0;" ::: "memory");
    __syncthreads();

    int lane = tid & 31, wrp = tid >> 5;
    int warpm = wrp & 3, warpn = wrp >> 2;     // warp tile 32m x 32n over 128x64
    uint32_t b_off = (uint32_t)((warpn * 32 + ((lane >> 4) & 1) * 8 + (lane & 7)) * 128 +
                                ((lane >> 3) & 1) * 16);
    float* pbase = g_part + (size_t)ksp * B * PT;

    for (int t = 0; t < T; t++) {
        // ===== phase A: partial GEMM (128m x 64n x 512k), rotated chunk order =====
        const __nv_bfloat16* ahi;
        const __nv_bfloat16* alo;
        size_t astr;
        if (t == 0) { ahi = g_h0hi; alo = g_h0lo; astr = PT; }
        else {
            ahi = g_histhi + (size_t)(t - 1) * PT;
            alo = g_histlo + (size_t)(t - 1) * PT;
            astr = (size_t)T * PT;
        }
        float acc[2][4][4] = {};
        auto issueA = [&](int cc, int buf) {
            uint32_t dst = sb + PA_BUF(buf);
            int k0 = kbase + cc * 64;
            #pragma unroll
            for (int j = 0; j < 4; j++) {
                int u = tid + 256 * j;
                int row = u >> 3, kk = u & 7;
                size_t soff = (size_t)(bm + row) * astr + k0 + kk * 8;
                uint32_t d1 = dst + swz((uint32_t)(row * 128 + kk * 16));
                cpasync16(d1, ahi + soff);
                cpasync16(d1 + 16384, alo + soff);
            }
            CP_COMMIT();
        };
        issueA(rot, 0);
        #pragma unroll
        for (int c = 0; c < 8; c++) {
            int cc = (c + rot) & 7;
            asm volatile("cp.async.wait_group 0;" ::: "memory");
            __syncthreads();
            if (c + 1 < 8) issueA((c + 1 + rot) & 7, (c + 1) & 1);
            uint32_t ah = sb + PA_BUF(c & 1), al = ah + 16384;
            uint32_t wh = sb + PW_CH(cc), wl = wh + 8192;
            #pragma unroll
            for (int kk = 0; kk < 4; kk++) {
                uint32_t Wh0[4], Wh1[4], Wl0[4], Wl1[4];
                uint32_t bo = b_off + kk * 32;
                ldmx4(Wh0, wh + swz(bo)); ldmx4(Wh1, wh + swz(bo + 2048));
                ldmx4(Wl0, wl + swz(bo)); ldmx4(Wl1, wl + swz(bo + 2048));
                #pragma unroll
                for (int mf = 0; mf < 2; mf++) {
                    uint32_t Ah[4], Al[4];
                    uint32_t ao = (uint32_t)((warpm * 32 + mf * 16 + (lane & 15)) * 128 +
                                             ((lane >> 4) & 1) * 16 + kk * 32);
                    ldmx4(Ah, ah + swz(ao));
                    ldmx4(Al, al + swz(ao));
                    mma16816(acc[mf][0], Ah, Wh0[0], Wh0[1]);
                    mma16816(acc[mf][1], Ah, Wh0[2], Wh0[3]);
                    mma16816(acc[mf][2], Ah, Wh1[0], Wh1[1]);
                    mma16816(acc[mf][3], Ah, Wh1[2], Wh1[3]);
                    mma16816(acc[mf][0], Al, Wh0[0], Wh0[1]);
                    mma16816(acc[mf][1], Al, Wh0[2], Wh0[3]);
                    mma16816(acc[mf][2], Al, Wh1[0], Wh1[1]);
                    mma16816(acc[mf][3], Al, Wh1[2], Wh1[3]);
                    mma16816(acc[mf][0], Ah, Wl0[0], Wl0[1]);
                    mma16816(acc[mf][1], Ah, Wl0[2], Wl0[3]);
                    mma16816(acc[mf][2], Ah, Wl1[0], Wl1[1]);
                    mma16816(acc[mf][3], Ah, Wl1[2], Wl1[3]);
                }
            }
        }
        // store partials for this k-split
        #pragma unroll
        for (int mf = 0; mf < 2; mf++) {
            int m0 = bm + warpm * 32 + mf * 16 + (lane >> 2);
            #pragma unroll
            for (int nf = 0; nf < 4; nf++) {
                int n = bn + warpn * 32 + nf * 8 + (lane & 3) * 2;
                *reinterpret_cast<float2*>(pbase + (size_t)m0 * PT + n) =
                    make_float2(acc[mf][nf][0], acc[mf][nf][1]);
                *reinterpret_cast<float2*>(pbase + (size_t)(m0 + 8) * PT + n) =
                    make_float2(acc[mf][nf][2], acc[mf][nf][3]);
            }
        }

        // ===== group sync: wait for the 3 k-split CTAs of this tile =====
        __threadfence();
        __syncthreads();
        if (tid == 0) {
            atomicAdd(&g_tc[grp], 1u);
            unsigned target = 3u * (unsigned)(t + 1);
            while (atomicAdd(&g_tc[grp], 0u) < target) {}
        }
        __syncthreads();
        __threadfence();

        // ===== phase B: reduce own tile (128m x 64n) + epilogue, MLP-batched loads =====
        {
            int e0 = ksp * 256 + tid;          // [0, 768)
            int e1 = e0 + 768;                 // [768, 1536)
            int e2 = e0 + 1536;                // [1536, 2304) -- valid if < 2048
            bool v2 = (e2 < 2048);
            int m0 = bm + (e0 >> 4), n0 = bn + ((e0 & 15) << 2);
            int m1 = bm + (e1 >> 4), n1 = bn + ((e1 & 15) << 2);
            int m2 = bm + (e2 >> 4), n2 = bn + ((e2 & 15) << 2);

            float4 pa[3], pb[3], pc[3];
            #pragma unroll
            for (int kq = 0; kq < KSPLIT; kq++) {
                pa[kq] = __ldcg(reinterpret_cast<const float4*>(
                    g_part + ((size_t)kq * B + m0) * PT + n0));
                pb[kq] = __ldcg(reinterpret_cast<const float4*>(
                    g_part + ((size_t)kq * B + m1) * PT + n1));
                if (v2) pc[kq] = __ldcg(reinterpret_cast<const float4*>(
                    g_part + ((size_t)kq * B + m2) * PT + n2));
            }

            auto epi = [&](int m, int n, float4 s) {
                float2 xv = *reinterpret_cast<const float2*>(inputs + ((size_t)m * T + t) * 2);
                float4 bs = *reinterpret_cast<const float4*>(g_bias + n);
                float4 w01 = *reinterpret_cast<const float4*>(g_win + 2 * n);
                float4 w23 = *reinterpret_cast<const float4*>(g_win + 2 * n + 4);
                float a0 = s.x + bs.x + xv.x * w01.x + xv.y * w01.y;
                float a1 = s.y + bs.y + xv.x * w01.z + xv.y * w01.w;
                float a2 = s.z + bs.z + xv.x * w23.x + xv.y * w23.y;
                float a3 = s.w + bs.w + xv.x * w23.z + xv.y * w23.w;
                float alpha = (n < P1) ? 0.1f : 0.05f;
                float oma = 1.0f - alpha;
                const float* hp;
                float* op;
                if (n < P1) {
                    hp = (t == 0) ? g_h0 + (size_t)m * PT + n
                                  : oh1 + ((size_t)m * T + t - 1) * P1 + n;
                    op = oh1 + ((size_t)m * T + t) * P1 + n;
                } else {
                    hp = (t == 0) ? g_h0 + (size_t)m * PT + n
                                  : oh2 + ((size_t)m * T + t - 1) * P2 + (n - P1);
                    op = oh2 + ((size_t)m * T + t) * P2 + (n - P1);
                }
                float4 h4 = *reinterpret_cast<const float4*>(hp);
                float4 nh;
                nh.x = oma * h4.x + alpha * fast_tanh(a0);
                nh.y = oma * h4.y + alpha * fast_tanh(a1);
                nh.z = oma * h4.z + alpha * fast_tanh(a2);
                nh.w = oma * h4.w + alpha * fast_tanh(a3);
                *reinterpret_cast<float4*>(op) = nh;
                __nv_bfloat16 hx = __float2bfloat16(nh.x), hy = __float2bfloat16(nh.y);
                __nv_bfloat16 hz = __float2bfloat16(nh.z), hw = __float2bfloat16(nh.w);
                uint2 hv = make_uint2(
                    (uint32_t)__bfloat16_as_ushort(hx) | ((uint32_t)__bfloat16_as_ushort(hy) << 16),
                    (uint32_t)__bfloat16_as_ushort(hz) | ((uint32_t)__bfloat16_as_ushort(hw) << 16));
                __nv_bfloat16 lx = __float2bfloat16(nh.x - __bfloat162float(hx));
                __nv_bfloat16 ly = __float2bfloat16(nh.y - __bfloat162float(hy));
                __nv_bfloat16 lz = __float2bfloat16(nh.z - __bfloat162float(hz));
                __nv_bfloat16 lw = __float2bfloat16(nh.w - __bfloat162float(hw));
                uint2 lv = make_uint2(
                    (uint32_t)__bfloat16_as_ushort(lx) | ((uint32_t)__bfloat16_as_ushort(ly) << 16),
                    (uint32_t)__bfloat16_as_ushort(lz) | ((uint32_t)__bfloat16_as_ushort(lw) << 16));
                size_t hoff = ((size_t)m * T + t) * PT + n;
                *reinterpret_cast<uint2*>(reinterpret_cast<char*>(g_histhi) + hoff * 2) = hv;
                *reinterpret_cast<uint2*>(reinterpret_cast<char*>(g_histlo) + hoff * 2) = lv;
            };

            float4 s0 = pa[0];
            s0.x += pa[1].x + pa[2].x; s0.y += pa[1].y + pa[2].y;
            s0.z += pa[1].z + pa[2].z; s0.w += pa[1].w + pa[2].w;
            epi(m0, n0, s0);
            float4 s1 = pb[0];
            s1.x += pb[1].x + pb[2].x; s1.y += pb[1].y + pb[2].y;
            s1.z += pb[1].z + pb[2].z; s1.w += pb[1].w + pb[2].w;
            epi(m1, n1, s1);
            if (v2) {
                float4 s2 = pc[0];
                s2.x += pc[1].x + pc[2].x; s2.y += pc[1].y + pc[2].y;
                s2.z += pc[1].z + pc[2].z; s2.w += pc[1].w + pc[2].w;
                epi(m2, n2, s2);
            }
        }

        // ===== single global barrier: h(t) published =====
        grid_bar(tid);
    }
}

// ---------------- output projection: 128x128 tile, reads pre-split history ----------------
__global__ void __launch_bounds__(256)
out_kernel(float* __restrict__ out2) {
    extern __shared__ char smraw[];
    char* sm = (char*)(((uintptr_t)smraw + 1023) & ~(uintptr_t)1023);
    uint32_t sb = smem_u32(sm);
    int tid = threadIdx.x;
    int bn = blockIdx.x * 128;     // over O (4 tiles)
    int bm = blockIdx.y * 128;     // over B*T (400 tiles)

    int lane = tid & 31, wrp = tid >> 5;
    int warpm = wrp & 3, warpn = wrp >> 2;   // warp tile 32m x 64n
    uint32_t b_off = (uint32_t)((warpn * 64 + ((lane >> 4) & 1) * 8 + (lane & 7)) * 128 +
                                ((lane >> 3) & 1) * 16);

    auto issueAW = [&](int c) {
        int k0 = c * 64;
        int buf = c % 3;
        uint32_t da = sb + OA(buf);
        #pragma unroll
        for (int j = 0; j < 4; j++) {
            int u = tid + 256 * j;
            int row = u >> 3, kk = u & 7;
            size_t soff = (size_t)(bm + row) * PT + k0 + kk * 8;
            uint32_t d1 = da + swz((uint32_t)(row * 128 + kk * 16));
            cpasync16(d1, g_histhi + soff);
            cpasync16(d1 + 16384, g_histlo + soff);
        }
        uint32_t dw = sb + OW(buf);
        #pragma unroll
        for (int j = 0; j < 4; j++) {
            int u = tid + 256 * j;
            int row = u >> 3, kk = u & 7;
            size_t goff = (size_t)(bn + row) * PT + k0 + kk * 8;
            uint32_t d1 = dw + swz((uint32_t)(row * 128 + kk * 16));
            cpasync16(d1, g_Wouthi + goff);
            cpasync16(d1 + 16384, g_Woutlo + goff);
        }
        CP_COMMIT();
    };

    float acc[2][8][4] = {};
    issueAW(0);
    issueAW(1);
    for (int c = 0; c < NCHUNK; c++) {
        if (c < NCHUNK - 1) asm volatile("cp.async.wait_group 1;" ::: "memory");
        else                asm volatile("cp.async.wait_group 0;" ::: "memory");
        __syncthreads();
        if (c + 2 < NCHUNK) issueAW(c + 2);

        uint32_t ah = sb + OA(c % 3), al = ah + 16384;
        uint32_t wh = sb + OW(c % 3), wl = wh + 16384;
        #pragma unroll
        for (int kk = 0; kk < 4; kk++) {
            uint32_t WhA[4], WhB[4], WhC[4], WhD[4];
            uint32_t WlA[4], WlB[4], WlC[4], WlD[4];
            uint32_t bo = b_off + kk * 32;
            ldmx4(WhA, wh + swz(bo));        ldmx4(WhB, wh + swz(bo + 2048));
            ldmx4(WhC, wh + swz(bo + 4096)); ldmx4(WhD, wh + swz(bo + 6144));
            ldmx4(WlA, wl + swz(bo));        ldmx4(WlB, wl + swz(bo + 2048));
            ldmx4(WlC, wl + swz(bo + 4096)); ldmx4(WlD, wl + swz(bo + 6144));
            #pragma unroll
            for (int mf = 0; mf < 2; mf++) {
                uint32_t Ah[4], Al[4];
                uint32_t ao = (uint32_t)((warpm * 32 + mf * 16 + (lane & 15)) * 128 +
                                         ((lane >> 4) & 1) * 16 + kk * 32);
                ldmx4(Ah, ah + swz(ao));
                ldmx4(Al, al + swz(ao));
                mma16816(acc[mf][0], Ah, WhA[0], WhA[1]); mma16816(acc[mf][1], Ah, WhA[2], WhA[3]);
                mma16816(acc[mf][2], Ah, WhB[0], WhB[1]); mma16816(acc[mf][3], Ah, WhB[2], WhB[3]);
                mma16816(acc[mf][4], Ah, WhC[0], WhC[1]); mma16816(acc[mf][5], Ah, WhC[2], WhC[3]);
                mma16816(acc[mf][6], Ah, WhD[0], WhD[1]); mma16816(acc[mf][7], Ah, WhD[2], WhD[3]);
                mma16816(acc[mf][0], Al, WhA[0], WhA[1]); mma16816(acc[mf][1], Al, WhA[2], WhA[3]);
                mma16816(acc[mf][2], Al, WhB[0], WhB[1]); mma16816(acc[mf][3], Al, WhB[2], WhB[3]);
                mma16816(acc[mf][4], Al, WhC[0], WhC[1]); mma16816(acc[mf][5], Al, WhC[2], WhC[3]);
                mma16816(acc[mf][6], Al, WhD[0], WhD[1]); mma16816(acc[mf][7], Al, WhD[2], WhD[3]);
                mma16816(acc[mf][0], Ah, WlA[0], WlA[1]); mma16816(acc[mf][1], Ah, WlA[2], WlA[3]);
                mma16816(acc[mf][2], Ah, WlB[0], WlB[1]); mma16816(acc[mf][3], Ah, WlB[2], WlB[3]);
                mma16816(acc[mf][4], Ah, WlC[0], WlC[1]); mma16816(acc[mf][5], Ah, WlC[2], WlC[3]);
                mma16816(acc[mf][6], Ah, WlD[0], WlD[1]); mma16816(acc[mf][7], Ah, WlD[2], WlD[3]);
            }
        }
    }

    #pragma unroll
    for (int mf = 0; mf < 2; mf++) {
        #pragma unroll
        for (int half = 0; half < 2; half++) {
            size_t m = (size_t)bm + warpm * 32 + mf * 16 + (lane >> 2) + half * 8;
            #pragma unroll
            for (int nj = 0; nj < 8; nj++) {
                int cc = warpn * 64 + nj * 8 + 2 * (lane & 3);
                float2 o2;
                o2.x = acc[mf][nj][half * 2 + 0];
                o2.y = acc[mf][nj][half * 2 + 1];
                *reinterpret_cast<float2*>(out2 + m * O + bn + cc) = o2;
            }
        }
    }
}

// ---------------- host ----------------
extern "C" void kernel_launch(void* const* d_in, const int* in_sizes, int n_in,
                              void* d_out, int out_size) {
    const float* inputs  = (const float*)d_in[0];
    const float* place0  = (const float*)d_in[1];
    const float* W_in1   = (const float*)d_in[2];
    const float* b_in1   = (const float*)d_in[3];
    const float* W_in2   = (const float*)d_in[4];
    const float* b_in2   = (const float*)d_in[5];
    const float* W_rec1  = (const float*)d_in[6];
    const float* b_rec1  = (const float*)d_in[7];
    const float* W_rec2  = (const float*)d_in[8];
    const float* b_rec2  = (const float*)d_in[9];
    const float* W_12    = (const float*)d_in[10];
    const float* b_12    = (const float*)d_in[11];
    const float* W_21    = (const float*)d_in[12];
    const float* b_21    = (const float*)d_in[13];
    const float* W_out   = (const float*)d_in[14];
    const float* W_h1    = (const float*)d_in[15];
    const float* W_h2    = (const float*)d_in[16];

    float* oh1  = (float*)d_out;
    float* oh2  = oh1 + (size_t)B * T * P1;
    float* out2 = oh2 + (size_t)B * T * P2;

    cudaFuncSetAttribute(rnn_kernel, cudaFuncAttributeMaxDynamicSharedMemorySize, PSM_REQ);
    cudaFuncSetAttribute(out_kernel, cudaFuncAttributeMaxDynamicSharedMemorySize, OSM_REQ);

    pack_kernel<<<PT, 256>>>(W_rec1, b_rec1, W_rec2, b_rec2,
                             W_12, b_12, W_21, b_21,
                             W_in1, b_in1, W_in2, b_in2, W_out);

    {
        dim3 grid(PT / 64, B / 64);
        init_kernel<<<grid, 256>>>(place0, W_h1, W_h2);
    }

    rnn_kernel<<<NCTAS, 256, PSM_REQ>>>(inputs, oh1, oh2);

    {
        dim3 grid(O / 128, (B * T) / 128);  // 4 x 400
        out_kernel<<<grid, 256, OSM_REQ>>>(out2);
    }
}

// round 12
// speedup vs baseline: 7.2827x; 1.0405x over previous
#include <cuda_runtime.h>
#include <cuda_bf16.h>
#include <cstdint>

#define B 256
#define T 200
#define P1 1024
#define P2 512
#define PT 1536
#define O 512
#define NCHUNK 24        // K chunks of 64 (out_kernel)

#define NCTAS 144
#define KSPLIT 3
#define KPC 512          // K per CTA in persistent kernel
#define NGRP 48          // 24 n-tiles x 2 m-tiles

// ---------------- device scratch ----------------
__device__ float g_bias[PT];
__device__ float g_win[2 * PT];
__device__ float g_h0[B * PT];
__device__ __nv_bfloat16 g_h0hi[B * PT];
__device__ __nv_bfloat16 g_h0lo[B * PT];
__device__ __nv_bfloat16 g_histhi[(size_t)B * T * PT];   // bf16 hi history
__device__ __nv_bfloat16 g_histlo[(size_t)B * T * PT];   // bf16 lo history
__device__ float g_part[KSPLIT * B * PT];                // split-K partials
__device__ __nv_bfloat16 g_Whi[PT * PT];
__device__ __nv_bfloat16 g_Wlo[PT * PT];
__device__ __nv_bfloat16 g_Wouthi[O * PT];
__device__ __nv_bfloat16 g_Woutlo[O * PT];
__device__ unsigned g_cnt;
__device__ unsigned g_gen;
__device__ unsigned g_tc[NGRP];          // per-tile-group cumulative counters

// ---------------- smem layout: persistent rnn kernel ----------------
#define PW_CH(c)  ((c) * 16384)                  // W chunk c: hi 8KB, lo +8192 (8 chunks)
#define PA_BUF(b) (131072 + (b) * 32768)         // A buf: hi 16KB, lo +16384 (2 bufs)
#define PSM_REQ   (131072 + 2 * 32768 + 1024)

// ---------------- smem layout: out_kernel (128x64 tile, 2-stage, 2 CTA/SM) ----------------
#define OA(b)    ((b) * 32768)                   // A buf: hi 16KB, lo +16384 (2 bufs)
#define OW(b)    (65536 + (b) * 16384)           // W buf: hi 8KB, lo +8192 (2 bufs)
#define OSM_REQ  (65536 + 2 * 16384 + 1024)      // ~97KB -> 2 CTAs/SM

// ---------------- helpers ----------------
__device__ __forceinline__ uint32_t smem_u32(const void* p) {
    uint32_t a;
    asm("{ .reg .u64 t; cvta.to.shared.u64 t, %1; cvt.u32.u64 %0, t; }" : "=r"(a) : "l"(p));
    return a;
}
__device__ __forceinline__ uint32_t swz(uint32_t o) { return o ^ ((o >> 3) & 0x70); }

__device__ __forceinline__ void ldmx4(uint32_t r[4], uint32_t addr) {
    asm volatile("ldmatrix.sync.aligned.m8n8.x4.shared.b16 {%0,%1,%2,%3}, [%4];"
        : "=r"(r[0]), "=r"(r[1]), "=r"(r[2]), "=r"(r[3]) : "r"(addr));
}
__device__ __forceinline__ void mma16816(float d[4], const uint32_t a[4], uint32_t b0, uint32_t b1) {
    asm volatile("mma.sync.aligned.m16n8k16.row.col.f32.bf16.bf16.f32 "
        "{%0,%1,%2,%3}, {%4,%5,%6,%7}, {%8,%9}, {%0,%1,%2,%3};"
        : "+f"(d[0]), "+f"(d[1]), "+f"(d[2]), "+f"(d[3])
        : "r"(a[0]), "r"(a[1]), "r"(a[2]), "r"(a[3]), "r"(b0), "r"(b1));
}
__device__ __forceinline__ void cpasync16(uint32_t dst, const void* src) {
    asm volatile("cp.async.cg.shared.global [%0], [%1], 16;" :: "r"(dst), "l"(src));
}
#define CP_COMMIT() asm volatile("cp.async.commit_group;" ::: "memory")

__device__ __forceinline__ float fast_tanh(float x) {
    return 1.0f - __fdividef(2.0f, __expf(2.0f * x) + 1.0f);
}

__device__ __forceinline__ unsigned ldcg_u32(const unsigned* p) {
    unsigned v;
    asm volatile("ld.global.cg.u32 %0, [%1];" : "=r"(v) : "l"(p) : "memory");
    return v;
}

// grid-wide sense-reversing barrier (all NCTAS co-resident: 1 CTA/SM)
__device__ __forceinline__ void grid_bar(int tid) {
    __syncthreads();
    if (tid == 0) {
        __threadfence();
        unsigned gen = atomicAdd(&g_gen, 0u);
        if (atomicAdd(&g_cnt, 1u) == NCTAS - 1u) {
            atomicExch(&g_cnt, 0u);
            __threadfence();
            atomicAdd(&g_gen, 1u);
        } else {
            while (*((volatile unsigned*)&g_gen) == gen) {}
        }
        __threadfence();
    }
    __syncthreads();
}

// ---------------- pack: one CTA per weight row; fuse biases, split to bf16 hi/lo ----------------
__global__ void __launch_bounds__(256)
pack_kernel(const float* __restrict__ W_rec1, const float* __restrict__ b_rec1,
            const float* __restrict__ W_rec2, const float* __restrict__ b_rec2,
            const float* __restrict__ W_12,   const float* __restrict__ b_12,
            const float* __restrict__ W_21,   const float* __restrict__ b_21,
            const float* __restrict__ W_in1,  const float* __restrict__ b_in1,
            const float* __restrict__ W_in2,  const float* __restrict__ b_in2,
            const float* __restrict__ W_out) {
    int n = blockIdx.x;      // 0..1535
    int tid = threadIdx.x;

    if (n == 0 && tid < NGRP) g_tc[tid] = 0;
    if (n == 0 && tid == 0) g_cnt = 0;

    const float* s1 = (n < P1) ? (W_rec1 + (size_t)n * P1) : (W_12 + (size_t)(n - P1) * P1);
    const float* s2 = (n < P1) ? (W_21 + (size_t)n * P2)   : (W_rec2 + (size_t)(n - P1) * P2);
    for (int k = tid; k < P1; k += 256) {
        float v = s1[k];
        __nv_bfloat16 h = __float2bfloat16(v);
        g_Whi[(size_t)n * PT + k] = h;
        g_Wlo[(size_t)n * PT + k] = __float2bfloat16(v - __bfloat162float(h));
    }
    for (int k = tid; k < P2; k += 256) {
        float v = s2[k];
        __nv_bfloat16 h = __float2bfloat16(v);
        g_Whi[(size_t)n * PT + P1 + k] = h;
        g_Wlo[(size_t)n * PT + P1 + k] = __float2bfloat16(v - __bfloat162float(h));
    }
    if (n < O) {
        for (int k = tid; k < PT; k += 256) {
            float v = W_out[(size_t)n * PT + k];
            __nv_bfloat16 h = __float2bfloat16(v);
            g_Wouthi[(size_t)n * PT + k] = h;
            g_Woutlo[(size_t)n * PT + k] = __float2bfloat16(v - __bfloat162float(h));
        }
    }
    if (tid == 0) {
        if (n < P1) {
            g_bias[n] = b_rec1[n] + b_21[n] + b_in1[n];
            g_win[2 * n]     = W_in1[2 * n];
            g_win[2 * n + 1] = W_in1[2 * n + 1];
        } else {
            int n2 = n - P1;
            g_bias[n] = b_rec2[n2] + b_12[n2] + b_in2[n2];
            g_win[2 * n]     = W_in2[2 * n2];
            g_win[2 * n + 1] = W_in2[2 * n2 + 1];
        }
    }
}

// ---------------- init: h0 = place @ [W_h1;W_h2].T + write split ----------------
__global__ void init_kernel(const float* __restrict__ place,
                            const float* __restrict__ Wh1,
                            const float* __restrict__ Wh2) {
    __shared__ float As[16][65];
    __shared__ float Ws[16][65];
    int tid = threadIdx.x;
    int bn = blockIdx.x * 64;
    int bm = blockIdx.y * 64;
    float acc[4][4] = {};
    for (int k0 = 0; k0 < O; k0 += 16) {
        #pragma unroll
        for (int i = 0; i < 4; i++) {
            int lin = tid + 256 * i;
            int r = lin >> 4, c = lin & 15;
            As[c][r] = place[(bm + r) * O + k0 + c];
            int n = bn + r;
            Ws[c][r] = (n < P1) ? Wh1[n * O + k0 + c] : Wh2[(n - P1) * O + k0 + c];
        }
        __syncthreads();
        #pragma unroll
        for (int c = 0; c < 16; c++) {
            float af[4], wf[4];
            int ty = tid >> 4, tx = tid & 15;
            #pragma unroll
            for (int j = 0; j < 4; j++) { af[j] = As[c][ty * 4 + j]; wf[j] = Ws[c][tx * 4 + j]; }
            #pragma unroll
            for (int a = 0; a < 4; a++)
                #pragma unroll
                for (int b2 = 0; b2 < 4; b2++)
                    acc[a][b2] = fmaf(af[a], wf[b2], acc[a][b2]);
        }
        __syncthreads();
    }
    int ty = tid >> 4, tx = tid & 15;
    #pragma unroll
    for (int a = 0; a < 4; a++)
        #pragma unroll
        for (int b2 = 0; b2 < 4; b2++) {
            float v = acc[a][b2];
            size_t off = (size_t)(bm + ty * 4 + a) * PT + bn + tx * 4 + b2;
            g_h0[off] = v;
            __nv_bfloat16 h = __float2bfloat16(v);
            g_h0hi[off] = h;
            g_h0lo[off] = __float2bfloat16(v - __bfloat162float(h));
        }
}

// ---------------- persistent RNN kernel (R7 proven sync; pass-major MMA; light polls) ----------------
// 144 CTAs = 24 n-tiles(64) x 2 m-tiles(128) x 3 k-splits(512)
__global__ void __launch_bounds__(256)
rnn_kernel(const float* __restrict__ inputs,
           float* __restrict__ oh1, float* __restrict__ oh2) {
    extern __shared__ char smraw[];
    char* sm = (char*)(((uintptr_t)smraw + 1023) & ~(uintptr_t)1023);
    uint32_t sb = smem_u32(sm);
    int tid = threadIdx.x;
    int cta = blockIdx.x;
    int nt = cta / 6;
    int rem = cta % 6;
    int mt = rem / 3;
    int ksp = rem % 3;
    int bn = nt * 64;
    int bm = mt * 128;
    int kbase = ksp * KPC;
    int grp = nt * 2 + mt;
    int rot = cta & 7;               // per-CTA chunk rotation (keeps R11 behavior)

    // ---- load resident W slice (64 n x 512 k, hi+lo = 128KB) once ----
    for (int c = 0; c < 8; c++) {
        int k0 = kbase + c * 64;
        #pragma unroll
        for (int j = 0; j < 2; j++) {
            int u = tid + 256 * j;
            int row = u >> 3, kk = u & 7;
            size_t goff = (size_t)(bn + row) * PT + k0 + kk * 8;
            uint32_t d1 = sb + PW_CH(c) + swz((uint32_t)(row * 128 + kk * 16));
            cpasync16(d1, g_Whi + goff);
            cpasync16(d1 + 8192, g_Wlo + goff);
        }
    }
    CP_COMMIT();
    asm volatile("cp.async.wait_group 0;" ::: "memory");
    __syncthreads();

    int lane = tid & 31, wrp = tid >> 5;
    int warpm = wrp & 3, warpn = wrp >> 2;     // warp tile 32m x 32n over 128x64
    uint32_t b_off = (uint32_t)((warpn * 32 + ((lane >> 4) & 1) * 8 + (lane & 7)) * 128 +
                                ((lane >> 3) & 1) * 16);
    float* pbase = g_part + (size_t)ksp * B * PT;

    for (int t = 0; t < T; t++) {
        // ===== phase A: partial GEMM (128m x 64n x 512k), rotated chunk order =====
        const __nv_bfloat16* ahi;
        const __nv_bfloat16* alo;
        size_t astr;
        if (t == 0) { ahi = g_h0hi; alo = g_h0lo; astr = PT; }
        else {
            ahi = g_histhi + (size_t)(t - 1) * PT;
            alo = g_histlo + (size_t)(t - 1) * PT;
            astr = (size_t)T * PT;
        }
        float acc[2][4][4] = {};
        auto issueA = [&](int cc, int buf) {
            uint32_t dst = sb + PA_BUF(buf);
            int k0 = kbase + cc * 64;
            #pragma unroll
            for (int j = 0; j < 4; j++) {
                int u = tid + 256 * j;
                int row = u >> 3, kk = u & 7;
                size_t soff = (size_t)(bm + row) * astr + k0 + kk * 8;
                uint32_t d1 = dst + swz((uint32_t)(row * 128 + kk * 16));
                cpasync16(d1, ahi + soff);
                cpasync16(d1 + 16384, alo + soff);
            }
            CP_COMMIT();
        };
        issueA(rot, 0);
        #pragma unroll
        for (int c = 0; c < 8; c++) {
            int cc = (c + rot) & 7;
            asm volatile("cp.async.wait_group 0;" ::: "memory");
            __syncthreads();
            if (c + 1 < 8) issueA((c + 1 + rot) & 7, (c + 1) & 1);
            uint32_t ah = sb + PA_BUF(c & 1), al = ah + 16384;
            uint32_t wh = sb + PW_CH(cc), wl = wh + 8192;
            #pragma unroll
            for (int kk = 0; kk < 4; kk++) {
                uint32_t Wh0[4], Wh1[4], Wl0[4], Wl1[4];
                uint32_t bo = b_off + kk * 32;
                ldmx4(Wh0, wh + swz(bo)); ldmx4(Wh1, wh + swz(bo + 2048));
                ldmx4(Wl0, wl + swz(bo)); ldmx4(Wl1, wl + swz(bo + 2048));
                // load both m-frags up front, then pass-major mma (acc reuse distance 8)
                uint32_t Ah[2][4], Al[2][4];
                #pragma unroll
                for (int mf = 0; mf < 2; mf++) {
                    uint32_t ao = (uint32_t)((warpm * 32 + mf * 16 + (lane & 15)) * 128 +
                                             ((lane >> 4) & 1) * 16 + kk * 32);
                    ldmx4(Ah[mf], ah + swz(ao));
                    ldmx4(Al[mf], al + swz(ao));
                }
                #pragma unroll
                for (int mf = 0; mf < 2; mf++) {
                    mma16816(acc[mf][0], Ah[mf], Wh0[0], Wh0[1]);
                    mma16816(acc[mf][1], Ah[mf], Wh0[2], Wh0[3]);
                    mma16816(acc[mf][2], Ah[mf], Wh1[0], Wh1[1]);
                    mma16816(acc[mf][3], Ah[mf], Wh1[2], Wh1[3]);
                }
                #pragma unroll
                for (int mf = 0; mf < 2; mf++) {
                    mma16816(acc[mf][0], Al[mf], Wh0[0], Wh0[1]);
                    mma16816(acc[mf][1], Al[mf], Wh0[2], Wh0[3]);
                    mma16816(acc[mf][2], Al[mf], Wh1[0], Wh1[1]);
                    mma16816(acc[mf][3], Al[mf], Wh1[2], Wh1[3]);
                }
                #pragma unroll
                for (int mf = 0; mf < 2; mf++) {
                    mma16816(acc[mf][0], Ah[mf], Wl0[0], Wl0[1]);
                    mma16816(acc[mf][1], Ah[mf], Wl0[2], Wl0[3]);
                    mma16816(acc[mf][2], Ah[mf], Wl1[0], Wl1[1]);
                    mma16816(acc[mf][3], Ah[mf], Wl1[2], Wl1[3]);
                }
            }
        }
        // store partials for this k-split
        #pragma unroll
        for (int mf = 0; mf < 2; mf++) {
            int m0 = bm + warpm * 32 + mf * 16 + (lane >> 2);
            #pragma unroll
            for (int nf = 0; nf < 4; nf++) {
                int n = bn + warpn * 32 + nf * 8 + (lane & 3) * 2;
                *reinterpret_cast<float2*>(pbase + (size_t)m0 * PT + n) =
                    make_float2(acc[mf][nf][0], acc[mf][nf][1]);
                *reinterpret_cast<float2*>(pbase + (size_t)(m0 + 8) * PT + n) =
                    make_float2(acc[mf][nf][2], acc[mf][nf][3]);
            }
        }

        // ===== group sync: wait for the 3 k-split CTAs of this tile =====
        __threadfence();
        __syncthreads();
        if (tid == 0) {
            atomicAdd(&g_tc[grp], 1u);
            unsigned target = 3u * (unsigned)(t + 1);
            while (ldcg_u32(&g_tc[grp]) < target) {}
        }
        __syncthreads();
        __threadfence();

        // ===== phase B: reduce own tile (128m x 64n) + epilogue, MLP-batched loads =====
        {
            int e0 = ksp * 256 + tid;
            int e1 = e0 + 768;
            int e2 = e0 + 1536;
            bool v2 = (e2 < 2048);
            int m0 = bm + (e0 >> 4), n0 = bn + ((e0 & 15) << 2);
            int m1 = bm + (e1 >> 4), n1 = bn + ((e1 & 15) << 2);
            int m2 = bm + (e2 >> 4), n2 = bn + ((e2 & 15) << 2);

            float4 pa[3], pb[3], pc[3];
            #pragma unroll
            for (int kq = 0; kq < KSPLIT; kq++) {
                pa[kq] = __ldcg(reinterpret_cast<const float4*>(
                    g_part + ((size_t)kq * B + m0) * PT + n0));
                pb[kq] = __ldcg(reinterpret_cast<const float4*>(
                    g_part + ((size_t)kq * B + m1) * PT + n1));
                if (v2) pc[kq] = __ldcg(reinterpret_cast<const float4*>(
                    g_part + ((size_t)kq * B + m2) * PT + n2));
            }

            auto epi = [&](int m, int n, float4 s) {
                float2 xv = *reinterpret_cast<const float2*>(inputs + ((size_t)m * T + t) * 2);
                float4 bs = *reinterpret_cast<const float4*>(g_bias + n);
                float4 w01 = *reinterpret_cast<const float4*>(g_win + 2 * n);
                float4 w23 = *reinterpret_cast<const float4*>(g_win + 2 * n + 4);
                float a0 = s.x + bs.x + xv.x * w01.x + xv.y * w01.y;
                float a1 = s.y + bs.y + xv.x * w01.z + xv.y * w01.w;
                float a2 = s.z + bs.z + xv.x * w23.x + xv.y * w23.y;
                float a3 = s.w + bs.w + xv.x * w23.z + xv.y * w23.w;
                float alpha = (n < P1) ? 0.1f : 0.05f;
                float oma = 1.0f - alpha;
                const float* hp;
                float* op;
                if (n < P1) {
                    hp = (t == 0) ? g_h0 + (size_t)m * PT + n
                                  : oh1 + ((size_t)m * T + t - 1) * P1 + n;
                    op = oh1 + ((size_t)m * T + t) * P1 + n;
                } else {
                    hp = (t == 0) ? g_h0 + (size_t)m * PT + n
                                  : oh2 + ((size_t)m * T + t - 1) * P2 + (n - P1);
                    op = oh2 + ((size_t)m * T + t) * P2 + (n - P1);
                }
                float4 h4 = *reinterpret_cast<const float4*>(hp);
                float4 nh;
                nh.x = oma * h4.x + alpha * fast_tanh(a0);
                nh.y = oma * h4.y + alpha * fast_tanh(a1);
                nh.z = oma * h4.z + alpha * fast_tanh(a2);
                nh.w = oma * h4.w + alpha * fast_tanh(a3);
                *reinterpret_cast<float4*>(op) = nh;
                __nv_bfloat16 hx = __float2bfloat16(nh.x), hy = __float2bfloat16(nh.y);
                __nv_bfloat16 hz = __float2bfloat16(nh.z), hw = __float2bfloat16(nh.w);
                uint2 hv = make_uint2(
                    (uint32_t)__bfloat16_as_ushort(hx) | ((uint32_t)__bfloat16_as_ushort(hy) << 16),
                    (uint32_t)__bfloat16_as_ushort(hz) | ((uint32_t)__bfloat16_as_ushort(hw) << 16));
                __nv_bfloat16 lx = __float2bfloat16(nh.x - __bfloat162float(hx));
                __nv_bfloat16 ly = __float2bfloat16(nh.y - __bfloat162float(hy));
                __nv_bfloat16 lz = __float2bfloat16(nh.z - __bfloat162float(hz));
                __nv_bfloat16 lw = __float2bfloat16(nh.w - __bfloat162float(hw));
                uint2 lv = make_uint2(
                    (uint32_t)__bfloat16_as_ushort(lx) | ((uint32_t)__bfloat16_as_ushort(ly) << 16),
                    (uint32_t)__bfloat16_as_ushort(lz) | ((uint32_t)__bfloat16_as_ushort(lw) << 16));
                size_t hoff = ((size_t)m * T + t) * PT + n;
                *reinterpret_cast<uint2*>(reinterpret_cast<char*>(g_histhi) + hoff * 2) = hv;
                *reinterpret_cast<uint2*>(reinterpret_cast<char*>(g_histlo) + hoff * 2) = lv;
            };

            float4 s0 = pa[0];
            s0.x += pa[1].x + pa[2].x; s0.y += pa[1].y + pa[2].y;
            s0.z += pa[1].z + pa[2].z; s0.w += pa[1].w + pa[2].w;
            epi(m0, n0, s0);
            float4 s1 = pb[0];
            s1.x += pb[1].x + pb[2].x; s1.y += pb[1].y + pb[2].y;
            s1.z += pb[1].z + pb[2].z; s1.w += pb[1].w + pb[2].w;
            epi(m1, n1, s1);
            if (v2) {
                float4 s2 = pc[0];
                s2.x += pc[1].x + pc[2].x; s2.y += pc[1].y + pc[2].y;
                s2.z += pc[1].z + pc[2].z; s2.w += pc[1].w + pc[2].w;
                epi(m2, n2, s2);
            }
        }

        // ===== single global barrier: h(t) published =====
        grid_bar(tid);
    }
}

// ---------------- output projection: 128x64 tile, 2-stage, 2 CTA/SM ----------------
__global__ void __launch_bounds__(256)
out_kernel(float* __restrict__ out2) {
    extern __shared__ char smraw[];
    char* sm = (char*)(((uintptr_t)smraw + 1023) & ~(uintptr_t)1023);
    uint32_t sb = smem_u32(sm);
    int tid = threadIdx.x;
    int bn = blockIdx.x * 64;      // over O (8 tiles)
    int bm = blockIdx.y * 128;     // over B*T (400 tiles)

    int lane = tid & 31, wrp = tid >> 5;
    int warpm = wrp & 3, warpn = wrp >> 2;   // warp tile 32m x 32n
    uint32_t b_off = (uint32_t)((warpn * 32 + ((lane >> 4) & 1) * 8 + (lane & 7)) * 128 +
                                ((lane >> 3) & 1) * 16);

    auto issueAW = [&](int c) {
        int k0 = c * 64;
        int buf = c & 1;
        uint32_t da = sb + OA(buf);
        #pragma unroll
        for (int j = 0; j < 4; j++) {
            int u = tid + 256 * j;
            int row = u >> 3, kk = u & 7;
            size_t soff = (size_t)(bm + row) * PT + k0 + kk * 8;
            uint32_t d1 = da + swz((uint32_t)(row * 128 + kk * 16));
            cpasync16(d1, g_histhi + soff);
            cpasync16(d1 + 16384, g_histlo + soff);
        }
        uint32_t dw = sb + OW(buf);
        #pragma unroll
        for (int j = 0; j < 2; j++) {
            int u = tid + 256 * j;
            int row = u >> 3, kk = u & 7;
            size_t goff = (size_t)(bn + row) * PT + k0 + kk * 8;
            uint32_t d1 = dw + swz((uint32_t)(row * 128 + kk * 16));
            cpasync16(d1, g_Wouthi + goff);
            cpasync16(d1 + 8192, g_Woutlo + goff);
        }
        CP_COMMIT();
    };

    float acc[2][4][4] = {};
    issueAW(0);
    issueAW(1);
    for (int c = 0; c < NCHUNK; c++) {
        if (c < NCHUNK - 1) asm volatile("cp.async.wait_group 1;" ::: "memory");
        else                asm volatile("cp.async.wait_group 0;" ::: "memory");
        __syncthreads();

        uint32_t ah = sb + OA(c & 1), al = ah + 16384;
        uint32_t wh = sb + OW(c & 1), wl = wh + 8192;
        #pragma unroll
        for (int kk = 0; kk < 4; kk++) {
            uint32_t Wh0[4], Wh1[4], Wl0[4], Wl1[4];
            uint32_t bo = b_off + kk * 32;
            ldmx4(Wh0, wh + swz(bo)); ldmx4(Wh1, wh + swz(bo + 2048));
            ldmx4(Wl0, wl + swz(bo)); ldmx4(Wl1, wl + swz(bo + 2048));
            uint32_t Ah[2][4], Al[2][4];
            #pragma unroll
            for (int mf = 0; mf < 2; mf++) {
                uint32_t ao = (uint32_t)((warpm * 32 + mf * 16 + (lane & 15)) * 128 +
                                         ((lane >> 4) & 1) * 16 + kk * 32);
                ldmx4(Ah[mf], ah + swz(ao));
                ldmx4(Al[mf], al + swz(ao));
            }
            #pragma unroll
            for (int mf = 0; mf < 2; mf++) {
                mma16816(acc[mf][0], Ah[mf], Wh0[0], Wh0[1]);
                mma16816(acc[mf][1], Ah[mf], Wh0[2], Wh0[3]);
                mma16816(acc[mf][2], Ah[mf], Wh1[0], Wh1[1]);
                mma16816(acc[mf][3], Ah[mf], Wh1[2], Wh1[3]);
            }
            #pragma unroll
            for (int mf = 0; mf < 2; mf++) {
                mma16816(acc[mf][0], Al[mf], Wh0[0], Wh0[1]);
                mma16816(acc[mf][1], Al[mf], Wh0[2], Wh0[3]);
                mma16816(acc[mf][2], Al[mf], Wh1[0], Wh1[1]);
                mma16816(acc[mf][3], Al[mf], Wh1[2], Wh1[3]);
            }
            #pragma unroll
            for (int mf = 0; mf < 2; mf++) {
                mma16816(acc[mf][0], Ah[mf], Wl0[0], Wl0[1]);
                mma16816(acc[mf][1], Ah[mf], Wl0[2], Wl0[3]);
                mma16816(acc[mf][2], Ah[mf], Wl1[0], Wl1[1]);
                mma16816(acc[mf][3], Ah[mf], Wl1[2], Wl1[3]);
            }
        }
        __syncthreads();
        if (c + 2 < NCHUNK) issueAW(c + 2);   // refill the buffer just consumed
    }

    #pragma unroll
    for (int mf = 0; mf < 2; mf++) {
        #pragma unroll
        for (int half = 0; half < 2; half++) {
            size_t m = (size_t)bm + warpm * 32 + mf * 16 + (lane >> 2) + half * 8;
            #pragma unroll
            for (int nj = 0; nj < 4; nj++) {
                int cc = warpn * 32 + nj * 8 + 2 * (lane & 3);
                float2 o2;
                o2.x = acc[mf][nj][half * 2 + 0];
                o2.y = acc[mf][nj][half * 2 + 1];
                *reinterpret_cast<float2*>(out2 + m * O + bn + cc) = o2;
            }
        }
    }
}

// ---------------- host ----------------
extern "C" void kernel_launch(void* const* d_in, const int* in_sizes, int n_in,
                              void* d_out, int out_size) {
    const float* inputs  = (const float*)d_in[0];
    const float* place0  = (const float*)d_in[1];
    const float* W_in1   = (const float*)d_in[2];
    const float* b_in1   = (const float*)d_in[3];
    const float* W_in2   = (const float*)d_in[4];
    const float* b_in2   = (const float*)d_in[5];
    const float* W_rec1  = (const float*)d_in[6];
    const float* b_rec1  = (const float*)d_in[7];
    const float* W_rec2  = (const float*)d_in[8];
    const float* b_rec2  = (const float*)d_in[9];
    const float* W_12    = (const float*)d_in[10];
    const float* b_12    = (const float*)d_in[11];
    const float* W_21    = (const float*)d_in[12];
    const float* b_21    = (const float*)d_in[13];
    const float* W_out   = (const float*)d_in[14];
    const float* W_h1    = (const float*)d_in[15];
    const float* W_h2    = (const float*)d_in[16];

    float* oh1  = (float*)d_out;
    float* oh2  = oh1 + (size_t)B * T * P1;
    float* out2 = oh2 + (size_t)B * T * P2;

    cudaFuncSetAttribute(rnn_kernel, cudaFuncAttributeMaxDynamicSharedMemorySize, PSM_REQ);
    cudaFuncSetAttribute(out_kernel, cudaFuncAttributeMaxDynamicSharedMemorySize, OSM_REQ);

    pack_kernel<<<PT, 256>>>(W_rec1, b_rec1, W_rec2, b_rec2,
                             W_12, b_12, W_21, b_21,
                             W_in1, b_in1, W_in2, b_in2, W_out);

    {
        dim3 grid(PT / 64, B / 64);
        init_kernel<<<grid, 256>>>(place0, W_h1, W_h2);
    }

    rnn_kernel<<<NCTAS, 256, PSM_REQ>>>(inputs, oh1, oh2);

    {
        dim3 grid(O / 64, (B * T) / 128);  // 8 x 400
        out_kernel<<<grid, 256, OSM_REQ>>>(out2);
    }
}